// round 7
// baseline (speedup 1.0000x reference)
#include <cuda_runtime.h>
#include <cuda_bf16.h>
#include <mma.h>
#include <math.h>
#include <stdint.h>

using namespace nvcuda;

#define D_MODEL 512
#define NHEAD   8
#define DK      64
#define BB      4
#define NN      2048
#define M_TOTAL (BB * NN)     // 8192
#define BH      (BB * NHEAD)  // 32
#define NKV     (NN / 64)     // 32 kv blocks

// Q pre-scale: 1/sqrt(64) * log2(e)
#define SC_ATTN 0.18033688f

// ---------------- scratch (allocation-free static device arrays) -----------
__device__ __align__(128) __nv_bfloat16 g_xh[M_TOTAL * D_MODEL];
__device__ __align__(128) __nv_bfloat16 g_xl[M_TOTAL * D_MODEL];
__device__ __align__(128) __nv_bfloat16 g_wh[4][D_MODEL * D_MODEL];
__device__ __align__(128) __nv_bfloat16 g_wl[4][D_MODEL * D_MODEL];
__device__ __align__(128) __nv_bfloat16 g_qh[BH * NN * DK];  // [bh][n][d] (pre-scaled)
__device__ __align__(128) __nv_bfloat16 g_ql[BH * NN * DK];
__device__ __align__(128) __nv_bfloat16 g_kh[BH * NN * DK];
__device__ __align__(128) __nv_bfloat16 g_kl[BH * NN * DK];
__device__ __align__(128) __nv_bfloat16 g_vth[BH * DK * NN]; // [bh][d][n]
__device__ __align__(128) __nv_bfloat16 g_vtl[BH * DK * NN];
__device__ __align__(128) __nv_bfloat16 g_ah[M_TOTAL * D_MODEL]; // attn out split
__device__ __align__(128) __nv_bfloat16 g_al[M_TOTAL * D_MODEL];

// ---------------------------------------------------------------------------
// helpers
// ---------------------------------------------------------------------------
__device__ __forceinline__ uint32_t packb(float x, float y) {
    __nv_bfloat162 t = __floats2bfloat162_rn(x, y);
    return *reinterpret_cast<uint32_t*>(&t);
}
__device__ __forceinline__ void split2(float x, float y, uint32_t& hi, uint32_t& lo) {
    float hx = __bfloat162float(__float2bfloat16(x));
    float hy = __bfloat162float(__float2bfloat16(y));
    hi = packb(hx, hy);
    lo = packb(x - hx, y - hy);
}
__device__ __forceinline__ void mma16816(float* c, const uint32_t* a, uint32_t b0, uint32_t b1) {
    asm volatile(
        "mma.sync.aligned.m16n8k16.row.col.f32.bf16.bf16.f32 "
        "{%0,%1,%2,%3}, {%4,%5,%6,%7}, {%8,%9}, {%0,%1,%2,%3};\n"
        : "+f"(c[0]), "+f"(c[1]), "+f"(c[2]), "+f"(c[3])
        : "r"(a[0]), "r"(a[1]), "r"(a[2]), "r"(a[3]), "r"(b0), "r"(b1));
}
__device__ __forceinline__ void ldsm_x4(uint32_t& d0, uint32_t& d1, uint32_t& d2, uint32_t& d3,
                                        uint32_t saddr) {
    asm volatile("ldmatrix.sync.aligned.m8n8.x4.shared.b16 {%0,%1,%2,%3}, [%4];"
                 : "=r"(d0), "=r"(d1), "=r"(d2), "=r"(d3) : "r"(saddr));
}
__device__ __forceinline__ void cp16(uint32_t dst, const void* src) {
    asm volatile("cp.async.cg.shared.global [%0], [%1], 16;" :: "r"(dst), "l"(src));
}
__device__ __forceinline__ void cp_commit() { asm volatile("cp.async.commit_group;"); }
template<int N> __device__ __forceinline__ void cp_wait() {
    asm volatile("cp.async.wait_group %0;" :: "n"(N));
}
__device__ __forceinline__ uint32_t SW(uint32_t r, uint32_t c) {
    return r * 128u + ((c ^ (r & 7u)) << 4);
}

// ---------------------------------------------------------------------------
// split kernel: float -> (hi, lo) bf16, float4 granularity
// ---------------------------------------------------------------------------
__global__ void __launch_bounds__(256)
split_mat(const float* __restrict__ src, __nv_bfloat16* __restrict__ hi,
          __nv_bfloat16* __restrict__ lo, int n4)
{
    int i = blockIdx.x * 256 + threadIdx.x;
    if (i >= n4) return;
    float4 v = reinterpret_cast<const float4*>(src)[i];
    uint32_t h01, l01, h23, l23;
    split2(v.x, v.y, h01, l01);
    split2(v.z, v.w, h23, l23);
    reinterpret_cast<uint2*>(hi)[i] = make_uint2(h01, h23);
    reinterpret_cast<uint2*>(lo)[i] = make_uint2(l01, l23);
}

// ---------------------------------------------------------------------------
// Pipelined GEMM on pre-split bf16: out = A[M,512] @ W[512,512] + bias
// 128x64 tile, BK=32, 256 thr / 8 warps, warp tile 32x32, 2 CTAs/SM.
// cp.async double-buffered. Epilogue modes:
//   0: fp32 out [row][512]
//   1: split bf16 [bh][n][64] (scale applied)  (Q,K)
//   2: split bf16 transposed [bh][d][n]        (V)
// ---------------------------------------------------------------------------
#define XS_LD 40   // bf16 elems per X smem row (80 B, 16B-aligned)
#define WS_LD 72   // bf16 elems per W smem row (144 B)
#define CS_LD 68   // f32 stage row
#define G_XH_SZ (128 * XS_LD * 2)          // 10240 B
#define G_WH_SZ (32 * WS_LD * 2)           // 4608 B
#define G_STAGE (2 * G_XH_SZ + 2 * G_WH_SZ) // 29696 B
#define GEMM_SMEM (2 * G_STAGE)            // 59392 B
#define NKT 16

__global__ void __launch_bounds__(256, 2)
gemm_ps(const __nv_bfloat16* __restrict__ Ah, const __nv_bfloat16* __restrict__ Al,
        const __nv_bfloat16* __restrict__ Wh, const __nv_bfloat16* __restrict__ Wl,
        const float* __restrict__ bias, void* __restrict__ out0,
        void* __restrict__ out1, int mode, float scale)
{
    extern __shared__ __align__(128) unsigned char sm[];
    const uint32_t sb = (uint32_t)__cvta_generic_to_shared(sm);

    const int tid = threadIdx.x;
    const int wid = tid >> 5;
    const int wm  = wid & 3;
    const int wn  = wid >> 2;
    const int m0  = blockIdx.y * 128;
    const int n0  = blockIdx.x * 64;

    // loader geometry
    const int xr = tid >> 2;          // 0..63 (and +64)
    const int xc = tid & 3;           // 16B chunk in 64B row
    const int wr = tid >> 3;          // 0..31
    const int wc = tid & 7;           // 16B chunk in 128B row

    auto load_stage = [&](int stage, int kt) {
        uint32_t base = sb + stage * G_STAGE;
        // X hi/lo: 128 rows x 32 cols
        #pragma unroll
        for (int t = 0; t < 2; t++) {
            int r = xr + t * 64;
            uint32_t doff = r * (XS_LD * 2) + xc * 16;
            size_t goff = (size_t)(m0 + r) * D_MODEL + kt + xc * 8;
            cp16(base + doff, Ah + goff);
            cp16(base + G_XH_SZ + doff, Al + goff);
        }
        // W hi/lo: 32 rows x 64 cols
        {
            uint32_t doff = wr * (WS_LD * 2) + wc * 16;
            size_t goff = (size_t)(kt + wr) * D_MODEL + n0 + wc * 8;
            cp16(base + 2 * G_XH_SZ + doff, Wh + goff);
            cp16(base + 2 * G_XH_SZ + G_WH_SZ + doff, Wl + goff);
        }
        cp_commit();
    };

    wmma::fragment<wmma::accumulator, 16, 16, 16, float> acc[2][2];
    #pragma unroll
    for (int i = 0; i < 2; i++)
        #pragma unroll
        for (int j = 0; j < 2; j++)
            wmma::fill_fragment(acc[i][j], 0.0f);

    load_stage(0, 0);
    load_stage(1, 32);

    for (int it = 0; it < NKT; it++) {
        if (it == NKT - 1) cp_wait<0>(); else cp_wait<1>();
        __syncthreads();

        const __nv_bfloat16* Xhi = (const __nv_bfloat16*)(sm + (it & 1) * G_STAGE);
        const __nv_bfloat16* Xlo = Xhi + 128 * XS_LD;
        const __nv_bfloat16* Whi = Xlo + 128 * XS_LD;
        const __nv_bfloat16* Wlo = Whi + 32 * WS_LD;

        #pragma unroll
        for (int kk = 0; kk < 32; kk += 16) {
            wmma::fragment<wmma::matrix_a, 16, 16, 16, __nv_bfloat16, wmma::row_major> ahi[2], alo[2];
            #pragma unroll
            for (int i = 0; i < 2; i++) {
                wmma::load_matrix_sync(ahi[i], Xhi + (wm * 32 + 16 * i) * XS_LD + kk, XS_LD);
                wmma::load_matrix_sync(alo[i], Xlo + (wm * 32 + 16 * i) * XS_LD + kk, XS_LD);
            }
            #pragma unroll
            for (int j = 0; j < 2; j++) {
                wmma::fragment<wmma::matrix_b, 16, 16, 16, __nv_bfloat16, wmma::row_major> bhi, blo;
                wmma::load_matrix_sync(bhi, Whi + kk * WS_LD + wn * 32 + 16 * j, WS_LD);
                wmma::load_matrix_sync(blo, Wlo + kk * WS_LD + wn * 32 + 16 * j, WS_LD);
                #pragma unroll
                for (int i = 0; i < 2; i++) {
                    wmma::mma_sync(acc[i][j], ahi[i], bhi, acc[i][j]);
                    wmma::mma_sync(acc[i][j], ahi[i], blo, acc[i][j]);
                    wmma::mma_sync(acc[i][j], alo[i], bhi, acc[i][j]);
                }
            }
        }
        __syncthreads();
        if (it + 2 < NKT) load_stage(it & 1, (it + 2) * 32);
    }

    // stage C in smem (reuses stage buffers; all reads done)
    float* Cst = (float*)sm;
    #pragma unroll
    for (int i = 0; i < 2; i++)
        #pragma unroll
        for (int j = 0; j < 2; j++)
            wmma::store_matrix_sync(Cst + (wm * 32 + 16 * i) * CS_LD + wn * 32 + 16 * j,
                                    acc[i][j], CS_LD, wmma::mem_row_major);
    __syncthreads();

    if (mode == 0) {
        float* out = (float*)out0;
        const int orow = tid >> 4;
        const int ocol = (tid & 15) * 4;
        float4 b4 = *reinterpret_cast<const float4*>(&bias[n0 + ocol]);
        #pragma unroll
        for (int t = 0; t < 8; t++) {
            int r = orow + t * 16;
            float4 v = *reinterpret_cast<const float4*>(&Cst[r * CS_LD + ocol]);
            v.x += b4.x; v.y += b4.y; v.z += b4.z; v.w += b4.w;
            *reinterpret_cast<float4*>(&out[(size_t)(m0 + r) * D_MODEL + n0 + ocol]) = v;
        }
    } else if (mode == 1) {
        __nv_bfloat16* ohi = (__nv_bfloat16*)out0;
        __nv_bfloat16* olo = (__nv_bfloat16*)out1;
        const int h = blockIdx.x;
        const int orow = tid >> 4;
        const int ocol = (tid & 15) * 4;
        float4 b4 = *reinterpret_cast<const float4*>(&bias[n0 + ocol]);
        #pragma unroll
        for (int t = 0; t < 8; t++) {
            int r  = orow + t * 16;
            int rg = m0 + r;
            int b_ = rg >> 11;
            int n_ = rg & 2047;
            float4 v = *reinterpret_cast<const float4*>(&Cst[r * CS_LD + ocol]);
            float v0 = (v.x + b4.x) * scale;
            float v1 = (v.y + b4.y) * scale;
            float v2 = (v.z + b4.z) * scale;
            float v3 = (v.w + b4.w) * scale;
            uint32_t h01, l01, h23, l23;
            split2(v0, v1, h01, l01);
            split2(v2, v3, h23, l23);
            size_t off = ((size_t)(b_ * NHEAD + h) * NN + n_) * DK + ocol;
            *reinterpret_cast<uint2*>(&ohi[off]) = make_uint2(h01, h23);
            *reinterpret_cast<uint2*>(&olo[off]) = make_uint2(l01, l23);
        }
    } else {
        __nv_bfloat16* ohi = (__nv_bfloat16*)out0;
        __nv_bfloat16* olo = (__nv_bfloat16*)out1;
        const int h   = blockIdx.x;
        const int od  = tid >> 2;
        const int on0 = (tid & 3) * 32;
        const int b_  = m0 >> 11;
        const int nb  = (m0 & 2047) + on0;
        const float bv = bias[n0 + od];
        size_t rowoff = ((size_t)(b_ * NHEAD + h) * DK + od) * NN + nb;
        #pragma unroll
        for (int i = 0; i < 32; i += 2) {
            float v0 = Cst[(on0 + i) * CS_LD + od] + bv;
            float v1 = Cst[(on0 + i + 1) * CS_LD + od] + bv;
            uint32_t hp, lp;
            split2(v0, v1, hp, lp);
            *reinterpret_cast<uint32_t*>(&ohi[rowoff + i]) = hp;
            *reinterpret_cast<uint32_t*>(&olo[rowoff + i]) = lp;
        }
    }
}

// ---------------------------------------------------------------------------
// Flash attention: BM=128, BN=64, d=64, 256 thr / 8 warps, 2 CTAs/SM.
// ---------------------------------------------------------------------------
#define SM_QHI 0
#define SM_QLO 16384
#define SM_BUF(b) (32768 + (b) * 32768)
#define SM_KHI 0
#define SM_KLO 8192
#define SM_VHI 16384
#define SM_VLO 24576
#define ATTN_SMEM (32768 + 2 * 32768)   // 96 KB

__global__ void __launch_bounds__(256, 2)
attn_tc()
{
    extern __shared__ __align__(128) unsigned char sm[];
    const uint32_t sbase = (uint32_t)__cvta_generic_to_shared(sm);

    const int tid  = threadIdx.x;
    const int lane = tid & 31;
    const int w    = tid >> 5;
    const int rq   = lane >> 2;
    const int bh   = blockIdx.y;
    const int m0   = blockIdx.x * 128;

    const __nv_bfloat16* qh_g = g_qh + (size_t)bh * NN * DK;
    const __nv_bfloat16* ql_g = g_ql + (size_t)bh * NN * DK;
    const __nv_bfloat16* kh_g = g_kh + (size_t)bh * NN * DK;
    const __nv_bfloat16* kl_g = g_kl + (size_t)bh * NN * DK;
    const __nv_bfloat16* vh_g = g_vth + (size_t)bh * DK * NN;
    const __nv_bfloat16* vl_g = g_vtl + (size_t)bh * DK * NN;

    {
        #pragma unroll
        for (int p = 0; p < 4; p++) {
            int id = tid + p * 256;
            int r = id >> 3, c = id & 7;
            size_t go = (size_t)(m0 + r) * DK + c * 8;
            uint32_t so = SW(r, c);
            cp16(sbase + SM_QHI + so, qh_g + go);
            cp16(sbase + SM_QLO + so, ql_g + go);
        }
        cp_commit();
    }
    {
        #pragma unroll
        for (int p = 0; p < 2; p++) {
            int id = tid + p * 256;
            int r = id >> 3, c = id & 7;
            uint32_t so = SW(r, c);
            size_t ko = (size_t)r * DK + c * 8;
            size_t vo = (size_t)r * NN + c * 8;
            cp16(sbase + SM_BUF(0) + SM_KHI + so, kh_g + ko);
            cp16(sbase + SM_BUF(0) + SM_KLO + so, kl_g + ko);
            cp16(sbase + SM_BUF(0) + SM_VHI + so, vh_g + vo);
            cp16(sbase + SM_BUF(0) + SM_VLO + so, vl_g + vo);
        }
        cp_commit();
    }

    float o[8][4];
    #pragma unroll
    for (int j = 0; j < 8; j++)
        #pragma unroll
        for (int e = 0; e < 4; e++) o[j][e] = 0.0f;
    float mrow[2] = {-1e30f, -1e30f};
    float lrow[2] = {0.0f, 0.0f};

    const uint32_t qrow = w * 16 + (lane & 15);
    const uint32_t qc   = lane >> 4;
    const uint32_t qoff = qrow * 128;
    const uint32_t qxr  = qrow & 7;
    const uint32_t brow = ((lane >> 4) << 3) + (lane & 7);
    const uint32_t bc   = (lane >> 3) & 1;
    const uint32_t bxr  = brow & 7;

    for (int i = 0; i < NKV; i++) {
        if (i < NKV - 1) {
            int buf = (i + 1) & 1;
            int kb = (i + 1) * 64;
            #pragma unroll
            for (int p = 0; p < 2; p++) {
                int id = tid + p * 256;
                int r = id >> 3, c = id & 7;
                uint32_t so = SW(r, c);
                size_t ko = (size_t)(kb + r) * DK + c * 8;
                size_t vo = (size_t)r * NN + kb + c * 8;
                cp16(sbase + SM_BUF(buf) + SM_KHI + so, kh_g + ko);
                cp16(sbase + SM_BUF(buf) + SM_KLO + so, kl_g + ko);
                cp16(sbase + SM_BUF(buf) + SM_VHI + so, vh_g + vo);
                cp16(sbase + SM_BUF(buf) + SM_VLO + so, vl_g + vo);
            }
            cp_commit();
            cp_wait<1>();
        } else {
            cp_wait<0>();
        }
        __syncthreads();

        const uint32_t kbuf = sbase + SM_BUF(i & 1);

        float s[8][4];
        #pragma unroll
        for (int j = 0; j < 8; j++)
            #pragma unroll
            for (int e = 0; e < 4; e++) s[j][e] = 0.0f;

        #pragma unroll
        for (int ks = 0; ks < 4; ks++) {
            uint32_t qh[4], ql[4];
            uint32_t qcc = 2 * ks + qc;
            ldsm_x4(qh[0], qh[1], qh[2], qh[3], sbase + SM_QHI + qoff + ((qcc ^ qxr) << 4));
            ldsm_x4(ql[0], ql[1], ql[2], ql[3], sbase + SM_QLO + qoff + ((qcc ^ qxr) << 4));
            uint32_t bcc = 2 * ks + bc;
            #pragma unroll
            for (int jp = 0; jp < 4; jp++) {
                uint32_t row = 16 * jp + brow;
                uint32_t off = row * 128 + ((bcc ^ bxr) << 4);
                uint32_t kh0, kh1, kh2, kh3, kl0, kl1, kl2, kl3;
                ldsm_x4(kh0, kh1, kh2, kh3, kbuf + SM_KHI + off);
                ldsm_x4(kl0, kl1, kl2, kl3, kbuf + SM_KLO + off);
                mma16816(s[2 * jp],     qh, kh0, kh1);
                mma16816(s[2 * jp],     qh, kl0, kl1);
                mma16816(s[2 * jp],     ql, kh0, kh1);
                mma16816(s[2 * jp + 1], qh, kh2, kh3);
                mma16816(s[2 * jp + 1], qh, kl2, kl3);
                mma16816(s[2 * jp + 1], ql, kh2, kh3);
            }
        }

        #pragma unroll
        for (int hh = 0; hh < 2; hh++) {
            float mx = -1e30f;
            #pragma unroll
            for (int j = 0; j < 8; j++)
                mx = fmaxf(mx, fmaxf(s[j][2 * hh], s[j][2 * hh + 1]));
            mx = fmaxf(mx, __shfl_xor_sync(0xffffffffu, mx, 1));
            mx = fmaxf(mx, __shfl_xor_sync(0xffffffffu, mx, 2));
            float mNew = fmaxf(mrow[hh], mx);
            float corr = exp2f(mrow[hh] - mNew);
            float rs = 0.0f;
            #pragma unroll
            for (int j = 0; j < 8; j++) {
                float p0 = exp2f(s[j][2 * hh]     - mNew);
                float p1 = exp2f(s[j][2 * hh + 1] - mNew);
                s[j][2 * hh]     = p0;
                s[j][2 * hh + 1] = p1;
                rs += p0 + p1;
            }
            rs += __shfl_xor_sync(0xffffffffu, rs, 1);
            rs += __shfl_xor_sync(0xffffffffu, rs, 2);
            lrow[hh] = lrow[hh] * corr + rs;
            mrow[hh] = mNew;
            #pragma unroll
            for (int j = 0; j < 8; j++) {
                o[j][2 * hh]     *= corr;
                o[j][2 * hh + 1] *= corr;
            }
        }

        #pragma unroll
        for (int ks = 0; ks < 4; ks++) {
            uint32_t ph[4], pl[4];
            split2(s[2 * ks][0],     s[2 * ks][1],     ph[0], pl[0]);
            split2(s[2 * ks][2],     s[2 * ks][3],     ph[1], pl[1]);
            split2(s[2 * ks + 1][0], s[2 * ks + 1][1], ph[2], pl[2]);
            split2(s[2 * ks + 1][2], s[2 * ks + 1][3], ph[3], pl[3]);
            uint32_t bcc = 2 * ks + bc;
            #pragma unroll
            for (int jp = 0; jp < 4; jp++) {
                uint32_t row = 16 * jp + brow;
                uint32_t off = row * 128 + ((bcc ^ bxr) << 4);
                uint32_t vh0, vh1, vh2, vh3, vl0, vl1, vl2, vl3;
                ldsm_x4(vh0, vh1, vh2, vh3, kbuf + SM_VHI + off);
                ldsm_x4(vl0, vl1, vl2, vl3, kbuf + SM_VLO + off);
                mma16816(o[2 * jp],     ph, vh0, vh1);
                mma16816(o[2 * jp],     ph, vl0, vl1);
                mma16816(o[2 * jp],     pl, vh0, vh1);
                mma16816(o[2 * jp + 1], ph, vh2, vh3);
                mma16816(o[2 * jp + 1], ph, vl2, vl3);
                mma16816(o[2 * jp + 1], pl, vh2, vh3);
            }
        }
        __syncthreads();
    }

    // epilogue: merge heads, write SPLIT bf16 -> g_ah/g_al [b*n][512]
    const int b_ = bh >> 3;
    const int h  = bh & 7;
    const int c0 = (lane & 3) * 2;
    const float i0 = 1.0f / lrow[0];
    const float i1 = 1.0f / lrow[1];
    const int ra = m0 + w * 16 + rq;
    #pragma unroll
    for (int j = 0; j < 8; j++) {
        int col = 8 * j + c0;
        uint32_t h0, l0, h1, l1;
        split2(o[j][0] * i0, o[j][1] * i0, h0, l0);
        split2(o[j][2] * i1, o[j][3] * i1, h1, l1);
        size_t off0 = ((size_t)(b_ * NN + ra)) * D_MODEL + h * DK + col;
        size_t off1 = ((size_t)(b_ * NN + ra + 8)) * D_MODEL + h * DK + col;
        *reinterpret_cast<uint32_t*>(&g_ah[off0]) = h0;
        *reinterpret_cast<uint32_t*>(&g_al[off0]) = l0;
        *reinterpret_cast<uint32_t*>(&g_ah[off1]) = h1;
        *reinterpret_cast<uint32_t*>(&g_al[off1]) = l1;
    }
}

// ---------------------------------------------------------------------------
extern "C" void kernel_launch(void* const* d_in, const int* in_sizes, int n_in,
                              void* d_out, int out_size)
{
    (void)in_sizes; (void)n_in; (void)out_size;
    const float* x  = (const float*)d_in[0];
    const float* Wq = (const float*)d_in[1];
    const float* bq = (const float*)d_in[2];
    const float* Wk = (const float*)d_in[3];
    const float* bk = (const float*)d_in[4];
    const float* Wv = (const float*)d_in[5];
    const float* bv = (const float*)d_in[6];
    const float* Wo = (const float*)d_in[7];
    const float* bo = (const float*)d_in[8];

    void *xh, *xl, *wh, *wl, *qh, *ql, *kh, *kl, *vh, *vl, *ah, *al;
    cudaGetSymbolAddress(&xh, g_xh);
    cudaGetSymbolAddress(&xl, g_xl);
    cudaGetSymbolAddress(&wh, g_wh);
    cudaGetSymbolAddress(&wl, g_wl);
    cudaGetSymbolAddress(&qh, g_qh);
    cudaGetSymbolAddress(&ql, g_ql);
    cudaGetSymbolAddress(&kh, g_kh);
    cudaGetSymbolAddress(&kl, g_kl);
    cudaGetSymbolAddress(&vh, g_vth);
    cudaGetSymbolAddress(&vl, g_vtl);
    cudaGetSymbolAddress(&ah, g_ah);
    cudaGetSymbolAddress(&al, g_al);

    __nv_bfloat16* whp = (__nv_bfloat16*)wh;
    __nv_bfloat16* wlp = (__nv_bfloat16*)wl;
    const int WSZ = D_MODEL * D_MODEL;

    cudaFuncSetAttribute(attn_tc, cudaFuncAttributeMaxDynamicSharedMemorySize, ATTN_SMEM);
    cudaFuncSetAttribute(gemm_ps, cudaFuncAttributeMaxDynamicSharedMemorySize, GEMM_SMEM);

    // pre-split inputs
    int n4x = (M_TOTAL * D_MODEL) / 4;
    split_mat<<<(n4x + 255) / 256, 256>>>(x, (__nv_bfloat16*)xh, (__nv_bfloat16*)xl, n4x);
    int n4w = WSZ / 4;
    split_mat<<<(n4w + 255) / 256, 256>>>(Wq, whp + 0 * WSZ, wlp + 0 * WSZ, n4w);
    split_mat<<<(n4w + 255) / 256, 256>>>(Wk, whp + 1 * WSZ, wlp + 1 * WSZ, n4w);
    split_mat<<<(n4w + 255) / 256, 256>>>(Wv, whp + 2 * WSZ, wlp + 2 * WSZ, n4w);
    split_mat<<<(n4w + 255) / 256, 256>>>(Wo, whp + 3 * WSZ, wlp + 3 * WSZ, n4w);

    dim3 gemm_grid(D_MODEL / 64, M_TOTAL / 128);   // (8, 64)
    gemm_ps<<<gemm_grid, 256, GEMM_SMEM>>>((const __nv_bfloat16*)xh, (const __nv_bfloat16*)xl,
                                           whp + 0 * WSZ, wlp + 0 * WSZ, bq, qh, ql, 1, SC_ATTN);
    gemm_ps<<<gemm_grid, 256, GEMM_SMEM>>>((const __nv_bfloat16*)xh, (const __nv_bfloat16*)xl,
                                           whp + 1 * WSZ, wlp + 1 * WSZ, bk, kh, kl, 1, 1.0f);
    gemm_ps<<<gemm_grid, 256, GEMM_SMEM>>>((const __nv_bfloat16*)xh, (const __nv_bfloat16*)xl,
                                           whp + 2 * WSZ, wlp + 2 * WSZ, bv, vh, vl, 2, 1.0f);

    dim3 attn_grid(NN / 128, BH);                  // (16, 32)
    attn_tc<<<attn_grid, 256, ATTN_SMEM>>>();

    gemm_ps<<<gemm_grid, 256, GEMM_SMEM>>>((const __nv_bfloat16*)ah, (const __nv_bfloat16*)al,
                                           whp + 3 * WSZ, wlp + 3 * WSZ, bo, d_out, nullptr, 0, 1.0f);
}

// round 9
// speedup vs baseline: 1.2992x; 1.2992x over previous
#include <cuda_runtime.h>
#include <cuda_bf16.h>
#include <math.h>
#include <stdint.h>

#define D_MODEL 512
#define NHEAD   8
#define DK      64
#define BB      4
#define NN      2048
#define M_TOTAL (BB * NN)     // 8192
#define BH      (BB * NHEAD)  // 32
#define NKV     (NN / 64)     // 32 kv blocks
#define WSZ     (D_MODEL * D_MODEL)

// Q pre-scale: 1/sqrt(64) * log2(e)
#define SC_ATTN 0.18033688f

// ---------------- scratch (allocation-free static device arrays) -----------
__device__ __align__(128) __nv_bfloat16 g_xh[M_TOTAL * D_MODEL];
__device__ __align__(128) __nv_bfloat16 g_xl[M_TOTAL * D_MODEL];
__device__ __align__(128) __nv_bfloat16 g_wth[4 * WSZ]; // W^T [n][k], 4 mats
__device__ __align__(128) __nv_bfloat16 g_wtl[4 * WSZ];
__device__ __align__(128) __nv_bfloat16 g_qh[BH * NN * DK];
__device__ __align__(128) __nv_bfloat16 g_ql[BH * NN * DK];
__device__ __align__(128) __nv_bfloat16 g_kh[BH * NN * DK];
__device__ __align__(128) __nv_bfloat16 g_kl[BH * NN * DK];
__device__ __align__(128) __nv_bfloat16 g_vth[BH * DK * NN]; // [bh][d][n]
__device__ __align__(128) __nv_bfloat16 g_vtl[BH * DK * NN];
__device__ __align__(128) __nv_bfloat16 g_ah[M_TOTAL * D_MODEL]; // attn out split
__device__ __align__(128) __nv_bfloat16 g_al[M_TOTAL * D_MODEL];

// ---------------------------------------------------------------------------
// helpers
// ---------------------------------------------------------------------------
__device__ __forceinline__ uint32_t packb(float x, float y) {
    __nv_bfloat162 t = __floats2bfloat162_rn(x, y);
    return *reinterpret_cast<uint32_t*>(&t);
}
__device__ __forceinline__ void split2(float x, float y, uint32_t& hi, uint32_t& lo) {
    float hx = __bfloat162float(__float2bfloat16(x));
    float hy = __bfloat162float(__float2bfloat16(y));
    hi = packb(hx, hy);
    lo = packb(x - hx, y - hy);
}
__device__ __forceinline__ void mma16816(float* c, const uint32_t* a, uint32_t b0, uint32_t b1) {
    asm volatile(
        "mma.sync.aligned.m16n8k16.row.col.f32.bf16.bf16.f32 "
        "{%0,%1,%2,%3}, {%4,%5,%6,%7}, {%8,%9}, {%0,%1,%2,%3};\n"
        : "+f"(c[0]), "+f"(c[1]), "+f"(c[2]), "+f"(c[3])
        : "r"(a[0]), "r"(a[1]), "r"(a[2]), "r"(a[3]), "r"(b0), "r"(b1));
}
__device__ __forceinline__ void ldsm_x4(uint32_t& d0, uint32_t& d1, uint32_t& d2, uint32_t& d3,
                                        uint32_t saddr) {
    asm volatile("ldmatrix.sync.aligned.m8n8.x4.shared.b16 {%0,%1,%2,%3}, [%4];"
                 : "=r"(d0), "=r"(d1), "=r"(d2), "=r"(d3) : "r"(saddr));
}
__device__ __forceinline__ void cp16(uint32_t dst, const void* src) {
    asm volatile("cp.async.cg.shared.global [%0], [%1], 16;" :: "r"(dst), "l"(src));
}
__device__ __forceinline__ void cp_commit() { asm volatile("cp.async.commit_group;"); }
template<int N> __device__ __forceinline__ void cp_wait() {
    asm volatile("cp.async.wait_group %0;" :: "n"(N));
}
__device__ __forceinline__ uint32_t SW(uint32_t r, uint32_t c) {
    return r * 128u + ((c ^ (r & 7u)) << 4);
}

// ---------------------------------------------------------------------------
// split kernels
// ---------------------------------------------------------------------------
__global__ void __launch_bounds__(256)
split_mat(const float* __restrict__ src, __nv_bfloat16* __restrict__ hi,
          __nv_bfloat16* __restrict__ lo, int n4)
{
    int i = blockIdx.x * 256 + threadIdx.x;
    if (i >= n4) return;
    float4 v = reinterpret_cast<const float4*>(src)[i];
    uint32_t h01, l01, h23, l23;
    split2(v.x, v.y, h01, l01);
    split2(v.z, v.w, h23, l23);
    reinterpret_cast<uint2*>(hi)[i] = make_uint2(h01, h23);
    reinterpret_cast<uint2*>(lo)[i] = make_uint2(l01, l23);
}

// transpose + split: th[n][k] = split(W[k][n])
__global__ void __launch_bounds__(256)
splitT(const float* __restrict__ W, __nv_bfloat16* __restrict__ th,
       __nv_bfloat16* __restrict__ tl)
{
    __shared__ float ts[32][33];
    int n0 = blockIdx.x * 32, k0 = blockIdx.y * 32;
    int tx = threadIdx.x & 31, ty = threadIdx.x >> 5;
    #pragma unroll
    for (int j = 0; j < 4; j++)
        ts[ty + j * 8][tx] = W[(size_t)(k0 + ty + j * 8) * D_MODEL + n0 + tx];
    __syncthreads();
    #pragma unroll
    for (int j = 0; j < 4; j++) {
        int n = ty + j * 8;
        float v = ts[tx][n];
        float hv = __bfloat162float(__float2bfloat16(v));
        th[(size_t)(n0 + n) * D_MODEL + k0 + tx] = __float2bfloat16(hv);
        tl[(size_t)(n0 + n) * D_MODEL + k0 + tx] = __float2bfloat16(v - hv);
    }
}

// ---------------------------------------------------------------------------
// Raw-mma GEMM (attention-S-phase clone): out = A[M,512] @ Wt^T + bias.
// CTA tile 128x64, BK=64, 256 thr / 8 warps; warp = 16 rows x 64 cols.
// cp.async double-buffered swizzled smem; ldmatrix.x4 operands.
// fused=1: QKV (grid.x=24, wsel=cb>>3): Q->mode1*SC_ATTN, K->mode1, V->mode2.
// fused=0: O-projection (grid.x=8): fp32 out.
// ---------------------------------------------------------------------------
#define GS_AHI 0
#define GS_ALO 16384
#define GS_BHI 32768
#define GS_BLO 40960
#define GS_STAGE 49152
#define GEMM_SMEM (2 * GS_STAGE)   // 96 KB

__global__ void __launch_bounds__(256, 2)
gemm_raw(const __nv_bfloat16* __restrict__ Ah, const __nv_bfloat16* __restrict__ Al,
         const __nv_bfloat16* __restrict__ Bh, const __nv_bfloat16* __restrict__ Bl,
         const float* __restrict__ bias_q, const float* __restrict__ bias_k,
         const float* __restrict__ bias_v, float* __restrict__ outf, int fused)
{
    extern __shared__ __align__(128) unsigned char sm[];
    const uint32_t sbase = (uint32_t)__cvta_generic_to_shared(sm);

    const int tid  = threadIdx.x;
    const int lane = tid & 31;
    const int w    = tid >> 5;
    const int rq   = lane >> 2;
    const int cb   = blockIdx.x;
    const int m0   = blockIdx.y * 128;

    const int wsel  = fused ? (cb >> 3) : 3;          // weight matrix select
    const int n_in  = (cb & 7) * 64;                  // col offset within matrix
    const size_t brow0 = (size_t)wsel * D_MODEL + n_in; // row base into Wt[4*512][512]

    auto load_chunk = [&](int kc, int buf) {
        uint32_t base = sbase + buf * GS_STAGE;
        int kb = kc * 64;
        #pragma unroll
        for (int t = 0; t < 4; t++) {        // A: 128 rows x 8 chunks, hi+lo
            int id = tid + t * 256;
            int r = id >> 3, c = id & 7;
            uint32_t so = SW(r, c);
            size_t g = (size_t)(m0 + r) * D_MODEL + kb + c * 8;
            cp16(base + GS_AHI + so, Ah + g);
            cp16(base + GS_ALO + so, Al + g);
        }
        #pragma unroll
        for (int t = 0; t < 2; t++) {        // B: 64 rows x 8 chunks, hi+lo
            int id = tid + t * 256;
            int r = id >> 3, c = id & 7;
            uint32_t so = SW(r, c);
            size_t g = (brow0 + r) * D_MODEL + kb + c * 8;
            cp16(base + GS_BHI + so, Bh + g);
            cp16(base + GS_BLO + so, Bl + g);
        }
        cp_commit();
    };

    float s[8][4];
    #pragma unroll
    for (int j = 0; j < 8; j++)
        #pragma unroll
        for (int e = 0; e < 4; e++) s[j][e] = 0.0f;

    const uint32_t qrow = w * 16 + (lane & 15);
    const uint32_t qc   = lane >> 4;
    const uint32_t qoff = qrow * 128;
    const uint32_t qxr  = qrow & 7;
    const uint32_t brow = ((lane >> 4) << 3) + (lane & 7);
    const uint32_t bc   = (lane >> 3) & 1;
    const uint32_t bxr  = brow & 7;

    load_chunk(0, 0);
    load_chunk(1, 1);

    for (int i = 0; i < 8; i++) {
        if (i == 7) cp_wait<0>(); else cp_wait<1>();
        __syncthreads();
        const uint32_t abuf = sbase + (i & 1) * GS_STAGE;

        #pragma unroll
        for (int ks = 0; ks < 4; ks++) {
            uint32_t ah[4], al[4];
            uint32_t qcc = 2 * ks + qc;
            ldsm_x4(ah[0], ah[1], ah[2], ah[3], abuf + GS_AHI + qoff + ((qcc ^ qxr) << 4));
            ldsm_x4(al[0], al[1], al[2], al[3], abuf + GS_ALO + qoff + ((qcc ^ qxr) << 4));
            uint32_t bcc = 2 * ks + bc;
            #pragma unroll
            for (int jp = 0; jp < 4; jp++) {
                uint32_t row = 16 * jp + brow;
                uint32_t off = row * 128 + ((bcc ^ bxr) << 4);
                uint32_t bh0, bh1, bh2, bh3, bl0, bl1, bl2, bl3;
                ldsm_x4(bh0, bh1, bh2, bh3, abuf + GS_BHI + off);
                ldsm_x4(bl0, bl1, bl2, bl3, abuf + GS_BLO + off);
                mma16816(s[2 * jp],     ah, bh0, bh1);
                mma16816(s[2 * jp],     ah, bl0, bl1);
                mma16816(s[2 * jp],     al, bh0, bh1);
                mma16816(s[2 * jp + 1], ah, bh2, bh3);
                mma16816(s[2 * jp + 1], ah, bl2, bl3);
                mma16816(s[2 * jp + 1], al, bh2, bh3);
            }
        }
        __syncthreads();
        if (i + 2 < 8) load_chunk(i + 2, i & 1);
    }

    // ---- stage accumulators in smem (f32 [128][68]) ----
    float* Cst = (float*)sm;
    {
        const int c0 = (lane & 3) * 2;
        const int ra = w * 16 + rq;
        #pragma unroll
        for (int j = 0; j < 8; j++) {
            int col = 8 * j + c0;
            Cst[ra * 68 + col]           = s[j][0];
            Cst[ra * 68 + col + 1]       = s[j][1];
            Cst[(ra + 8) * 68 + col]     = s[j][2];
            Cst[(ra + 8) * 68 + col + 1] = s[j][3];
        }
    }
    __syncthreads();

    if (!fused) {
        // mode 0: fp32 [row][512], cols n_in..n_in+63 of output
        const int orow = tid >> 4;
        const int ocol = (tid & 15) * 4;
        float4 b4 = *reinterpret_cast<const float4*>(&bias_q[n_in + ocol]);
        #pragma unroll
        for (int t = 0; t < 8; t++) {
            int r = orow + t * 16;
            float4 v = *reinterpret_cast<const float4*>(&Cst[r * 68 + ocol]);
            v.x += b4.x; v.y += b4.y; v.z += b4.z; v.w += b4.w;
            *reinterpret_cast<float4*>(&outf[(size_t)(m0 + r) * D_MODEL + n_in + ocol]) = v;
        }
    } else if (wsel < 2) {
        // mode 1: split bf16 [bh][n][64], (Q gets SC_ATTN)
        const float scale = (wsel == 0) ? SC_ATTN : 1.0f;
        __nv_bfloat16* ohi = (wsel == 0) ? g_qh : g_kh;
        __nv_bfloat16* olo = (wsel == 0) ? g_ql : g_kl;
        const float* bias = (wsel == 0) ? bias_q : bias_k;
        const int h = cb & 7;
        const int orow = tid >> 4;
        const int ocol = (tid & 15) * 4;
        float4 b4 = *reinterpret_cast<const float4*>(&bias[n_in + ocol]);
        #pragma unroll
        for (int t = 0; t < 8; t++) {
            int r  = orow + t * 16;
            int rg = m0 + r;
            int b_ = rg >> 11;
            int n_ = rg & 2047;
            float4 v = *reinterpret_cast<const float4*>(&Cst[r * 68 + ocol]);
            float v0 = (v.x + b4.x) * scale;
            float v1 = (v.y + b4.y) * scale;
            float v2 = (v.z + b4.z) * scale;
            float v3 = (v.w + b4.w) * scale;
            uint32_t h01, l01, h23, l23;
            split2(v0, v1, h01, l01);
            split2(v2, v3, h23, l23);
            size_t off = ((size_t)(b_ * NHEAD + h) * NN + n_) * DK + ocol;
            *reinterpret_cast<uint2*>(&ohi[off]) = make_uint2(h01, h23);
            *reinterpret_cast<uint2*>(&olo[off]) = make_uint2(l01, l23);
        }
    } else {
        // mode 2: V transposed split bf16 [bh][d][n]
        const int h   = cb & 7;
        const int od  = tid >> 2;
        const int on0 = (tid & 3) * 32;
        const int b_  = m0 >> 11;
        const int nb  = (m0 & 2047) + on0;
        const float bv = bias_v[n_in + od];
        size_t rowoff = ((size_t)(b_ * NHEAD + h) * DK + od) * NN + nb;
        #pragma unroll
        for (int i = 0; i < 32; i += 2) {
            float v0 = Cst[(on0 + i) * 68 + od] + bv;
            float v1 = Cst[(on0 + i + 1) * 68 + od] + bv;
            uint32_t hp, lp;
            split2(v0, v1, hp, lp);
            *reinterpret_cast<uint32_t*>(&g_vth[rowoff + i]) = hp;
            *reinterpret_cast<uint32_t*>(&g_vtl[rowoff + i]) = lp;
        }
    }
}

// ---------------------------------------------------------------------------
// Flash attention (unchanged): BM=128, BN=64, d=64, 256 thr, 2 CTAs/SM.
// ---------------------------------------------------------------------------
#define SM_QHI 0
#define SM_QLO 16384
#define SM_BUF(b) (32768 + (b) * 32768)
#define SM_KHI 0
#define SM_KLO 8192
#define SM_VHI 16384
#define SM_VLO 24576
#define ATTN_SMEM (32768 + 2 * 32768)   // 96 KB

__global__ void __launch_bounds__(256, 2)
attn_tc()
{
    extern __shared__ __align__(128) unsigned char sm[];
    const uint32_t sbase = (uint32_t)__cvta_generic_to_shared(sm);

    const int tid  = threadIdx.x;
    const int lane = tid & 31;
    const int w    = tid >> 5;
    const int rq   = lane >> 2;
    const int bh   = blockIdx.y;
    const int m0   = blockIdx.x * 128;

    const __nv_bfloat16* qh_g = g_qh + (size_t)bh * NN * DK;
    const __nv_bfloat16* ql_g = g_ql + (size_t)bh * NN * DK;
    const __nv_bfloat16* kh_g = g_kh + (size_t)bh * NN * DK;
    const __nv_bfloat16* kl_g = g_kl + (size_t)bh * NN * DK;
    const __nv_bfloat16* vh_g = g_vth + (size_t)bh * DK * NN;
    const __nv_bfloat16* vl_g = g_vtl + (size_t)bh * DK * NN;

    {
        #pragma unroll
        for (int p = 0; p < 4; p++) {
            int id = tid + p * 256;
            int r = id >> 3, c = id & 7;
            size_t go = (size_t)(m0 + r) * DK + c * 8;
            uint32_t so = SW(r, c);
            cp16(sbase + SM_QHI + so, qh_g + go);
            cp16(sbase + SM_QLO + so, ql_g + go);
        }
        cp_commit();
    }
    {
        #pragma unroll
        for (int p = 0; p < 2; p++) {
            int id = tid + p * 256;
            int r = id >> 3, c = id & 7;
            uint32_t so = SW(r, c);
            size_t ko = (size_t)r * DK + c * 8;
            size_t vo = (size_t)r * NN + c * 8;
            cp16(sbase + SM_BUF(0) + SM_KHI + so, kh_g + ko);
            cp16(sbase + SM_BUF(0) + SM_KLO + so, kl_g + ko);
            cp16(sbase + SM_BUF(0) + SM_VHI + so, vh_g + vo);
            cp16(sbase + SM_BUF(0) + SM_VLO + so, vl_g + vo);
        }
        cp_commit();
    }

    float o[8][4];
    #pragma unroll
    for (int j = 0; j < 8; j++)
        #pragma unroll
        for (int e = 0; e < 4; e++) o[j][e] = 0.0f;
    float mrow[2] = {-1e30f, -1e30f};
    float lrow[2] = {0.0f, 0.0f};

    const uint32_t qrow = w * 16 + (lane & 15);
    const uint32_t qc   = lane >> 4;
    const uint32_t qoff = qrow * 128;
    const uint32_t qxr  = qrow & 7;
    const uint32_t brow = ((lane >> 4) << 3) + (lane & 7);
    const uint32_t bc   = (lane >> 3) & 1;
    const uint32_t bxr  = brow & 7;

    for (int i = 0; i < NKV; i++) {
        if (i < NKV - 1) {
            int buf = (i + 1) & 1;
            int kb = (i + 1) * 64;
            #pragma unroll
            for (int p = 0; p < 2; p++) {
                int id = tid + p * 256;
                int r = id >> 3, c = id & 7;
                uint32_t so = SW(r, c);
                size_t ko = (size_t)(kb + r) * DK + c * 8;
                size_t vo = (size_t)r * NN + kb + c * 8;
                cp16(sbase + SM_BUF(buf) + SM_KHI + so, kh_g + ko);
                cp16(sbase + SM_BUF(buf) + SM_KLO + so, kl_g + ko);
                cp16(sbase + SM_BUF(buf) + SM_VHI + so, vh_g + vo);
                cp16(sbase + SM_BUF(buf) + SM_VLO + so, vl_g + vo);
            }
            cp_commit();
            cp_wait<1>();
        } else {
            cp_wait<0>();
        }
        __syncthreads();

        const uint32_t kbuf = sbase + SM_BUF(i & 1);

        float s[8][4];
        #pragma unroll
        for (int j = 0; j < 8; j++)
            #pragma unroll
            for (int e = 0; e < 4; e++) s[j][e] = 0.0f;

        #pragma unroll
        for (int ks = 0; ks < 4; ks++) {
            uint32_t qh[4], ql[4];
            uint32_t qcc = 2 * ks + qc;
            ldsm_x4(qh[0], qh[1], qh[2], qh[3], sbase + SM_QHI + qoff + ((qcc ^ qxr) << 4));
            ldsm_x4(ql[0], ql[1], ql[2], ql[3], sbase + SM_QLO + qoff + ((qcc ^ qxr) << 4));
            uint32_t bcc = 2 * ks + bc;
            #pragma unroll
            for (int jp = 0; jp < 4; jp++) {
                uint32_t row = 16 * jp + brow;
                uint32_t off = row * 128 + ((bcc ^ bxr) << 4);
                uint32_t kh0, kh1, kh2, kh3, kl0, kl1, kl2, kl3;
                ldsm_x4(kh0, kh1, kh2, kh3, kbuf + SM_KHI + off);
                ldsm_x4(kl0, kl1, kl2, kl3, kbuf + SM_KLO + off);
                mma16816(s[2 * jp],     qh, kh0, kh1);
                mma16816(s[2 * jp],     qh, kl0, kl1);
                mma16816(s[2 * jp],     ql, kh0, kh1);
                mma16816(s[2 * jp + 1], qh, kh2, kh3);
                mma16816(s[2 * jp + 1], qh, kl2, kl3);
                mma16816(s[2 * jp + 1], ql, kh2, kh3);
            }
        }

        #pragma unroll
        for (int hh = 0; hh < 2; hh++) {
            float mx = -1e30f;
            #pragma unroll
            for (int j = 0; j < 8; j++)
                mx = fmaxf(mx, fmaxf(s[j][2 * hh], s[j][2 * hh + 1]));
            mx = fmaxf(mx, __shfl_xor_sync(0xffffffffu, mx, 1));
            mx = fmaxf(mx, __shfl_xor_sync(0xffffffffu, mx, 2));
            float mNew = fmaxf(mrow[hh], mx);
            float corr = exp2f(mrow[hh] - mNew);
            float rs = 0.0f;
            #pragma unroll
            for (int j = 0; j < 8; j++) {
                float p0 = exp2f(s[j][2 * hh]     - mNew);
                float p1 = exp2f(s[j][2 * hh + 1] - mNew);
                s[j][2 * hh]     = p0;
                s[j][2 * hh + 1] = p1;
                rs += p0 + p1;
            }
            rs += __shfl_xor_sync(0xffffffffu, rs, 1);
            rs += __shfl_xor_sync(0xffffffffu, rs, 2);
            lrow[hh] = lrow[hh] * corr + rs;
            mrow[hh] = mNew;
            #pragma unroll
            for (int j = 0; j < 8; j++) {
                o[j][2 * hh]     *= corr;
                o[j][2 * hh + 1] *= corr;
            }
        }

        #pragma unroll
        for (int ks = 0; ks < 4; ks++) {
            uint32_t ph[4], pl[4];
            split2(s[2 * ks][0],     s[2 * ks][1],     ph[0], pl[0]);
            split2(s[2 * ks][2],     s[2 * ks][3],     ph[1], pl[1]);
            split2(s[2 * ks + 1][0], s[2 * ks + 1][1], ph[2], pl[2]);
            split2(s[2 * ks + 1][2], s[2 * ks + 1][3], ph[3], pl[3]);
            uint32_t bcc = 2 * ks + bc;
            #pragma unroll
            for (int jp = 0; jp < 4; jp++) {
                uint32_t row = 16 * jp + brow;
                uint32_t off = row * 128 + ((bcc ^ bxr) << 4);
                uint32_t vh0, vh1, vh2, vh3, vl0, vl1, vl2, vl3;
                ldsm_x4(vh0, vh1, vh2, vh3, kbuf + SM_VHI + off);
                ldsm_x4(vl0, vl1, vl2, vl3, kbuf + SM_VLO + off);
                mma16816(o[2 * jp],     ph, vh0, vh1);
                mma16816(o[2 * jp],     ph, vl0, vl1);
                mma16816(o[2 * jp],     pl, vh0, vh1);
                mma16816(o[2 * jp + 1], ph, vh2, vh3);
                mma16816(o[2 * jp + 1], ph, vl2, vl3);
                mma16816(o[2 * jp + 1], pl, vh2, vh3);
            }
        }
        __syncthreads();
    }

    const int b_ = bh >> 3;
    const int h  = bh & 7;
    const int c0 = (lane & 3) * 2;
    const float i0 = 1.0f / lrow[0];
    const float i1 = 1.0f / lrow[1];
    const int ra = m0 + w * 16 + rq;
    #pragma unroll
    for (int j = 0; j < 8; j++) {
        int col = 8 * j + c0;
        uint32_t h0, l0, h1, l1;
        split2(o[j][0] * i0, o[j][1] * i0, h0, l0);
        split2(o[j][2] * i1, o[j][3] * i1, h1, l1);
        size_t off0 = ((size_t)(b_ * NN + ra)) * D_MODEL + h * DK + col;
        size_t off1 = ((size_t)(b_ * NN + ra + 8)) * D_MODEL + h * DK + col;
        *reinterpret_cast<uint32_t*>(&g_ah[off0]) = h0;
        *reinterpret_cast<uint32_t*>(&g_al[off0]) = l0;
        *reinterpret_cast<uint32_t*>(&g_ah[off1]) = h1;
        *reinterpret_cast<uint32_t*>(&g_al[off1]) = l1;
    }
}

// ---------------------------------------------------------------------------
extern "C" void kernel_launch(void* const* d_in, const int* in_sizes, int n_in,
                              void* d_out, int out_size)
{
    (void)in_sizes; (void)n_in; (void)out_size;
    const float* x  = (const float*)d_in[0];
    const float* Wq = (const float*)d_in[1];
    const float* bq = (const float*)d_in[2];
    const float* Wk = (const float*)d_in[3];
    const float* bk = (const float*)d_in[4];
    const float* Wv = (const float*)d_in[5];
    const float* bv = (const float*)d_in[6];
    const float* Wo = (const float*)d_in[7];
    const float* bo = (const float*)d_in[8];

    void *xh, *xl, *wth, *wtl, *ah, *al;
    cudaGetSymbolAddress(&xh, g_xh);
    cudaGetSymbolAddress(&xl, g_xl);
    cudaGetSymbolAddress(&wth, g_wth);
    cudaGetSymbolAddress(&wtl, g_wtl);
    cudaGetSymbolAddress(&ah, g_ah);
    cudaGetSymbolAddress(&al, g_al);

    __nv_bfloat16* whp = (__nv_bfloat16*)wth;
    __nv_bfloat16* wlp = (__nv_bfloat16*)wtl;

    cudaFuncSetAttribute(attn_tc, cudaFuncAttributeMaxDynamicSharedMemorySize, ATTN_SMEM);
    cudaFuncSetAttribute(gemm_raw, cudaFuncAttributeMaxDynamicSharedMemorySize, GEMM_SMEM);

    int n4x = (M_TOTAL * D_MODEL) / 4;
    split_mat<<<(n4x + 255) / 256, 256>>>(x, (__nv_bfloat16*)xh, (__nv_bfloat16*)xl, n4x);
    dim3 tg(16, 16);
    splitT<<<tg, 256>>>(Wq, whp + 0 * WSZ, wlp + 0 * WSZ);
    splitT<<<tg, 256>>>(Wk, whp + 1 * WSZ, wlp + 1 * WSZ);
    splitT<<<tg, 256>>>(Wv, whp + 2 * WSZ, wlp + 2 * WSZ);
    splitT<<<tg, 256>>>(Wo, whp + 3 * WSZ, wlp + 3 * WSZ);

    // fused QKV projection: grid (24, 64)
    dim3 qkv_grid(24, M_TOTAL / 128);
    gemm_raw<<<qkv_grid, 256, GEMM_SMEM>>>((const __nv_bfloat16*)xh, (const __nv_bfloat16*)xl,
                                           whp, wlp, bq, bk, bv, nullptr, 1);

    dim3 attn_grid(NN / 128, BH);   // (16, 32)
    attn_tc<<<attn_grid, 256, ATTN_SMEM>>>();

    // O projection: grid (8, 64)
    dim3 o_grid(8, M_TOTAL / 128);
    gemm_raw<<<o_grid, 256, GEMM_SMEM>>>((const __nv_bfloat16*)ah, (const __nv_bfloat16*)al,
                                         whp, wlp, bo, nullptr, nullptr, (float*)d_out, 0);
}

// round 10
// speedup vs baseline: 1.4831x; 1.1415x over previous
#include <cuda_runtime.h>
#include <cuda_bf16.h>
#include <math.h>
#include <stdint.h>

#define D_MODEL 512
#define NHEAD   8
#define DK      64
#define BB      4
#define NN      2048
#define M_TOTAL (BB * NN)     // 8192
#define BH      (BB * NHEAD)  // 32
#define NKV     (NN / 64)     // 32 kv blocks
#define WSZ     (D_MODEL * D_MODEL)

// Q pre-scale: 1/sqrt(64) * log2(e)
#define SC_ATTN 0.18033688f

// ---------------- scratch (allocation-free static device arrays) -----------
__device__ __align__(128) __nv_bfloat16 g_xh[M_TOTAL * D_MODEL];
__device__ __align__(128) __nv_bfloat16 g_xl[M_TOTAL * D_MODEL];
__device__ __align__(128) __nv_bfloat16 g_wth[4 * WSZ]; // W^T [n][k], 4 mats
__device__ __align__(128) __nv_bfloat16 g_wtl[4 * WSZ];
__device__ __align__(128) __nv_bfloat16 g_qh[BH * NN * DK];
__device__ __align__(128) __nv_bfloat16 g_ql[BH * NN * DK];
__device__ __align__(128) __nv_bfloat16 g_kh[BH * NN * DK];
__device__ __align__(128) __nv_bfloat16 g_kl[BH * NN * DK];
__device__ __align__(128) __nv_bfloat16 g_vth[BH * DK * NN]; // [bh][d][n]
__device__ __align__(128) __nv_bfloat16 g_vtl[BH * DK * NN];
__device__ __align__(128) __nv_bfloat16 g_ah[M_TOTAL * D_MODEL]; // attn out split
__device__ __align__(128) __nv_bfloat16 g_al[M_TOTAL * D_MODEL];

// ---------------------------------------------------------------------------
// helpers
// ---------------------------------------------------------------------------
__device__ __forceinline__ uint32_t packb(float x, float y) {
    __nv_bfloat162 t = __floats2bfloat162_rn(x, y);
    return *reinterpret_cast<uint32_t*>(&t);
}
__device__ __forceinline__ void split2(float x, float y, uint32_t& hi, uint32_t& lo) {
    float hx = __bfloat162float(__float2bfloat16(x));
    float hy = __bfloat162float(__float2bfloat16(y));
    hi = packb(hx, hy);
    lo = packb(x - hx, y - hy);
}
__device__ __forceinline__ float rnd_bf(float x) {
    return __bfloat162float(__float2bfloat16(x));
}
__device__ __forceinline__ void mma16816(float* c, const uint32_t* a, uint32_t b0, uint32_t b1) {
    asm volatile(
        "mma.sync.aligned.m16n8k16.row.col.f32.bf16.bf16.f32 "
        "{%0,%1,%2,%3}, {%4,%5,%6,%7}, {%8,%9}, {%0,%1,%2,%3};\n"
        : "+f"(c[0]), "+f"(c[1]), "+f"(c[2]), "+f"(c[3])
        : "r"(a[0]), "r"(a[1]), "r"(a[2]), "r"(a[3]), "r"(b0), "r"(b1));
}
__device__ __forceinline__ void ldsm_x4(uint32_t& d0, uint32_t& d1, uint32_t& d2, uint32_t& d3,
                                        uint32_t saddr) {
    asm volatile("ldmatrix.sync.aligned.m8n8.x4.shared.b16 {%0,%1,%2,%3}, [%4];"
                 : "=r"(d0), "=r"(d1), "=r"(d2), "=r"(d3) : "r"(saddr));
}
__device__ __forceinline__ void cp16(uint32_t dst, const void* src) {
    asm volatile("cp.async.cg.shared.global [%0], [%1], 16;" :: "r"(dst), "l"(src));
}
__device__ __forceinline__ void cp_commit() { asm volatile("cp.async.commit_group;"); }
template<int N> __device__ __forceinline__ void cp_wait() {
    asm volatile("cp.async.wait_group %0;" :: "n"(N));
}
__device__ __forceinline__ uint32_t SW(uint32_t r, uint32_t c) {
    return r * 128u + ((c ^ (r & 7u)) << 4);
}

// ---------------------------------------------------------------------------
// fused prep: x hi/lo split + 4x weight transpose/split, one launch.
// blocks [0, NXB): x split; [NXB, NXB+1024): W transpose (256 blocks per mat)
// ---------------------------------------------------------------------------
#define NXB ((M_TOTAL * D_MODEL / 4) / 256)   // 4096

__global__ void __launch_bounds__(256)
prep_all(const float* __restrict__ x,
         const float* __restrict__ W0, const float* __restrict__ W1,
         const float* __restrict__ W2, const float* __restrict__ W3)
{
    const int bid = blockIdx.x;
    if (bid < NXB) {
        int i = bid * 256 + threadIdx.x;
        float4 v = reinterpret_cast<const float4*>(x)[i];
        uint32_t h01, l01, h23, l23;
        split2(v.x, v.y, h01, l01);
        split2(v.z, v.w, h23, l23);
        reinterpret_cast<uint2*>(g_xh)[i] = make_uint2(h01, h23);
        reinterpret_cast<uint2*>(g_xl)[i] = make_uint2(l01, l23);
        return;
    }
    __shared__ float ts[32][33];
    const int t   = bid - NXB;
    const int mat = t >> 8;
    const int blk = t & 255;
    const float* W = (mat == 0) ? W0 : (mat == 1) ? W1 : (mat == 2) ? W2 : W3;
    __nv_bfloat16* th = g_wth + (size_t)mat * WSZ;
    __nv_bfloat16* tl = g_wtl + (size_t)mat * WSZ;
    int n0 = (blk & 15) * 32, k0 = (blk >> 4) * 32;
    int tx = threadIdx.x & 31, ty = threadIdx.x >> 5;
    #pragma unroll
    for (int j = 0; j < 4; j++)
        ts[ty + j * 8][tx] = W[(size_t)(k0 + ty + j * 8) * D_MODEL + n0 + tx];
    __syncthreads();
    #pragma unroll
    for (int j = 0; j < 4; j++) {
        int n = ty + j * 8;
        float v = ts[tx][n];
        float hv = rnd_bf(v);
        th[(size_t)(n0 + n) * D_MODEL + k0 + tx] = __float2bfloat16(hv);
        tl[(size_t)(n0 + n) * D_MODEL + k0 + tx] = __float2bfloat16(v - hv);
    }
}

// ---------------------------------------------------------------------------
// Raw-mma GEMM: out = A[M,512] @ Wt^T + bias.  (unchanged from R9)
// CTA tile 128x64, BK=64, 256 thr / 8 warps.
// fused=1: QKV (grid.x=24): Q->mode1*SC_ATTN, K->mode1, V->mode2.
// fused=0: O-projection (grid.x=8): fp32 out.
// ---------------------------------------------------------------------------
#define GS_AHI 0
#define GS_ALO 16384
#define GS_BHI 32768
#define GS_BLO 40960
#define GS_STAGE 49152
#define GEMM_SMEM (2 * GS_STAGE)   // 96 KB

__global__ void __launch_bounds__(256, 2)
gemm_raw(const __nv_bfloat16* __restrict__ Ah, const __nv_bfloat16* __restrict__ Al,
         const __nv_bfloat16* __restrict__ Bh, const __nv_bfloat16* __restrict__ Bl,
         const float* __restrict__ bias_q, const float* __restrict__ bias_k,
         const float* __restrict__ bias_v, float* __restrict__ outf, int fused)
{
    extern __shared__ __align__(128) unsigned char sm[];
    const uint32_t sbase = (uint32_t)__cvta_generic_to_shared(sm);

    const int tid  = threadIdx.x;
    const int lane = tid & 31;
    const int w    = tid >> 5;
    const int rq   = lane >> 2;
    const int cb   = blockIdx.x;
    const int m0   = blockIdx.y * 128;

    const int wsel  = fused ? (cb >> 3) : 3;
    const int n_in  = (cb & 7) * 64;
    const size_t brow0 = (size_t)wsel * D_MODEL + n_in;

    auto load_chunk = [&](int kc, int buf) {
        uint32_t base = sbase + buf * GS_STAGE;
        int kb = kc * 64;
        #pragma unroll
        for (int t = 0; t < 4; t++) {
            int id = tid + t * 256;
            int r = id >> 3, c = id & 7;
            uint32_t so = SW(r, c);
            size_t g = (size_t)(m0 + r) * D_MODEL + kb + c * 8;
            cp16(base + GS_AHI + so, Ah + g);
            cp16(base + GS_ALO + so, Al + g);
        }
        #pragma unroll
        for (int t = 0; t < 2; t++) {
            int id = tid + t * 256;
            int r = id >> 3, c = id & 7;
            uint32_t so = SW(r, c);
            size_t g = (brow0 + r) * D_MODEL + kb + c * 8;
            cp16(base + GS_BHI + so, Bh + g);
            cp16(base + GS_BLO + so, Bl + g);
        }
        cp_commit();
    };

    float s[8][4];
    #pragma unroll
    for (int j = 0; j < 8; j++)
        #pragma unroll
        for (int e = 0; e < 4; e++) s[j][e] = 0.0f;

    const uint32_t qrow = w * 16 + (lane & 15);
    const uint32_t qc   = lane >> 4;
    const uint32_t qoff = qrow * 128;
    const uint32_t qxr  = qrow & 7;
    const uint32_t brow = ((lane >> 4) << 3) + (lane & 7);
    const uint32_t bc   = (lane >> 3) & 1;
    const uint32_t bxr  = brow & 7;

    load_chunk(0, 0);
    load_chunk(1, 1);

    for (int i = 0; i < 8; i++) {
        if (i == 7) cp_wait<0>(); else cp_wait<1>();
        __syncthreads();
        const uint32_t abuf = sbase + (i & 1) * GS_STAGE;

        #pragma unroll
        for (int ks = 0; ks < 4; ks++) {
            uint32_t ah[4], al[4];
            uint32_t qcc = 2 * ks + qc;
            ldsm_x4(ah[0], ah[1], ah[2], ah[3], abuf + GS_AHI + qoff + ((qcc ^ qxr) << 4));
            ldsm_x4(al[0], al[1], al[2], al[3], abuf + GS_ALO + qoff + ((qcc ^ qxr) << 4));
            uint32_t bcc = 2 * ks + bc;
            #pragma unroll
            for (int jp = 0; jp < 4; jp++) {
                uint32_t row = 16 * jp + brow;
                uint32_t off = row * 128 + ((bcc ^ bxr) << 4);
                uint32_t bh0, bh1, bh2, bh3, bl0, bl1, bl2, bl3;
                ldsm_x4(bh0, bh1, bh2, bh3, abuf + GS_BHI + off);
                ldsm_x4(bl0, bl1, bl2, bl3, abuf + GS_BLO + off);
                mma16816(s[2 * jp],     ah, bh0, bh1);
                mma16816(s[2 * jp],     ah, bl0, bl1);
                mma16816(s[2 * jp],     al, bh0, bh1);
                mma16816(s[2 * jp + 1], ah, bh2, bh3);
                mma16816(s[2 * jp + 1], ah, bl2, bl3);
                mma16816(s[2 * jp + 1], al, bh2, bh3);
            }
        }
        __syncthreads();
        if (i + 2 < 8) load_chunk(i + 2, i & 1);
    }

    float* Cst = (float*)sm;
    {
        const int c0 = (lane & 3) * 2;
        const int ra = w * 16 + rq;
        #pragma unroll
        for (int j = 0; j < 8; j++) {
            int col = 8 * j + c0;
            Cst[ra * 68 + col]           = s[j][0];
            Cst[ra * 68 + col + 1]       = s[j][1];
            Cst[(ra + 8) * 68 + col]     = s[j][2];
            Cst[(ra + 8) * 68 + col + 1] = s[j][3];
        }
    }
    __syncthreads();

    if (!fused) {
        const int orow = tid >> 4;
        const int ocol = (tid & 15) * 4;
        float4 b4 = *reinterpret_cast<const float4*>(&bias_q[n_in + ocol]);
        #pragma unroll
        for (int t = 0; t < 8; t++) {
            int r = orow + t * 16;
            float4 v = *reinterpret_cast<const float4*>(&Cst[r * 68 + ocol]);
            v.x += b4.x; v.y += b4.y; v.z += b4.z; v.w += b4.w;
            *reinterpret_cast<float4*>(&outf[(size_t)(m0 + r) * D_MODEL + n_in + ocol]) = v;
        }
    } else if (wsel < 2) {
        const float scale = (wsel == 0) ? SC_ATTN : 1.0f;
        __nv_bfloat16* ohi = (wsel == 0) ? g_qh : g_kh;
        __nv_bfloat16* olo = (wsel == 0) ? g_ql : g_kl;
        const float* bias = (wsel == 0) ? bias_q : bias_k;
        const int h = cb & 7;
        const int orow = tid >> 4;
        const int ocol = (tid & 15) * 4;
        float4 b4 = *reinterpret_cast<const float4*>(&bias[n_in + ocol]);
        #pragma unroll
        for (int t = 0; t < 8; t++) {
            int r  = orow + t * 16;
            int rg = m0 + r;
            int b_ = rg >> 11;
            int n_ = rg & 2047;
            float4 v = *reinterpret_cast<const float4*>(&Cst[r * 68 + ocol]);
            float v0 = (v.x + b4.x) * scale;
            float v1 = (v.y + b4.y) * scale;
            float v2 = (v.z + b4.z) * scale;
            float v3 = (v.w + b4.w) * scale;
            uint32_t h01, l01, h23, l23;
            split2(v0, v1, h01, l01);
            split2(v2, v3, h23, l23);
            size_t off = ((size_t)(b_ * NHEAD + h) * NN + n_) * DK + ocol;
            *reinterpret_cast<uint2*>(&ohi[off]) = make_uint2(h01, h23);
            *reinterpret_cast<uint2*>(&olo[off]) = make_uint2(l01, l23);
        }
    } else {
        const int h   = cb & 7;
        const int od  = tid >> 2;
        const int on0 = (tid & 3) * 32;
        const int b_  = m0 >> 11;
        const int nb  = (m0 & 2047) + on0;
        const float bv = bias_v[n_in + od];
        size_t rowoff = ((size_t)(b_ * NHEAD + h) * DK + od) * NN + nb;
        #pragma unroll
        for (int i = 0; i < 32; i += 2) {
            float v0 = Cst[(on0 + i) * 68 + od] + bv;
            float v1 = Cst[(on0 + i + 1) * 68 + od] + bv;
            uint32_t hp, lp;
            split2(v0, v1, hp, lp);
            *reinterpret_cast<uint32_t*>(&g_vth[rowoff + i]) = hp;
            *reinterpret_cast<uint32_t*>(&g_vtl[rowoff + i]) = lp;
        }
    }
}

// ---------------------------------------------------------------------------
// Flash attention: BM=128, BN=64, d=64, 256 thr, 2 CTAs/SM.
// PV now 2-MMA: P single-limb bf16, denominator = sum of ROUNDED p's
// (weight-perturbation formulation -> quantization error self-cancels).
// ---------------------------------------------------------------------------
#define SM_QHI 0
#define SM_QLO 16384
#define SM_BUF(b) (32768 + (b) * 32768)
#define SM_KHI 0
#define SM_KLO 8192
#define SM_VHI 16384
#define SM_VLO 24576
#define ATTN_SMEM (32768 + 2 * 32768)   // 96 KB

__global__ void __launch_bounds__(256, 2)
attn_tc()
{
    extern __shared__ __align__(128) unsigned char sm[];
    const uint32_t sbase = (uint32_t)__cvta_generic_to_shared(sm);

    const int tid  = threadIdx.x;
    const int lane = tid & 31;
    const int w    = tid >> 5;
    const int rq   = lane >> 2;
    const int bh   = blockIdx.y;
    const int m0   = blockIdx.x * 128;

    const __nv_bfloat16* qh_g = g_qh + (size_t)bh * NN * DK;
    const __nv_bfloat16* ql_g = g_ql + (size_t)bh * NN * DK;
    const __nv_bfloat16* kh_g = g_kh + (size_t)bh * NN * DK;
    const __nv_bfloat16* kl_g = g_kl + (size_t)bh * NN * DK;
    const __nv_bfloat16* vh_g = g_vth + (size_t)bh * DK * NN;
    const __nv_bfloat16* vl_g = g_vtl + (size_t)bh * DK * NN;

    {
        #pragma unroll
        for (int p = 0; p < 4; p++) {
            int id = tid + p * 256;
            int r = id >> 3, c = id & 7;
            size_t go = (size_t)(m0 + r) * DK + c * 8;
            uint32_t so = SW(r, c);
            cp16(sbase + SM_QHI + so, qh_g + go);
            cp16(sbase + SM_QLO + so, ql_g + go);
        }
        cp_commit();
    }
    {
        #pragma unroll
        for (int p = 0; p < 2; p++) {
            int id = tid + p * 256;
            int r = id >> 3, c = id & 7;
            uint32_t so = SW(r, c);
            size_t ko = (size_t)r * DK + c * 8;
            size_t vo = (size_t)r * NN + c * 8;
            cp16(sbase + SM_BUF(0) + SM_KHI + so, kh_g + ko);
            cp16(sbase + SM_BUF(0) + SM_KLO + so, kl_g + ko);
            cp16(sbase + SM_BUF(0) + SM_VHI + so, vh_g + vo);
            cp16(sbase + SM_BUF(0) + SM_VLO + so, vl_g + vo);
        }
        cp_commit();
    }

    float o[8][4];
    #pragma unroll
    for (int j = 0; j < 8; j++)
        #pragma unroll
        for (int e = 0; e < 4; e++) o[j][e] = 0.0f;
    float mrow[2] = {-1e30f, -1e30f};
    float lrow[2] = {0.0f, 0.0f};

    const uint32_t qrow = w * 16 + (lane & 15);
    const uint32_t qc   = lane >> 4;
    const uint32_t qoff = qrow * 128;
    const uint32_t qxr  = qrow & 7;
    const uint32_t brow = ((lane >> 4) << 3) + (lane & 7);
    const uint32_t bc   = (lane >> 3) & 1;
    const uint32_t bxr  = brow & 7;

    for (int i = 0; i < NKV; i++) {
        if (i < NKV - 1) {
            int buf = (i + 1) & 1;
            int kb = (i + 1) * 64;
            #pragma unroll
            for (int p = 0; p < 2; p++) {
                int id = tid + p * 256;
                int r = id >> 3, c = id & 7;
                uint32_t so = SW(r, c);
                size_t ko = (size_t)(kb + r) * DK + c * 8;
                size_t vo = (size_t)r * NN + kb + c * 8;
                cp16(sbase + SM_BUF(buf) + SM_KHI + so, kh_g + ko);
                cp16(sbase + SM_BUF(buf) + SM_KLO + so, kl_g + ko);
                cp16(sbase + SM_BUF(buf) + SM_VHI + so, vh_g + vo);
                cp16(sbase + SM_BUF(buf) + SM_VLO + so, vl_g + vo);
            }
            cp_commit();
            cp_wait<1>();
        } else {
            cp_wait<0>();
        }
        __syncthreads();

        const uint32_t kbuf = sbase + SM_BUF(i & 1);

        float s[8][4];
        #pragma unroll
        for (int j = 0; j < 8; j++)
            #pragma unroll
            for (int e = 0; e < 4; e++) s[j][e] = 0.0f;

        #pragma unroll
        for (int ks = 0; ks < 4; ks++) {
            uint32_t qh[4], ql[4];
            uint32_t qcc = 2 * ks + qc;
            ldsm_x4(qh[0], qh[1], qh[2], qh[3], sbase + SM_QHI + qoff + ((qcc ^ qxr) << 4));
            ldsm_x4(ql[0], ql[1], ql[2], ql[3], sbase + SM_QLO + qoff + ((qcc ^ qxr) << 4));
            uint32_t bcc = 2 * ks + bc;
            #pragma unroll
            for (int jp = 0; jp < 4; jp++) {
                uint32_t row = 16 * jp + brow;
                uint32_t off = row * 128 + ((bcc ^ bxr) << 4);
                uint32_t kh0, kh1, kh2, kh3, kl0, kl1, kl2, kl3;
                ldsm_x4(kh0, kh1, kh2, kh3, kbuf + SM_KHI + off);
                ldsm_x4(kl0, kl1, kl2, kl3, kbuf + SM_KLO + off);
                mma16816(s[2 * jp],     qh, kh0, kh1);
                mma16816(s[2 * jp],     qh, kl0, kl1);
                mma16816(s[2 * jp],     ql, kh0, kh1);
                mma16816(s[2 * jp + 1], qh, kh2, kh3);
                mma16816(s[2 * jp + 1], qh, kl2, kl3);
                mma16816(s[2 * jp + 1], ql, kh2, kh3);
            }
        }

        // online softmax; p rounded to bf16 BEFORE accumulating denominator
        #pragma unroll
        for (int hh = 0; hh < 2; hh++) {
            float mx = -1e30f;
            #pragma unroll
            for (int j = 0; j < 8; j++)
                mx = fmaxf(mx, fmaxf(s[j][2 * hh], s[j][2 * hh + 1]));
            mx = fmaxf(mx, __shfl_xor_sync(0xffffffffu, mx, 1));
            mx = fmaxf(mx, __shfl_xor_sync(0xffffffffu, mx, 2));
            float mNew = fmaxf(mrow[hh], mx);
            float corr = exp2f(mrow[hh] - mNew);
            float rs = 0.0f;
            #pragma unroll
            for (int j = 0; j < 8; j++) {
                float p0 = rnd_bf(exp2f(s[j][2 * hh]     - mNew));
                float p1 = rnd_bf(exp2f(s[j][2 * hh + 1] - mNew));
                s[j][2 * hh]     = p0;
                s[j][2 * hh + 1] = p1;
                rs += p0 + p1;
            }
            rs += __shfl_xor_sync(0xffffffffu, rs, 1);
            rs += __shfl_xor_sync(0xffffffffu, rs, 2);
            lrow[hh] = lrow[hh] * corr + rs;
            mrow[hh] = mNew;
            #pragma unroll
            for (int j = 0; j < 8; j++) {
                o[j][2 * hh]     *= corr;
                o[j][2 * hh + 1] *= corr;
            }
        }

        // O += P @ V : P single limb (exact pack of rounded p), V hi+lo
        #pragma unroll
        for (int ks = 0; ks < 4; ks++) {
            uint32_t ph[4];
            ph[0] = packb(s[2 * ks][0],     s[2 * ks][1]);
            ph[1] = packb(s[2 * ks][2],     s[2 * ks][3]);
            ph[2] = packb(s[2 * ks + 1][0], s[2 * ks + 1][1]);
            ph[3] = packb(s[2 * ks + 1][2], s[2 * ks + 1][3]);
            uint32_t bcc = 2 * ks + bc;
            #pragma unroll
            for (int jp = 0; jp < 4; jp++) {
                uint32_t row = 16 * jp + brow;
                uint32_t off = row * 128 + ((bcc ^ bxr) << 4);
                uint32_t vh0, vh1, vh2, vh3, vl0, vl1, vl2, vl3;
                ldsm_x4(vh0, vh1, vh2, vh3, kbuf + SM_VHI + off);
                ldsm_x4(vl0, vl1, vl2, vl3, kbuf + SM_VLO + off);
                mma16816(o[2 * jp],     ph, vh0, vh1);
                mma16816(o[2 * jp],     ph, vl0, vl1);
                mma16816(o[2 * jp + 1], ph, vh2, vh3);
                mma16816(o[2 * jp + 1], ph, vl2, vl3);
            }
        }
        __syncthreads();
    }

    const int b_ = bh >> 3;
    const int h  = bh & 7;
    const int c0 = (lane & 3) * 2;
    const float i0 = 1.0f / lrow[0];
    const float i1 = 1.0f / lrow[1];
    const int ra = m0 + w * 16 + rq;
    #pragma unroll
    for (int j = 0; j < 8; j++) {
        int col = 8 * j + c0;
        uint32_t h0, l0, h1, l1;
        split2(o[j][0] * i0, o[j][1] * i0, h0, l0);
        split2(o[j][2] * i1, o[j][3] * i1, h1, l1);
        size_t off0 = ((size_t)(b_ * NN + ra)) * D_MODEL + h * DK + col;
        size_t off1 = ((size_t)(b_ * NN + ra + 8)) * D_MODEL + h * DK + col;
        *reinterpret_cast<uint32_t*>(&g_ah[off0]) = h0;
        *reinterpret_cast<uint32_t*>(&g_al[off0]) = l0;
        *reinterpret_cast<uint32_t*>(&g_ah[off1]) = h1;
        *reinterpret_cast<uint32_t*>(&g_al[off1]) = l1;
    }
}

// ---------------------------------------------------------------------------
extern "C" void kernel_launch(void* const* d_in, const int* in_sizes, int n_in,
                              void* d_out, int out_size)
{
    (void)in_sizes; (void)n_in; (void)out_size;
    const float* x  = (const float*)d_in[0];
    const float* Wq = (const float*)d_in[1];
    const float* bq = (const float*)d_in[2];
    const float* Wk = (const float*)d_in[3];
    const float* bk = (const float*)d_in[4];
    const float* Wv = (const float*)d_in[5];
    const float* bv = (const float*)d_in[6];
    const float* Wo = (const float*)d_in[7];
    const float* bo = (const float*)d_in[8];

    void *xh, *xl, *wth, *wtl, *ah, *al;
    cudaGetSymbolAddress(&xh, g_xh);
    cudaGetSymbolAddress(&xl, g_xl);
    cudaGetSymbolAddress(&wth, g_wth);
    cudaGetSymbolAddress(&wtl, g_wtl);
    cudaGetSymbolAddress(&ah, g_ah);
    cudaGetSymbolAddress(&al, g_al);

    __nv_bfloat16* whp = (__nv_bfloat16*)wth;
    __nv_bfloat16* wlp = (__nv_bfloat16*)wtl;

    cudaFuncSetAttribute(attn_tc, cudaFuncAttributeMaxDynamicSharedMemorySize, ATTN_SMEM);
    cudaFuncSetAttribute(gemm_raw, cudaFuncAttributeMaxDynamicSharedMemorySize, GEMM_SMEM);

    // single fused prep launch
    prep_all<<<NXB + 1024, 256>>>(x, Wq, Wk, Wv, Wo);

    // fused QKV projection: grid (24, 64)
    dim3 qkv_grid(24, M_TOTAL / 128);
    gemm_raw<<<qkv_grid, 256, GEMM_SMEM>>>((const __nv_bfloat16*)xh, (const __nv_bfloat16*)xl,
                                           whp, wlp, bq, bk, bv, nullptr, 1);

    dim3 attn_grid(NN / 128, BH);   // (16, 32)
    attn_tc<<<attn_grid, 256, ATTN_SMEM>>>();

    // O projection: grid (8, 64)
    dim3 o_grid(8, M_TOTAL / 128);
    gemm_raw<<<o_grid, 256, GEMM_SMEM>>>((const __nv_bfloat16*)ah, (const __nv_bfloat16*)al,
                                         whp, wlp, bo, nullptr, nullptr, (float*)d_out, 0);
}

// round 11
// speedup vs baseline: 1.6252x; 1.0958x over previous
#include <cuda_runtime.h>
#include <cuda_fp16.h>
#include <math.h>
#include <stdint.h>

#define D_MODEL 512
#define NHEAD   8
#define DK      64
#define BB      4
#define NN      2048
#define M_TOTAL (BB * NN)     // 8192
#define BH      (BB * NHEAD)  // 32
#define NKV     (NN / 64)     // 32 kv blocks
#define WSZ     (D_MODEL * D_MODEL)

// Q pre-scale: 1/sqrt(64) * log2(e)
#define SC_ATTN 0.18033688f

// ---------------- scratch (allocation-free static device arrays) -----------
__device__ __align__(128) __half g_xh[M_TOTAL * D_MODEL];
__device__ __align__(128) __half g_xl[M_TOTAL * D_MODEL];
__device__ __align__(128) __half g_wth[4 * WSZ]; // W^T [n][k], 4 mats
__device__ __align__(128) __half g_wtl[4 * WSZ];
__device__ __align__(128) __half g_qh[BH * NN * DK];
__device__ __align__(128) __half g_ql[BH * NN * DK];
__device__ __align__(128) __half g_kh[BH * NN * DK];
__device__ __align__(128) __half g_kl[BH * NN * DK];
__device__ __align__(128) __half g_vth[BH * DK * NN]; // [bh][d][n], single limb
__device__ __align__(128) __half g_ah[M_TOTAL * D_MODEL]; // attn out split
__device__ __align__(128) __half g_al[M_TOTAL * D_MODEL];

// ---------------------------------------------------------------------------
// helpers (fp16 splits)
// ---------------------------------------------------------------------------
__device__ __forceinline__ uint32_t packh(float x, float y) {
    __half2 t = __floats2half2_rn(x, y);
    return *reinterpret_cast<uint32_t*>(&t);
}
__device__ __forceinline__ void split2(float x, float y, uint32_t& hi, uint32_t& lo) {
    float hx = __half2float(__float2half_rn(x));
    float hy = __half2float(__float2half_rn(y));
    hi = packh(hx, hy);
    lo = packh(x - hx, y - hy);
}
__device__ __forceinline__ float rnd_h(float x) {
    return __half2float(__float2half_rn(x));
}
__device__ __forceinline__ void mma16816(float* c, const uint32_t* a, uint32_t b0, uint32_t b1) {
    asm volatile(
        "mma.sync.aligned.m16n8k16.row.col.f32.f16.f16.f32 "
        "{%0,%1,%2,%3}, {%4,%5,%6,%7}, {%8,%9}, {%0,%1,%2,%3};\n"
        : "+f"(c[0]), "+f"(c[1]), "+f"(c[2]), "+f"(c[3])
        : "r"(a[0]), "r"(a[1]), "r"(a[2]), "r"(a[3]), "r"(b0), "r"(b1));
}
__device__ __forceinline__ void ldsm_x4(uint32_t& d0, uint32_t& d1, uint32_t& d2, uint32_t& d3,
                                        uint32_t saddr) {
    asm volatile("ldmatrix.sync.aligned.m8n8.x4.shared.b16 {%0,%1,%2,%3}, [%4];"
                 : "=r"(d0), "=r"(d1), "=r"(d2), "=r"(d3) : "r"(saddr));
}
__device__ __forceinline__ void cp16(uint32_t dst, const void* src) {
    asm volatile("cp.async.cg.shared.global [%0], [%1], 16;" :: "r"(dst), "l"(src));
}
__device__ __forceinline__ void cp_commit() { asm volatile("cp.async.commit_group;"); }
template<int N> __device__ __forceinline__ void cp_wait() {
    asm volatile("cp.async.wait_group %0;" :: "n"(N));
}
__device__ __forceinline__ uint32_t SW(uint32_t r, uint32_t c) {
    return r * 128u + ((c ^ (r & 7u)) << 4);
}

// ---------------------------------------------------------------------------
// fused prep: x hi/lo split + 4x weight transpose/split, one launch.
// ---------------------------------------------------------------------------
#define NXB ((M_TOTAL * D_MODEL / 4) / 256)   // 4096

__global__ void __launch_bounds__(256)
prep_all(const float* __restrict__ x,
         const float* __restrict__ W0, const float* __restrict__ W1,
         const float* __restrict__ W2, const float* __restrict__ W3)
{
    const int bid = blockIdx.x;
    if (bid < NXB) {
        int i = bid * 256 + threadIdx.x;
        float4 v = reinterpret_cast<const float4*>(x)[i];
        uint32_t h01, l01, h23, l23;
        split2(v.x, v.y, h01, l01);
        split2(v.z, v.w, h23, l23);
        reinterpret_cast<uint2*>(g_xh)[i] = make_uint2(h01, h23);
        reinterpret_cast<uint2*>(g_xl)[i] = make_uint2(l01, l23);
        return;
    }
    __shared__ float ts[32][33];
    const int t   = bid - NXB;
    const int mat = t >> 8;
    const int blk = t & 255;
    const float* W = (mat == 0) ? W0 : (mat == 1) ? W1 : (mat == 2) ? W2 : W3;
    __half* th = g_wth + (size_t)mat * WSZ;
    __half* tl = g_wtl + (size_t)mat * WSZ;
    int n0 = (blk & 15) * 32, k0 = (blk >> 4) * 32;
    int tx = threadIdx.x & 31, ty = threadIdx.x >> 5;
    #pragma unroll
    for (int j = 0; j < 4; j++)
        ts[ty + j * 8][tx] = W[(size_t)(k0 + ty + j * 8) * D_MODEL + n0 + tx];
    __syncthreads();
    #pragma unroll
    for (int j = 0; j < 4; j++) {
        int n = ty + j * 8;
        float v = ts[tx][n];
        float hv = rnd_h(v);
        th[(size_t)(n0 + n) * D_MODEL + k0 + tx] = __float2half_rn(hv);
        tl[(size_t)(n0 + n) * D_MODEL + k0 + tx] = __float2half_rn(v - hv);
    }
}

// ---------------------------------------------------------------------------
// Raw-mma GEMM: out = A[M,512] @ Wt^T + bias.
// CTA tile 128x64, BK=64, 256 thr / 8 warps, 3-limb fp16 split.
// fused=1: QKV (grid.x=24): Q->mode1*SC_ATTN, K->mode1, V->mode2 (single limb).
// fused=0: O-projection (grid.x=8): fp32 out.
// ---------------------------------------------------------------------------
#define GS_AHI 0
#define GS_ALO 16384
#define GS_BHI 32768
#define GS_BLO 40960
#define GS_STAGE 49152
#define GEMM_SMEM (2 * GS_STAGE)   // 96 KB

__global__ void __launch_bounds__(256, 2)
gemm_raw(const __half* __restrict__ Ah, const __half* __restrict__ Al,
         const __half* __restrict__ Bh, const __half* __restrict__ Bl,
         const float* __restrict__ bias_q, const float* __restrict__ bias_k,
         const float* __restrict__ bias_v, float* __restrict__ outf, int fused)
{
    extern __shared__ __align__(128) unsigned char sm[];
    const uint32_t sbase = (uint32_t)__cvta_generic_to_shared(sm);

    const int tid  = threadIdx.x;
    const int lane = tid & 31;
    const int w    = tid >> 5;
    const int rq   = lane >> 2;
    const int cb   = blockIdx.x;
    const int m0   = blockIdx.y * 128;

    const int wsel  = fused ? (cb >> 3) : 3;
    const int n_in  = (cb & 7) * 64;
    const size_t brow0 = (size_t)wsel * D_MODEL + n_in;

    auto load_chunk = [&](int kc, int buf) {
        uint32_t base = sbase + buf * GS_STAGE;
        int kb = kc * 64;
        #pragma unroll
        for (int t = 0; t < 4; t++) {
            int id = tid + t * 256;
            int r = id >> 3, c = id & 7;
            uint32_t so = SW(r, c);
            size_t g = (size_t)(m0 + r) * D_MODEL + kb + c * 8;
            cp16(base + GS_AHI + so, Ah + g);
            cp16(base + GS_ALO + so, Al + g);
        }
        #pragma unroll
        for (int t = 0; t < 2; t++) {
            int id = tid + t * 256;
            int r = id >> 3, c = id & 7;
            uint32_t so = SW(r, c);
            size_t g = (brow0 + r) * D_MODEL + kb + c * 8;
            cp16(base + GS_BHI + so, Bh + g);
            cp16(base + GS_BLO + so, Bl + g);
        }
        cp_commit();
    };

    float s[8][4];
    #pragma unroll
    for (int j = 0; j < 8; j++)
        #pragma unroll
        for (int e = 0; e < 4; e++) s[j][e] = 0.0f;

    const uint32_t qrow = w * 16 + (lane & 15);
    const uint32_t qc   = lane >> 4;
    const uint32_t qoff = qrow * 128;
    const uint32_t qxr  = qrow & 7;
    const uint32_t brow = ((lane >> 4) << 3) + (lane & 7);
    const uint32_t bc   = (lane >> 3) & 1;
    const uint32_t bxr  = brow & 7;

    load_chunk(0, 0);
    load_chunk(1, 1);

    for (int i = 0; i < 8; i++) {
        if (i == 7) cp_wait<0>(); else cp_wait<1>();
        __syncthreads();
        const uint32_t abuf = sbase + (i & 1) * GS_STAGE;

        #pragma unroll
        for (int ks = 0; ks < 4; ks++) {
            uint32_t ah[4], al[4];
            uint32_t qcc = 2 * ks + qc;
            ldsm_x4(ah[0], ah[1], ah[2], ah[3], abuf + GS_AHI + qoff + ((qcc ^ qxr) << 4));
            ldsm_x4(al[0], al[1], al[2], al[3], abuf + GS_ALO + qoff + ((qcc ^ qxr) << 4));
            uint32_t bcc = 2 * ks + bc;
            #pragma unroll
            for (int jp = 0; jp < 4; jp++) {
                uint32_t row = 16 * jp + brow;
                uint32_t off = row * 128 + ((bcc ^ bxr) << 4);
                uint32_t bh0, bh1, bh2, bh3, bl0, bl1, bl2, bl3;
                ldsm_x4(bh0, bh1, bh2, bh3, abuf + GS_BHI + off);
                ldsm_x4(bl0, bl1, bl2, bl3, abuf + GS_BLO + off);
                mma16816(s[2 * jp],     ah, bh0, bh1);
                mma16816(s[2 * jp],     ah, bl0, bl1);
                mma16816(s[2 * jp],     al, bh0, bh1);
                mma16816(s[2 * jp + 1], ah, bh2, bh3);
                mma16816(s[2 * jp + 1], ah, bl2, bl3);
                mma16816(s[2 * jp + 1], al, bh2, bh3);
            }
        }
        __syncthreads();
        if (i + 2 < 8) load_chunk(i + 2, i & 1);
    }

    float* Cst = (float*)sm;
    {
        const int c0 = (lane & 3) * 2;
        const int ra = w * 16 + rq;
        #pragma unroll
        for (int j = 0; j < 8; j++) {
            int col = 8 * j + c0;
            Cst[ra * 68 + col]           = s[j][0];
            Cst[ra * 68 + col + 1]       = s[j][1];
            Cst[(ra + 8) * 68 + col]     = s[j][2];
            Cst[(ra + 8) * 68 + col + 1] = s[j][3];
        }
    }
    __syncthreads();

    if (!fused) {
        const int orow = tid >> 4;
        const int ocol = (tid & 15) * 4;
        float4 b4 = *reinterpret_cast<const float4*>(&bias_q[n_in + ocol]);
        #pragma unroll
        for (int t = 0; t < 8; t++) {
            int r = orow + t * 16;
            float4 v = *reinterpret_cast<const float4*>(&Cst[r * 68 + ocol]);
            v.x += b4.x; v.y += b4.y; v.z += b4.z; v.w += b4.w;
            *reinterpret_cast<float4*>(&outf[(size_t)(m0 + r) * D_MODEL + n_in + ocol]) = v;
        }
    } else if (wsel < 2) {
        const float scale = (wsel == 0) ? SC_ATTN : 1.0f;
        __half* ohi = (wsel == 0) ? g_qh : g_kh;
        __half* olo = (wsel == 0) ? g_ql : g_kl;
        const float* bias = (wsel == 0) ? bias_q : bias_k;
        const int h = cb & 7;
        const int orow = tid >> 4;
        const int ocol = (tid & 15) * 4;
        float4 b4 = *reinterpret_cast<const float4*>(&bias[n_in + ocol]);
        #pragma unroll
        for (int t = 0; t < 8; t++) {
            int r  = orow + t * 16;
            int rg = m0 + r;
            int b_ = rg >> 11;
            int n_ = rg & 2047;
            float4 v = *reinterpret_cast<const float4*>(&Cst[r * 68 + ocol]);
            float v0 = (v.x + b4.x) * scale;
            float v1 = (v.y + b4.y) * scale;
            float v2 = (v.z + b4.z) * scale;
            float v3 = (v.w + b4.w) * scale;
            uint32_t h01, l01, h23, l23;
            split2(v0, v1, h01, l01);
            split2(v2, v3, h23, l23);
            size_t off = ((size_t)(b_ * NHEAD + h) * NN + n_) * DK + ocol;
            *reinterpret_cast<uint2*>(&ohi[off]) = make_uint2(h01, h23);
            *reinterpret_cast<uint2*>(&olo[off]) = make_uint2(l01, l23);
        }
    } else {
        // V transposed, SINGLE fp16 limb [bh][d][n]
        const int h   = cb & 7;
        const int od  = tid >> 2;
        const int on0 = (tid & 3) * 32;
        const int b_  = m0 >> 11;
        const int nb  = (m0 & 2047) + on0;
        const float bv = bias_v[n_in + od];
        size_t rowoff = ((size_t)(b_ * NHEAD + h) * DK + od) * NN + nb;
        #pragma unroll
        for (int i = 0; i < 32; i += 2) {
            float v0 = Cst[(on0 + i) * 68 + od] + bv;
            float v1 = Cst[(on0 + i + 1) * 68 + od] + bv;
            *reinterpret_cast<uint32_t*>(&g_vth[rowoff + i]) = packh(v0, v1);
        }
    }
}

// ---------------------------------------------------------------------------
// Flash attention: BM=128, BN=64, d=64, 256 thr, 2 CTAs/SM.
// S: 3-limb fp16. PV: 1-limb P x 1-limb V (fp16), denominator from rounded p.
// ---------------------------------------------------------------------------
#define SM_QHI 0
#define SM_QLO 16384
#define SM_BUF(b) (32768 + (b) * 24576)
#define SM_KHI 0
#define SM_KLO 8192
#define SM_VHI 16384
#define ATTN_SMEM (32768 + 2 * 24576)   // 80 KB

__global__ void __launch_bounds__(256, 2)
attn_tc()
{
    extern __shared__ __align__(128) unsigned char sm[];
    const uint32_t sbase = (uint32_t)__cvta_generic_to_shared(sm);

    const int tid  = threadIdx.x;
    const int lane = tid & 31;
    const int w    = tid >> 5;
    const int rq   = lane >> 2;
    const int bh   = blockIdx.y;
    const int m0   = blockIdx.x * 128;

    const __half* qh_g = g_qh + (size_t)bh * NN * DK;
    const __half* ql_g = g_ql + (size_t)bh * NN * DK;
    const __half* kh_g = g_kh + (size_t)bh * NN * DK;
    const __half* kl_g = g_kl + (size_t)bh * NN * DK;
    const __half* vh_g = g_vth + (size_t)bh * DK * NN;

    {
        #pragma unroll
        for (int p = 0; p < 4; p++) {
            int id = tid + p * 256;
            int r = id >> 3, c = id & 7;
            size_t go = (size_t)(m0 + r) * DK + c * 8;
            uint32_t so = SW(r, c);
            cp16(sbase + SM_QHI + so, qh_g + go);
            cp16(sbase + SM_QLO + so, ql_g + go);
        }
        cp_commit();
    }
    {
        #pragma unroll
        for (int p = 0; p < 2; p++) {
            int id = tid + p * 256;
            int r = id >> 3, c = id & 7;
            uint32_t so = SW(r, c);
            size_t ko = (size_t)r * DK + c * 8;
            size_t vo = (size_t)r * NN + c * 8;
            cp16(sbase + SM_BUF(0) + SM_KHI + so, kh_g + ko);
            cp16(sbase + SM_BUF(0) + SM_KLO + so, kl_g + ko);
            cp16(sbase + SM_BUF(0) + SM_VHI + so, vh_g + vo);
        }
        cp_commit();
    }

    float o[8][4];
    #pragma unroll
    for (int j = 0; j < 8; j++)
        #pragma unroll
        for (int e = 0; e < 4; e++) o[j][e] = 0.0f;
    float mrow[2] = {-1e30f, -1e30f};
    float lrow[2] = {0.0f, 0.0f};

    const uint32_t qrow = w * 16 + (lane & 15);
    const uint32_t qc   = lane >> 4;
    const uint32_t qoff = qrow * 128;
    const uint32_t qxr  = qrow & 7;
    const uint32_t brow = ((lane >> 4) << 3) + (lane & 7);
    const uint32_t bc   = (lane >> 3) & 1;
    const uint32_t bxr  = brow & 7;

    for (int i = 0; i < NKV; i++) {
        if (i < NKV - 1) {
            int buf = (i + 1) & 1;
            int kb = (i + 1) * 64;
            #pragma unroll
            for (int p = 0; p < 2; p++) {
                int id = tid + p * 256;
                int r = id >> 3, c = id & 7;
                uint32_t so = SW(r, c);
                size_t ko = (size_t)(kb + r) * DK + c * 8;
                size_t vo = (size_t)r * NN + kb + c * 8;
                cp16(sbase + SM_BUF(buf) + SM_KHI + so, kh_g + ko);
                cp16(sbase + SM_BUF(buf) + SM_KLO + so, kl_g + ko);
                cp16(sbase + SM_BUF(buf) + SM_VHI + so, vh_g + vo);
            }
            cp_commit();
            cp_wait<1>();
        } else {
            cp_wait<0>();
        }
        __syncthreads();

        const uint32_t kbuf = sbase + SM_BUF(i & 1);

        float s[8][4];
        #pragma unroll
        for (int j = 0; j < 8; j++)
            #pragma unroll
            for (int e = 0; e < 4; e++) s[j][e] = 0.0f;

        #pragma unroll
        for (int ks = 0; ks < 4; ks++) {
            uint32_t qh[4], ql[4];
            uint32_t qcc = 2 * ks + qc;
            ldsm_x4(qh[0], qh[1], qh[2], qh[3], sbase + SM_QHI + qoff + ((qcc ^ qxr) << 4));
            ldsm_x4(ql[0], ql[1], ql[2], ql[3], sbase + SM_QLO + qoff + ((qcc ^ qxr) << 4));
            uint32_t bcc = 2 * ks + bc;
            #pragma unroll
            for (int jp = 0; jp < 4; jp++) {
                uint32_t row = 16 * jp + brow;
                uint32_t off = row * 128 + ((bcc ^ bxr) << 4);
                uint32_t kh0, kh1, kh2, kh3, kl0, kl1, kl2, kl3;
                ldsm_x4(kh0, kh1, kh2, kh3, kbuf + SM_KHI + off);
                ldsm_x4(kl0, kl1, kl2, kl3, kbuf + SM_KLO + off);
                mma16816(s[2 * jp],     qh, kh0, kh1);
                mma16816(s[2 * jp],     qh, kl0, kl1);
                mma16816(s[2 * jp],     ql, kh0, kh1);
                mma16816(s[2 * jp + 1], qh, kh2, kh3);
                mma16816(s[2 * jp + 1], qh, kl2, kl3);
                mma16816(s[2 * jp + 1], ql, kh2, kh3);
            }
        }

        // online softmax; p rounded to fp16 BEFORE accumulating denominator
        #pragma unroll
        for (int hh = 0; hh < 2; hh++) {
            float mx = -1e30f;
            #pragma unroll
            for (int j = 0; j < 8; j++)
                mx = fmaxf(mx, fmaxf(s[j][2 * hh], s[j][2 * hh + 1]));
            mx = fmaxf(mx, __shfl_xor_sync(0xffffffffu, mx, 1));
            mx = fmaxf(mx, __shfl_xor_sync(0xffffffffu, mx, 2));
            float mNew = fmaxf(mrow[hh], mx);
            float corr = exp2f(mrow[hh] - mNew);
            float rs = 0.0f;
            #pragma unroll
            for (int j = 0; j < 8; j++) {
                float p0 = rnd_h(exp2f(s[j][2 * hh]     - mNew));
                float p1 = rnd_h(exp2f(s[j][2 * hh + 1] - mNew));
                s[j][2 * hh]     = p0;
                s[j][2 * hh + 1] = p1;
                rs += p0 + p1;
            }
            rs += __shfl_xor_sync(0xffffffffu, rs, 1);
            rs += __shfl_xor_sync(0xffffffffu, rs, 2);
            lrow[hh] = lrow[hh] * corr + rs;
            mrow[hh] = mNew;
            #pragma unroll
            for (int j = 0; j < 8; j++) {
                o[j][2 * hh]     *= corr;
                o[j][2 * hh + 1] *= corr;
            }
        }

        // O += P @ V : single-limb P (exact pack of rounded p) x single-limb V
        #pragma unroll
        for (int ks = 0; ks < 4; ks++) {
            uint32_t ph[4];
            ph[0] = packh(s[2 * ks][0],     s[2 * ks][1]);
            ph[1] = packh(s[2 * ks][2],     s[2 * ks][3]);
            ph[2] = packh(s[2 * ks + 1][0], s[2 * ks + 1][1]);
            ph[3] = packh(s[2 * ks + 1][2], s[2 * ks + 1][3]);
            uint32_t bcc = 2 * ks + bc;
            #pragma unroll
            for (int jp = 0; jp < 4; jp++) {
                uint32_t row = 16 * jp + brow;
                uint32_t off = row * 128 + ((bcc ^ bxr) << 4);
                uint32_t vh0, vh1, vh2, vh3;
                ldsm_x4(vh0, vh1, vh2, vh3, kbuf + SM_VHI + off);
                mma16816(o[2 * jp],     ph, vh0, vh1);
                mma16816(o[2 * jp + 1], ph, vh2, vh3);
            }
        }
        __syncthreads();
    }

    const int b_ = bh >> 3;
    const int h  = bh & 7;
    const int c0 = (lane & 3) * 2;
    const float i0 = 1.0f / lrow[0];
    const float i1 = 1.0f / lrow[1];
    const int ra = m0 + w * 16 + rq;
    #pragma unroll
    for (int j = 0; j < 8; j++) {
        int col = 8 * j + c0;
        uint32_t h0, l0, h1, l1;
        split2(o[j][0] * i0, o[j][1] * i0, h0, l0);
        split2(o[j][2] * i1, o[j][3] * i1, h1, l1);
        size_t off0 = ((size_t)(b_ * NN + ra)) * D_MODEL + h * DK + col;
        size_t off1 = ((size_t)(b_ * NN + ra + 8)) * D_MODEL + h * DK + col;
        *reinterpret_cast<uint32_t*>(&g_ah[off0]) = h0;
        *reinterpret_cast<uint32_t*>(&g_al[off0]) = l0;
        *reinterpret_cast<uint32_t*>(&g_ah[off1]) = h1;
        *reinterpret_cast<uint32_t*>(&g_al[off1]) = l1;
    }
}

// ---------------------------------------------------------------------------
extern "C" void kernel_launch(void* const* d_in, const int* in_sizes, int n_in,
                              void* d_out, int out_size)
{
    (void)in_sizes; (void)n_in; (void)out_size;
    const float* x  = (const float*)d_in[0];
    const float* Wq = (const float*)d_in[1];
    const float* bq = (const float*)d_in[2];
    const float* Wk = (const float*)d_in[3];
    const float* bk = (const float*)d_in[4];
    const float* Wv = (const float*)d_in[5];
    const float* bv = (const float*)d_in[6];
    const float* Wo = (const float*)d_in[7];
    const float* bo = (const float*)d_in[8];

    void *xh, *xl, *wth, *wtl, *ah, *al;
    cudaGetSymbolAddress(&xh, g_xh);
    cudaGetSymbolAddress(&xl, g_xl);
    cudaGetSymbolAddress(&wth, g_wth);
    cudaGetSymbolAddress(&wtl, g_wtl);
    cudaGetSymbolAddress(&ah, g_ah);
    cudaGetSymbolAddress(&al, g_al);

    __half* whp = (__half*)wth;
    __half* wlp = (__half*)wtl;

    cudaFuncSetAttribute(attn_tc, cudaFuncAttributeMaxDynamicSharedMemorySize, ATTN_SMEM);
    cudaFuncSetAttribute(gemm_raw, cudaFuncAttributeMaxDynamicSharedMemorySize, GEMM_SMEM);

    // single fused prep launch
    prep_all<<<NXB + 1024, 256>>>(x, Wq, Wk, Wv, Wo);

    // fused QKV projection: grid (24, 64)
    dim3 qkv_grid(24, M_TOTAL / 128);
    gemm_raw<<<qkv_grid, 256, GEMM_SMEM>>>((const __half*)xh, (const __half*)xl,
                                           whp, wlp, bq, bk, bv, nullptr, 1);

    dim3 attn_grid(NN / 128, BH);   // (16, 32)
    attn_tc<<<attn_grid, 256, ATTN_SMEM>>>();

    // O projection: grid (8, 64)
    dim3 o_grid(8, M_TOTAL / 128);
    gemm_raw<<<o_grid, 256, GEMM_SMEM>>>((const __half*)ah, (const __half*)al,
                                         whp, wlp, bo, nullptr, nullptr, (float*)d_out, 0);
}

// round 13
// speedup vs baseline: 1.8341x; 1.1285x over previous
#include <cuda_runtime.h>
#include <cuda_fp16.h>
#include <math.h>
#include <stdint.h>

#define D_MODEL 512
#define NHEAD   8
#define DK      64
#define BB      4
#define NN      2048
#define M_TOTAL (BB * NN)     // 8192
#define BH      (BB * NHEAD)  // 32
#define NKV     (NN / 64)     // 32 kv blocks
#define WSZ     (D_MODEL * D_MODEL)

// Q pre-scale: 1/sqrt(64) * log2(e)
#define SC_ATTN 0.18033688f

// ---------------- scratch (allocation-free static device arrays) -----------
__device__ __align__(128) __half g_xh[M_TOTAL * D_MODEL];
__device__ __align__(128) __half g_xl[M_TOTAL * D_MODEL];
__device__ __align__(128) __half g_wth[4 * WSZ]; // W^T [n][k], single fp16 limb
__device__ __align__(128) __half g_qh[BH * NN * DK];
__device__ __align__(128) __half g_ql[BH * NN * DK];
__device__ __align__(128) __half g_kh[BH * NN * DK];
__device__ __align__(128) __half g_kl[BH * NN * DK];
__device__ __align__(128) __half g_vth[BH * DK * NN]; // [bh][d][n], single limb
__device__ __align__(128) __half g_ah[M_TOTAL * D_MODEL]; // attn out split
__device__ __align__(128) __half g_al[M_TOTAL * D_MODEL];

// ---------------------------------------------------------------------------
// helpers (fp16 splits)
// ---------------------------------------------------------------------------
__device__ __forceinline__ uint32_t packh(float x, float y) {
    __half2 t = __floats2half2_rn(x, y);
    return *reinterpret_cast<uint32_t*>(&t);
}
__device__ __forceinline__ void split2(float x, float y, uint32_t& hi, uint32_t& lo) {
    float hx = __half2float(__float2half_rn(x));
    float hy = __half2float(__float2half_rn(y));
    hi = packh(hx, hy);
    lo = packh(x - hx, y - hy);
}
__device__ __forceinline__ float rnd_h(float x) {
    return __half2float(__float2half_rn(x));
}
__device__ __forceinline__ void mma16816(float* c, const uint32_t* a, uint32_t b0, uint32_t b1) {
    asm volatile(
        "mma.sync.aligned.m16n8k16.row.col.f32.f16.f16.f32 "
        "{%0,%1,%2,%3}, {%4,%5,%6,%7}, {%8,%9}, {%0,%1,%2,%3};\n"
        : "+f"(c[0]), "+f"(c[1]), "+f"(c[2]), "+f"(c[3])
        : "r"(a[0]), "r"(a[1]), "r"(a[2]), "r"(a[3]), "r"(b0), "r"(b1));
}
__device__ __forceinline__ void ldsm_x4(uint32_t& d0, uint32_t& d1, uint32_t& d2, uint32_t& d3,
                                        uint32_t saddr) {
    asm volatile("ldmatrix.sync.aligned.m8n8.x4.shared.b16 {%0,%1,%2,%3}, [%4];"
                 : "=r"(d0), "=r"(d1), "=r"(d2), "=r"(d3) : "r"(saddr));
}
__device__ __forceinline__ void cp16(uint32_t dst, const void* src) {
    asm volatile("cp.async.cg.shared.global [%0], [%1], 16;" :: "r"(dst), "l"(src));
}
__device__ __forceinline__ void cp_commit() { asm volatile("cp.async.commit_group;"); }
template<int N> __device__ __forceinline__ void cp_wait() {
    asm volatile("cp.async.wait_group %0;" :: "n"(N));
}
__device__ __forceinline__ uint32_t SW(uint32_t r, uint32_t c) {
    return r * 128u + ((c ^ (r & 7u)) << 4);
}

// ---------------------------------------------------------------------------
// fused prep: x hi/lo split + 4x weight transpose (single fp16 limb), one launch.
// ---------------------------------------------------------------------------
#define NXB ((M_TOTAL * D_MODEL / 4) / 256)   // 4096

__global__ void __launch_bounds__(256)
prep_all(const float* __restrict__ x,
         const float* __restrict__ W0, const float* __restrict__ W1,
         const float* __restrict__ W2, const float* __restrict__ W3)
{
    const int bid = blockIdx.x;
    if (bid < NXB) {
        int i = bid * 256 + threadIdx.x;
        float4 v = reinterpret_cast<const float4*>(x)[i];
        uint32_t h01, l01, h23, l23;
        split2(v.x, v.y, h01, l01);
        split2(v.z, v.w, h23, l23);
        reinterpret_cast<uint2*>(g_xh)[i] = make_uint2(h01, h23);
        reinterpret_cast<uint2*>(g_xl)[i] = make_uint2(l01, l23);
        return;
    }
    __shared__ float ts[32][33];
    const int t   = bid - NXB;
    const int mat = t >> 8;
    const int blk = t & 255;
    const float* W = (mat == 0) ? W0 : (mat == 1) ? W1 : (mat == 2) ? W2 : W3;
    __half* th = g_wth + (size_t)mat * WSZ;
    int n0 = (blk & 15) * 32, k0 = (blk >> 4) * 32;
    int tx = threadIdx.x & 31, ty = threadIdx.x >> 5;
    #pragma unroll
    for (int j = 0; j < 4; j++)
        ts[ty + j * 8][tx] = W[(size_t)(k0 + ty + j * 8) * D_MODEL + n0 + tx];
    __syncthreads();
    #pragma unroll
    for (int j = 0; j < 4; j++) {
        int n = ty + j * 8;
        th[(size_t)(n0 + n) * D_MODEL + k0 + tx] = __float2half_rn(ts[tx][n]);
    }
}

// ---------------------------------------------------------------------------
// Raw-mma GEMM: out = A[M,512] @ Wt^T + bias.
// A 2-limb fp16 (hi+lo), W single fp16 limb -> 2 MMAs per fragment pair.
// CTA tile 128x64, BK=64, 256 thr / 8 warps, cp.async double-buffered.
// fused=1: QKV (grid.x=24): Q->mode1*SC_ATTN, K->mode1, V->mode2 (single limb).
// fused=0: O-projection (grid.x=8): fp32 out, bias = bias_o.
// ---------------------------------------------------------------------------
#define GS_AHI 0
#define GS_ALO 16384
#define GS_BHI 32768
#define GS_STAGE 40960
#define GEMM_SMEM (2 * GS_STAGE)   // 80 KB

__global__ void __launch_bounds__(256, 2)
gemm_raw(const __half* __restrict__ Ah, const __half* __restrict__ Al,
         const __half* __restrict__ Bh,
         const float* __restrict__ bias_q, const float* __restrict__ bias_k,
         const float* __restrict__ bias_v, const float* __restrict__ bias_o,
         float* __restrict__ outf, int fused)
{
    extern __shared__ __align__(128) unsigned char sm[];
    const uint32_t sbase = (uint32_t)__cvta_generic_to_shared(sm);

    const int tid  = threadIdx.x;
    const int lane = tid & 31;
    const int w    = tid >> 5;
    const int rq   = lane >> 2;
    const int cb   = blockIdx.x;
    const int m0   = blockIdx.y * 128;

    const int wsel  = fused ? (cb >> 3) : 3;
    const int n_in  = (cb & 7) * 64;
    const size_t brow0 = (size_t)wsel * D_MODEL + n_in;

    auto load_chunk = [&](int kc, int buf) {
        uint32_t base = sbase + buf * GS_STAGE;
        int kb = kc * 64;
        #pragma unroll
        for (int t = 0; t < 4; t++) {
            int id = tid + t * 256;
            int r = id >> 3, c = id & 7;
            uint32_t so = SW(r, c);
            size_t g = (size_t)(m0 + r) * D_MODEL + kb + c * 8;
            cp16(base + GS_AHI + so, Ah + g);
            cp16(base + GS_ALO + so, Al + g);
        }
        #pragma unroll
        for (int t = 0; t < 2; t++) {
            int id = tid + t * 256;
            int r = id >> 3, c = id & 7;
            uint32_t so = SW(r, c);
            size_t g = (brow0 + r) * D_MODEL + kb + c * 8;
            cp16(base + GS_BHI + so, Bh + g);
        }
        cp_commit();
    };

    float s[8][4];
    #pragma unroll
    for (int j = 0; j < 8; j++)
        #pragma unroll
        for (int e = 0; e < 4; e++) s[j][e] = 0.0f;

    const uint32_t qrow = w * 16 + (lane & 15);
    const uint32_t qc   = lane >> 4;
    const uint32_t qoff = qrow * 128;
    const uint32_t qxr  = qrow & 7;
    const uint32_t brow = ((lane >> 4) << 3) + (lane & 7);
    const uint32_t bc   = (lane >> 3) & 1;
    const uint32_t bxr  = brow & 7;

    load_chunk(0, 0);
    load_chunk(1, 1);

    for (int i = 0; i < 8; i++) {
        if (i == 7) cp_wait<0>(); else cp_wait<1>();
        __syncthreads();
        const uint32_t abuf = sbase + (i & 1) * GS_STAGE;

        #pragma unroll
        for (int ks = 0; ks < 4; ks++) {
            uint32_t ah[4], al[4];
            uint32_t qcc = 2 * ks + qc;
            ldsm_x4(ah[0], ah[1], ah[2], ah[3], abuf + GS_AHI + qoff + ((qcc ^ qxr) << 4));
            ldsm_x4(al[0], al[1], al[2], al[3], abuf + GS_ALO + qoff + ((qcc ^ qxr) << 4));
            uint32_t bcc = 2 * ks + bc;
            #pragma unroll
            for (int jp = 0; jp < 4; jp++) {
                uint32_t row = 16 * jp + brow;
                uint32_t off = row * 128 + ((bcc ^ bxr) << 4);
                uint32_t bh0, bh1, bh2, bh3;
                ldsm_x4(bh0, bh1, bh2, bh3, abuf + GS_BHI + off);
                mma16816(s[2 * jp],     ah, bh0, bh1);
                mma16816(s[2 * jp],     al, bh0, bh1);
                mma16816(s[2 * jp + 1], ah, bh2, bh3);
                mma16816(s[2 * jp + 1], al, bh2, bh3);
            }
        }
        __syncthreads();
        if (i + 2 < 8) load_chunk(i + 2, i & 1);
    }

    float* Cst = (float*)sm;
    {
        const int c0 = (lane & 3) * 2;
        const int ra = w * 16 + rq;
        #pragma unroll
        for (int j = 0; j < 8; j++) {
            int col = 8 * j + c0;
            Cst[ra * 68 + col]           = s[j][0];
            Cst[ra * 68 + col + 1]       = s[j][1];
            Cst[(ra + 8) * 68 + col]     = s[j][2];
            Cst[(ra + 8) * 68 + col + 1] = s[j][3];
        }
    }
    __syncthreads();

    if (!fused) {
        const int orow = tid >> 4;
        const int ocol = (tid & 15) * 4;
        float4 b4 = *reinterpret_cast<const float4*>(&bias_o[n_in + ocol]);
        #pragma unroll
        for (int t = 0; t < 8; t++) {
            int r = orow + t * 16;
            float4 v = *reinterpret_cast<const float4*>(&Cst[r * 68 + ocol]);
            v.x += b4.x; v.y += b4.y; v.z += b4.z; v.w += b4.w;
            *reinterpret_cast<float4*>(&outf[(size_t)(m0 + r) * D_MODEL + n_in + ocol]) = v;
        }
    } else if (wsel < 2) {
        const float scale = (wsel == 0) ? SC_ATTN : 1.0f;
        __half* ohi = (wsel == 0) ? g_qh : g_kh;
        __half* olo = (wsel == 0) ? g_ql : g_kl;
        const float* bias = (wsel == 0) ? bias_q : bias_k;
        const int h = cb & 7;
        const int orow = tid >> 4;
        const int ocol = (tid & 15) * 4;
        float4 b4 = *reinterpret_cast<const float4*>(&bias[n_in + ocol]);
        #pragma unroll
        for (int t = 0; t < 8; t++) {
            int r  = orow + t * 16;
            int rg = m0 + r;
            int b_ = rg >> 11;
            int n_ = rg & 2047;
            float4 v = *reinterpret_cast<const float4*>(&Cst[r * 68 + ocol]);
            float v0 = (v.x + b4.x) * scale;
            float v1 = (v.y + b4.y) * scale;
            float v2 = (v.z + b4.z) * scale;
            float v3 = (v.w + b4.w) * scale;
            uint32_t h01, l01, h23, l23;
            split2(v0, v1, h01, l01);
            split2(v2, v3, h23, l23);
            size_t off = ((size_t)(b_ * NHEAD + h) * NN + n_) * DK + ocol;
            *reinterpret_cast<uint2*>(&ohi[off]) = make_uint2(h01, h23);
            *reinterpret_cast<uint2*>(&olo[off]) = make_uint2(l01, l23);
        }
    } else {
        // V transposed, SINGLE fp16 limb [bh][d][n]
        const int h   = cb & 7;
        const int od  = tid >> 2;
        const int on0 = (tid & 3) * 32;
        const int b_  = m0 >> 11;
        const int nb  = (m0 & 2047) + on0;
        const float bv = bias_v[n_in + od];
        size_t rowoff = ((size_t)(b_ * NHEAD + h) * DK + od) * NN + nb;
        #pragma unroll
        for (int i = 0; i < 32; i += 2) {
            float v0 = Cst[(on0 + i) * 68 + od] + bv;
            float v1 = Cst[(on0 + i + 1) * 68 + od] + bv;
            *reinterpret_cast<uint32_t*>(&g_vth[rowoff + i]) = packh(v0, v1);
        }
    }
}

// ---------------------------------------------------------------------------
// Flash attention: BM=128, BN=64, d=64, 256 thr, 2 CTAs/SM.
// S: 3-limb fp16. PV: 1-limb P x 1-limb V, denominator from rounded p.
// ---------------------------------------------------------------------------
#define SM_QHI 0
#define SM_QLO 16384
#define SM_BUF(b) (32768 + (b) * 24576)
#define SM_KHI 0
#define SM_KLO 8192
#define SM_VHI 16384
#define ATTN_SMEM (32768 + 2 * 24576)   // 80 KB

__global__ void __launch_bounds__(256, 2)
attn_tc()
{
    extern __shared__ __align__(128) unsigned char sm[];
    const uint32_t sbase = (uint32_t)__cvta_generic_to_shared(sm);

    const int tid  = threadIdx.x;
    const int lane = tid & 31;
    const int w    = tid >> 5;
    const int rq   = lane >> 2;
    const int bh   = blockIdx.y;
    const int m0   = blockIdx.x * 128;

    const __half* qh_g = g_qh + (size_t)bh * NN * DK;
    const __half* ql_g = g_ql + (size_t)bh * NN * DK;
    const __half* kh_g = g_kh + (size_t)bh * NN * DK;
    const __half* kl_g = g_kl + (size_t)bh * NN * DK;
    const __half* vh_g = g_vth + (size_t)bh * DK * NN;

    {
        #pragma unroll
        for (int p = 0; p < 4; p++) {
            int id = tid + p * 256;
            int r = id >> 3, c = id & 7;
            size_t go = (size_t)(m0 + r) * DK + c * 8;
            uint32_t so = SW(r, c);
            cp16(sbase + SM_QHI + so, qh_g + go);
            cp16(sbase + SM_QLO + so, ql_g + go);
        }
        cp_commit();
    }
    {
        #pragma unroll
        for (int p = 0; p < 2; p++) {
            int id = tid + p * 256;
            int r = id >> 3, c = id & 7;
            uint32_t so = SW(r, c);
            size_t ko = (size_t)r * DK + c * 8;
            size_t vo = (size_t)r * NN + c * 8;
            cp16(sbase + SM_BUF(0) + SM_KHI + so, kh_g + ko);
            cp16(sbase + SM_BUF(0) + SM_KLO + so, kl_g + ko);
            cp16(sbase + SM_BUF(0) + SM_VHI + so, vh_g + vo);
        }
        cp_commit();
    }

    float o[8][4];
    #pragma unroll
    for (int j = 0; j < 8; j++)
        #pragma unroll
        for (int e = 0; e < 4; e++) o[j][e] = 0.0f;
    float mrow[2] = {-1e30f, -1e30f};
    float lrow[2] = {0.0f, 0.0f};

    const uint32_t qrow = w * 16 + (lane & 15);
    const uint32_t qc   = lane >> 4;
    const uint32_t qoff = qrow * 128;
    const uint32_t qxr  = qrow & 7;
    const uint32_t brow = ((lane >> 4) << 3) + (lane & 7);
    const uint32_t bc   = (lane >> 3) & 1;
    const uint32_t bxr  = brow & 7;

    for (int i = 0; i < NKV; i++) {
        if (i < NKV - 1) {
            int buf = (i + 1) & 1;
            int kb = (i + 1) * 64;
            #pragma unroll
            for (int p = 0; p < 2; p++) {
                int id = tid + p * 256;
                int r = id >> 3, c = id & 7;
                uint32_t so = SW(r, c);
                size_t ko = (size_t)(kb + r) * DK + c * 8;
                size_t vo = (size_t)r * NN + kb + c * 8;
                cp16(sbase + SM_BUF(buf) + SM_KHI + so, kh_g + ko);
                cp16(sbase + SM_BUF(buf) + SM_KLO + so, kl_g + ko);
                cp16(sbase + SM_BUF(buf) + SM_VHI + so, vh_g + vo);
            }
            cp_commit();
            cp_wait<1>();
        } else {
            cp_wait<0>();
        }
        __syncthreads();

        const uint32_t kbuf = sbase + SM_BUF(i & 1);

        float s[8][4];
        #pragma unroll
        for (int j = 0; j < 8; j++)
            #pragma unroll
            for (int e = 0; e < 4; e++) s[j][e] = 0.0f;

        #pragma unroll
        for (int ks = 0; ks < 4; ks++) {
            uint32_t qh[4], ql[4];
            uint32_t qcc = 2 * ks + qc;
            ldsm_x4(qh[0], qh[1], qh[2], qh[3], sbase + SM_QHI + qoff + ((qcc ^ qxr) << 4));
            ldsm_x4(ql[0], ql[1], ql[2], ql[3], sbase + SM_QLO + qoff + ((qcc ^ qxr) << 4));
            uint32_t bcc = 2 * ks + bc;
            #pragma unroll
            for (int jp = 0; jp < 4; jp++) {
                uint32_t row = 16 * jp + brow;
                uint32_t off = row * 128 + ((bcc ^ bxr) << 4);
                uint32_t kh0, kh1, kh2, kh3, kl0, kl1, kl2, kl3;
                ldsm_x4(kh0, kh1, kh2, kh3, kbuf + SM_KHI + off);
                ldsm_x4(kl0, kl1, kl2, kl3, kbuf + SM_KLO + off);
                mma16816(s[2 * jp],     qh, kh0, kh1);
                mma16816(s[2 * jp],     qh, kl0, kl1);
                mma16816(s[2 * jp],     ql, kh0, kh1);
                mma16816(s[2 * jp + 1], qh, kh2, kh3);
                mma16816(s[2 * jp + 1], qh, kl2, kl3);
                mma16816(s[2 * jp + 1], ql, kh2, kh3);
            }
        }

        // online softmax; p rounded to fp16 BEFORE accumulating denominator
        #pragma unroll
        for (int hh = 0; hh < 2; hh++) {
            float mx = -1e30f;
            #pragma unroll
            for (int j = 0; j < 8; j++)
                mx = fmaxf(mx, fmaxf(s[j][2 * hh], s[j][2 * hh + 1]));
            mx = fmaxf(mx, __shfl_xor_sync(0xffffffffu, mx, 1));
            mx = fmaxf(mx, __shfl_xor_sync(0xffffffffu, mx, 2));
            float mNew = fmaxf(mrow[hh], mx);
            float corr = exp2f(mrow[hh] - mNew);
            float rs = 0.0f;
            #pragma unroll
            for (int j = 0; j < 8; j++) {
                float p0 = rnd_h(exp2f(s[j][2 * hh]     - mNew));
                float p1 = rnd_h(exp2f(s[j][2 * hh + 1] - mNew));
                s[j][2 * hh]     = p0;
                s[j][2 * hh + 1] = p1;
                rs += p0 + p1;
            }
            rs += __shfl_xor_sync(0xffffffffu, rs, 1);
            rs += __shfl_xor_sync(0xffffffffu, rs, 2);
            lrow[hh] = lrow[hh] * corr + rs;
            mrow[hh] = mNew;
            #pragma unroll
            for (int j = 0; j < 8; j++) {
                o[j][2 * hh]     *= corr;
                o[j][2 * hh + 1] *= corr;
            }
        }

        // O += P @ V : single-limb P x single-limb V
        #pragma unroll
        for (int ks = 0; ks < 4; ks++) {
            uint32_t ph[4];
            ph[0] = packh(s[2 * ks][0],     s[2 * ks][1]);
            ph[1] = packh(s[2 * ks][2],     s[2 * ks][3]);
            ph[2] = packh(s[2 * ks + 1][0], s[2 * ks + 1][1]);
            ph[3] = packh(s[2 * ks + 1][2], s[2 * ks + 1][3]);
            uint32_t bcc = 2 * ks + bc;
            #pragma unroll
            for (int jp = 0; jp < 4; jp++) {
                uint32_t row = 16 * jp + brow;
                uint32_t off = row * 128 + ((bcc ^ bxr) << 4);
                uint32_t vh0, vh1, vh2, vh3;
                ldsm_x4(vh0, vh1, vh2, vh3, kbuf + SM_VHI + off);
                mma16816(o[2 * jp],     ph, vh0, vh1);
                mma16816(o[2 * jp + 1], ph, vh2, vh3);
            }
        }
        __syncthreads();
    }

    const int b_ = bh >> 3;
    const int h  = bh & 7;
    const int c0 = (lane & 3) * 2;
    const float i0 = 1.0f / lrow[0];
    const float i1 = 1.0f / lrow[1];
    const int ra = m0 + w * 16 + rq;
    #pragma unroll
    for (int j = 0; j < 8; j++) {
        int col = 8 * j + c0;
        uint32_t h0, l0, h1, l1;
        split2(o[j][0] * i0, o[j][1] * i0, h0, l0);
        split2(o[j][2] * i1, o[j][3] * i1, h1, l1);
        size_t off0 = ((size_t)(b_ * NN + ra)) * D_MODEL + h * DK + col;
        size_t off1 = ((size_t)(b_ * NN + ra + 8)) * D_MODEL + h * DK + col;
        *reinterpret_cast<uint32_t*>(&g_ah[off0]) = h0;
        *reinterpret_cast<uint32_t*>(&g_al[off0]) = l0;
        *reinterpret_cast<uint32_t*>(&g_ah[off1]) = h1;
        *reinterpret_cast<uint32_t*>(&g_al[off1]) = l1;
    }
}

// ---------------------------------------------------------------------------
extern "C" void kernel_launch(void* const* d_in, const int* in_sizes, int n_in,
                              void* d_out, int out_size)
{
    (void)in_sizes; (void)n_in; (void)out_size;
    const float* x  = (const float*)d_in[0];
    const float* Wq = (const float*)d_in[1];
    const float* bq = (const float*)d_in[2];
    const float* Wk = (const float*)d_in[3];
    const float* bk = (const float*)d_in[4];
    const float* Wv = (const float*)d_in[5];
    const float* bv = (const float*)d_in[6];
    const float* Wo = (const float*)d_in[7];
    const float* bo = (const float*)d_in[8];

    void *xh, *xl, *wth, *ah, *al;
    cudaGetSymbolAddress(&xh, g_xh);
    cudaGetSymbolAddress(&xl, g_xl);
    cudaGetSymbolAddress(&wth, g_wth);
    cudaGetSymbolAddress(&ah, g_ah);
    cudaGetSymbolAddress(&al, g_al);

    __half* whp = (__half*)wth;

    cudaFuncSetAttribute(attn_tc, cudaFuncAttributeMaxDynamicSharedMemorySize, ATTN_SMEM);
    cudaFuncSetAttribute(gemm_raw, cudaFuncAttributeMaxDynamicSharedMemorySize, GEMM_SMEM);

    // single fused prep launch
    prep_all<<<NXB + 1024, 256>>>(x, Wq, Wk, Wv, Wo);

    // fused QKV projection: grid (24, 64)
    dim3 qkv_grid(24, M_TOTAL / 128);
    gemm_raw<<<qkv_grid, 256, GEMM_SMEM>>>((const __half*)xh, (const __half*)xl,
                                           whp, bq, bk, bv, nullptr, nullptr, 1);

    dim3 attn_grid(NN / 128, BH);   // (16, 32)
    attn_tc<<<attn_grid, 256, ATTN_SMEM>>>();

    // O projection: grid (8, 64) — bias_o = bo (R12 bug: was reading bias_q)
    dim3 o_grid(8, M_TOTAL / 128);
    gemm_raw<<<o_grid, 256, GEMM_SMEM>>>((const __half*)ah, (const __half*)al,
                                         whp, nullptr, nullptr, nullptr, bo, (float*)d_out, 0);
}

// round 14
// speedup vs baseline: 2.0261x; 1.1047x over previous
#include <cuda_runtime.h>
#include <cuda_fp16.h>
#include <math.h>
#include <stdint.h>

#define D_MODEL 512
#define NHEAD   8
#define DK      64
#define BB      4
#define NN      2048
#define M_TOTAL (BB * NN)     // 8192
#define BH      (BB * NHEAD)  // 32
#define NKV     (NN / 64)     // 32 kv blocks
#define WSZ     (D_MODEL * D_MODEL)

// Q pre-scale: 1/sqrt(64) * log2(e)
#define SC_ATTN 0.18033688f

// ---------------- scratch (allocation-free static device arrays) -----------
__device__ __align__(128) __half g_xh[M_TOTAL * D_MODEL];
__device__ __align__(128) __half g_xl[M_TOTAL * D_MODEL];
__device__ __align__(128) __half g_wth[4 * WSZ]; // W^T [n][k], single fp16 limb
__device__ __align__(128) __half g_qh[BH * NN * DK];  // single limb (pre-scaled)
__device__ __align__(128) __half g_kh[BH * NN * DK];
__device__ __align__(128) __half g_kl[BH * NN * DK];
__device__ __align__(128) __half g_vth[BH * DK * NN]; // [bh][d][n], single limb
__device__ __align__(128) __half g_ah[M_TOTAL * D_MODEL]; // attn out split
__device__ __align__(128) __half g_al[M_TOTAL * D_MODEL];

// ---------------------------------------------------------------------------
// helpers (fp16 splits)
// ---------------------------------------------------------------------------
__device__ __forceinline__ uint32_t packh(float x, float y) {
    __half2 t = __floats2half2_rn(x, y);
    return *reinterpret_cast<uint32_t*>(&t);
}
__device__ __forceinline__ void split2(float x, float y, uint32_t& hi, uint32_t& lo) {
    float hx = __half2float(__float2half_rn(x));
    float hy = __half2float(__float2half_rn(y));
    hi = packh(hx, hy);
    lo = packh(x - hx, y - hy);
}
__device__ __forceinline__ float rnd_h(float x) {
    return __half2float(__float2half_rn(x));
}
__device__ __forceinline__ void mma16816(float* c, const uint32_t* a, uint32_t b0, uint32_t b1) {
    asm volatile(
        "mma.sync.aligned.m16n8k16.row.col.f32.f16.f16.f32 "
        "{%0,%1,%2,%3}, {%4,%5,%6,%7}, {%8,%9}, {%0,%1,%2,%3};\n"
        : "+f"(c[0]), "+f"(c[1]), "+f"(c[2]), "+f"(c[3])
        : "r"(a[0]), "r"(a[1]), "r"(a[2]), "r"(a[3]), "r"(b0), "r"(b1));
}
__device__ __forceinline__ void ldsm_x4(uint32_t& d0, uint32_t& d1, uint32_t& d2, uint32_t& d3,
                                        uint32_t saddr) {
    asm volatile("ldmatrix.sync.aligned.m8n8.x4.shared.b16 {%0,%1,%2,%3}, [%4];"
                 : "=r"(d0), "=r"(d1), "=r"(d2), "=r"(d3) : "r"(saddr));
}
__device__ __forceinline__ void cp16(uint32_t dst, const void* src) {
    asm volatile("cp.async.cg.shared.global [%0], [%1], 16;" :: "r"(dst), "l"(src));
}
__device__ __forceinline__ void cp_commit() { asm volatile("cp.async.commit_group;"); }
template<int N> __device__ __forceinline__ void cp_wait() {
    asm volatile("cp.async.wait_group %0;" :: "n"(N));
}
__device__ __forceinline__ uint32_t SW(uint32_t r, uint32_t c) {
    return r * 128u + ((c ^ (r & 7u)) << 4);
}

// ---------------------------------------------------------------------------
// fused prep: x hi/lo split + 4x weight transpose (single fp16 limb), one launch.
// ---------------------------------------------------------------------------
#define NXB ((M_TOTAL * D_MODEL / 4) / 256)   // 4096

__global__ void __launch_bounds__(256)
prep_all(const float* __restrict__ x,
         const float* __restrict__ W0, const float* __restrict__ W1,
         const float* __restrict__ W2, const float* __restrict__ W3)
{
    const int bid = blockIdx.x;
    if (bid < NXB) {
        int i = bid * 256 + threadIdx.x;
        float4 v = reinterpret_cast<const float4*>(x)[i];
        uint32_t h01, l01, h23, l23;
        split2(v.x, v.y, h01, l01);
        split2(v.z, v.w, h23, l23);
        reinterpret_cast<uint2*>(g_xh)[i] = make_uint2(h01, h23);
        reinterpret_cast<uint2*>(g_xl)[i] = make_uint2(l01, l23);
        return;
    }
    __shared__ float ts[32][33];
    const int t   = bid - NXB;
    const int mat = t >> 8;
    const int blk = t & 255;
    const float* W = (mat == 0) ? W0 : (mat == 1) ? W1 : (mat == 2) ? W2 : W3;
    __half* th = g_wth + (size_t)mat * WSZ;
    int n0 = (blk & 15) * 32, k0 = (blk >> 4) * 32;
    int tx = threadIdx.x & 31, ty = threadIdx.x >> 5;
    #pragma unroll
    for (int j = 0; j < 4; j++)
        ts[ty + j * 8][tx] = W[(size_t)(k0 + ty + j * 8) * D_MODEL + n0 + tx];
    __syncthreads();
    #pragma unroll
    for (int j = 0; j < 4; j++) {
        int n = ty + j * 8;
        th[(size_t)(n0 + n) * D_MODEL + k0 + tx] = __float2half_rn(ts[tx][n]);
    }
}

// ---------------------------------------------------------------------------
// Raw-mma GEMM: out = A[M,512] @ Wt^T + bias.
// A 2-limb fp16 (hi+lo), W single fp16 limb -> 2 MMAs per fragment pair.
// CTA tile 128x64, BK=64, 256 thr / 8 warps, cp.async double-buffered.
// fused=1: QKV (grid.x=24): Q->1-limb*SC_ATTN, K->2-limb, V->1-limb transposed.
// fused=0: O-projection (grid.x=8): fp32 out, bias = bias_o.
// ---------------------------------------------------------------------------
#define GS_AHI 0
#define GS_ALO 16384
#define GS_BHI 32768
#define GS_STAGE 40960
#define GEMM_SMEM (2 * GS_STAGE)   // 80 KB

__global__ void __launch_bounds__(256, 2)
gemm_raw(const __half* __restrict__ Ah, const __half* __restrict__ Al,
         const __half* __restrict__ Bh,
         const float* __restrict__ bias_q, const float* __restrict__ bias_k,
         const float* __restrict__ bias_v, const float* __restrict__ bias_o,
         float* __restrict__ outf, int fused)
{
    extern __shared__ __align__(128) unsigned char sm[];
    const uint32_t sbase = (uint32_t)__cvta_generic_to_shared(sm);

    const int tid  = threadIdx.x;
    const int lane = tid & 31;
    const int w    = tid >> 5;
    const int rq   = lane >> 2;
    const int cb   = blockIdx.x;
    const int m0   = blockIdx.y * 128;

    const int wsel  = fused ? (cb >> 3) : 3;
    const int n_in  = (cb & 7) * 64;
    const size_t brow0 = (size_t)wsel * D_MODEL + n_in;

    auto load_chunk = [&](int kc, int buf) {
        uint32_t base = sbase + buf * GS_STAGE;
        int kb = kc * 64;
        #pragma unroll
        for (int t = 0; t < 4; t++) {
            int id = tid + t * 256;
            int r = id >> 3, c = id & 7;
            uint32_t so = SW(r, c);
            size_t g = (size_t)(m0 + r) * D_MODEL + kb + c * 8;
            cp16(base + GS_AHI + so, Ah + g);
            cp16(base + GS_ALO + so, Al + g);
        }
        #pragma unroll
        for (int t = 0; t < 2; t++) {
            int id = tid + t * 256;
            int r = id >> 3, c = id & 7;
            uint32_t so = SW(r, c);
            size_t g = (brow0 + r) * D_MODEL + kb + c * 8;
            cp16(base + GS_BHI + so, Bh + g);
        }
        cp_commit();
    };

    float s[8][4];
    #pragma unroll
    for (int j = 0; j < 8; j++)
        #pragma unroll
        for (int e = 0; e < 4; e++) s[j][e] = 0.0f;

    const uint32_t qrow = w * 16 + (lane & 15);
    const uint32_t qc   = lane >> 4;
    const uint32_t qoff = qrow * 128;
    const uint32_t qxr  = qrow & 7;
    const uint32_t brow = ((lane >> 4) << 3) + (lane & 7);
    const uint32_t bc   = (lane >> 3) & 1;
    const uint32_t bxr  = brow & 7;

    load_chunk(0, 0);
    load_chunk(1, 1);

    for (int i = 0; i < 8; i++) {
        if (i == 7) cp_wait<0>(); else cp_wait<1>();
        __syncthreads();
        const uint32_t abuf = sbase + (i & 1) * GS_STAGE;

        #pragma unroll
        for (int ks = 0; ks < 4; ks++) {
            uint32_t ah[4], al[4];
            uint32_t qcc = 2 * ks + qc;
            ldsm_x4(ah[0], ah[1], ah[2], ah[3], abuf + GS_AHI + qoff + ((qcc ^ qxr) << 4));
            ldsm_x4(al[0], al[1], al[2], al[3], abuf + GS_ALO + qoff + ((qcc ^ qxr) << 4));
            uint32_t bcc = 2 * ks + bc;
            #pragma unroll
            for (int jp = 0; jp < 4; jp++) {
                uint32_t row = 16 * jp + brow;
                uint32_t off = row * 128 + ((bcc ^ bxr) << 4);
                uint32_t bh0, bh1, bh2, bh3;
                ldsm_x4(bh0, bh1, bh2, bh3, abuf + GS_BHI + off);
                mma16816(s[2 * jp],     ah, bh0, bh1);
                mma16816(s[2 * jp],     al, bh0, bh1);
                mma16816(s[2 * jp + 1], ah, bh2, bh3);
                mma16816(s[2 * jp + 1], al, bh2, bh3);
            }
        }
        __syncthreads();
        if (i + 2 < 8) load_chunk(i + 2, i & 1);
    }

    float* Cst = (float*)sm;
    {
        const int c0 = (lane & 3) * 2;
        const int ra = w * 16 + rq;
        #pragma unroll
        for (int j = 0; j < 8; j++) {
            int col = 8 * j + c0;
            Cst[ra * 68 + col]           = s[j][0];
            Cst[ra * 68 + col + 1]       = s[j][1];
            Cst[(ra + 8) * 68 + col]     = s[j][2];
            Cst[(ra + 8) * 68 + col + 1] = s[j][3];
        }
    }
    __syncthreads();

    if (!fused) {
        const int orow = tid >> 4;
        const int ocol = (tid & 15) * 4;
        float4 b4 = *reinterpret_cast<const float4*>(&bias_o[n_in + ocol]);
        #pragma unroll
        for (int t = 0; t < 8; t++) {
            int r = orow + t * 16;
            float4 v = *reinterpret_cast<const float4*>(&Cst[r * 68 + ocol]);
            v.x += b4.x; v.y += b4.y; v.z += b4.z; v.w += b4.w;
            *reinterpret_cast<float4*>(&outf[(size_t)(m0 + r) * D_MODEL + n_in + ocol]) = v;
        }
    } else if (wsel == 0) {
        // Q: SINGLE limb, scaled
        const int h = cb & 7;
        const int orow = tid >> 4;
        const int ocol = (tid & 15) * 4;
        float4 b4 = *reinterpret_cast<const float4*>(&bias_q[n_in + ocol]);
        #pragma unroll
        for (int t = 0; t < 8; t++) {
            int r  = orow + t * 16;
            int rg = m0 + r;
            int b_ = rg >> 11;
            int n_ = rg & 2047;
            float4 v = *reinterpret_cast<const float4*>(&Cst[r * 68 + ocol]);
            uint32_t h01 = packh((v.x + b4.x) * SC_ATTN, (v.y + b4.y) * SC_ATTN);
            uint32_t h23 = packh((v.z + b4.z) * SC_ATTN, (v.w + b4.w) * SC_ATTN);
            size_t off = ((size_t)(b_ * NHEAD + h) * NN + n_) * DK + ocol;
            *reinterpret_cast<uint2*>(&g_qh[off]) = make_uint2(h01, h23);
        }
    } else if (wsel == 1) {
        // K: 2-limb split
        const int h = cb & 7;
        const int orow = tid >> 4;
        const int ocol = (tid & 15) * 4;
        float4 b4 = *reinterpret_cast<const float4*>(&bias_k[n_in + ocol]);
        #pragma unroll
        for (int t = 0; t < 8; t++) {
            int r  = orow + t * 16;
            int rg = m0 + r;
            int b_ = rg >> 11;
            int n_ = rg & 2047;
            float4 v = *reinterpret_cast<const float4*>(&Cst[r * 68 + ocol]);
            uint32_t h01, l01, h23, l23;
            split2(v.x + b4.x, v.y + b4.y, h01, l01);
            split2(v.z + b4.z, v.w + b4.w, h23, l23);
            size_t off = ((size_t)(b_ * NHEAD + h) * NN + n_) * DK + ocol;
            *reinterpret_cast<uint2*>(&g_kh[off]) = make_uint2(h01, h23);
            *reinterpret_cast<uint2*>(&g_kl[off]) = make_uint2(l01, l23);
        }
    } else {
        // V transposed, SINGLE fp16 limb [bh][d][n]
        const int h   = cb & 7;
        const int od  = tid >> 2;
        const int on0 = (tid & 3) * 32;
        const int b_  = m0 >> 11;
        const int nb  = (m0 & 2047) + on0;
        const float bv = bias_v[n_in + od];
        size_t rowoff = ((size_t)(b_ * NHEAD + h) * DK + od) * NN + nb;
        #pragma unroll
        for (int i = 0; i < 32; i += 2) {
            float v0 = Cst[(on0 + i) * 68 + od] + bv;
            float v1 = Cst[(on0 + i + 1) * 68 + od] + bv;
            *reinterpret_cast<uint32_t*>(&g_vth[rowoff + i]) = packh(v0, v1);
        }
    }
}

// ---------------------------------------------------------------------------
// Flash attention: BM=128, BN=64, d=64, 256 thr, 2 CTAs/SM.
// S: 1-limb Q x 2-limb K (2 MMAs). PV: 1-limb P x 1-limb V.
// ---------------------------------------------------------------------------
#define SM_QHI 0
#define SM_BUF(b) (16384 + (b) * 24576)
#define SM_KHI 0
#define SM_KLO 8192
#define SM_VHI 16384
#define ATTN_SMEM (16384 + 2 * 24576)   // 64 KB

__global__ void __launch_bounds__(256, 2)
attn_tc()
{
    extern __shared__ __align__(128) unsigned char sm[];
    const uint32_t sbase = (uint32_t)__cvta_generic_to_shared(sm);

    const int tid  = threadIdx.x;
    const int lane = tid & 31;
    const int w    = tid >> 5;
    const int rq   = lane >> 2;
    const int bh   = blockIdx.y;
    const int m0   = blockIdx.x * 128;

    const __half* qh_g = g_qh + (size_t)bh * NN * DK;
    const __half* kh_g = g_kh + (size_t)bh * NN * DK;
    const __half* kl_g = g_kl + (size_t)bh * NN * DK;
    const __half* vh_g = g_vth + (size_t)bh * DK * NN;

    {
        #pragma unroll
        for (int p = 0; p < 4; p++) {
            int id = tid + p * 256;
            int r = id >> 3, c = id & 7;
            size_t go = (size_t)(m0 + r) * DK + c * 8;
            cp16(sbase + SM_QHI + SW(r, c), qh_g + go);
        }
        cp_commit();
    }
    {
        #pragma unroll
        for (int p = 0; p < 2; p++) {
            int id = tid + p * 256;
            int r = id >> 3, c = id & 7;
            uint32_t so = SW(r, c);
            size_t ko = (size_t)r * DK + c * 8;
            size_t vo = (size_t)r * NN + c * 8;
            cp16(sbase + SM_BUF(0) + SM_KHI + so, kh_g + ko);
            cp16(sbase + SM_BUF(0) + SM_KLO + so, kl_g + ko);
            cp16(sbase + SM_BUF(0) + SM_VHI + so, vh_g + vo);
        }
        cp_commit();
    }

    float o[8][4];
    #pragma unroll
    for (int j = 0; j < 8; j++)
        #pragma unroll
        for (int e = 0; e < 4; e++) o[j][e] = 0.0f;
    float mrow[2] = {-1e30f, -1e30f};
    float lrow[2] = {0.0f, 0.0f};

    const uint32_t qrow = w * 16 + (lane & 15);
    const uint32_t qc   = lane >> 4;
    const uint32_t qoff = qrow * 128;
    const uint32_t qxr  = qrow & 7;
    const uint32_t brow = ((lane >> 4) << 3) + (lane & 7);
    const uint32_t bc   = (lane >> 3) & 1;
    const uint32_t bxr  = brow & 7;

    for (int i = 0; i < NKV; i++) {
        if (i < NKV - 1) {
            int buf = (i + 1) & 1;
            int kb = (i + 1) * 64;
            #pragma unroll
            for (int p = 0; p < 2; p++) {
                int id = tid + p * 256;
                int r = id >> 3, c = id & 7;
                uint32_t so = SW(r, c);
                size_t ko = (size_t)(kb + r) * DK + c * 8;
                size_t vo = (size_t)r * NN + kb + c * 8;
                cp16(sbase + SM_BUF(buf) + SM_KHI + so, kh_g + ko);
                cp16(sbase + SM_BUF(buf) + SM_KLO + so, kl_g + ko);
                cp16(sbase + SM_BUF(buf) + SM_VHI + so, vh_g + vo);
            }
            cp_commit();
            cp_wait<1>();
        } else {
            cp_wait<0>();
        }
        __syncthreads();

        const uint32_t kbuf = sbase + SM_BUF(i & 1);

        float s[8][4];
        #pragma unroll
        for (int j = 0; j < 8; j++)
            #pragma unroll
            for (int e = 0; e < 4; e++) s[j][e] = 0.0f;

        #pragma unroll
        for (int ks = 0; ks < 4; ks++) {
            uint32_t qh[4];
            uint32_t qcc = 2 * ks + qc;
            ldsm_x4(qh[0], qh[1], qh[2], qh[3], sbase + SM_QHI + qoff + ((qcc ^ qxr) << 4));
            uint32_t bcc = 2 * ks + bc;
            #pragma unroll
            for (int jp = 0; jp < 4; jp++) {
                uint32_t row = 16 * jp + brow;
                uint32_t off = row * 128 + ((bcc ^ bxr) << 4);
                uint32_t kh0, kh1, kh2, kh3, kl0, kl1, kl2, kl3;
                ldsm_x4(kh0, kh1, kh2, kh3, kbuf + SM_KHI + off);
                ldsm_x4(kl0, kl1, kl2, kl3, kbuf + SM_KLO + off);
                mma16816(s[2 * jp],     qh, kh0, kh1);
                mma16816(s[2 * jp],     qh, kl0, kl1);
                mma16816(s[2 * jp + 1], qh, kh2, kh3);
                mma16816(s[2 * jp + 1], qh, kl2, kl3);
            }
        }

        // online softmax; p rounded to fp16 BEFORE accumulating denominator
        #pragma unroll
        for (int hh = 0; hh < 2; hh++) {
            float mx = -1e30f;
            #pragma unroll
            for (int j = 0; j < 8; j++)
                mx = fmaxf(mx, fmaxf(s[j][2 * hh], s[j][2 * hh + 1]));
            mx = fmaxf(mx, __shfl_xor_sync(0xffffffffu, mx, 1));
            mx = fmaxf(mx, __shfl_xor_sync(0xffffffffu, mx, 2));
            float mNew = fmaxf(mrow[hh], mx);
            float corr = exp2f(mrow[hh] - mNew);
            float rs = 0.0f;
            #pragma unroll
            for (int j = 0; j < 8; j++) {
                float p0 = rnd_h(exp2f(s[j][2 * hh]     - mNew));
                float p1 = rnd_h(exp2f(s[j][2 * hh + 1] - mNew));
                s[j][2 * hh]     = p0;
                s[j][2 * hh + 1] = p1;
                rs += p0 + p1;
            }
            rs += __shfl_xor_sync(0xffffffffu, rs, 1);
            rs += __shfl_xor_sync(0xffffffffu, rs, 2);
            lrow[hh] = lrow[hh] * corr + rs;
            mrow[hh] = mNew;
            #pragma unroll
            for (int j = 0; j < 8; j++) {
                o[j][2 * hh]     *= corr;
                o[j][2 * hh + 1] *= corr;
            }
        }

        // O += P @ V : single-limb P x single-limb V
        #pragma unroll
        for (int ks = 0; ks < 4; ks++) {
            uint32_t ph[4];
            ph[0] = packh(s[2 * ks][0],     s[2 * ks][1]);
            ph[1] = packh(s[2 * ks][2],     s[2 * ks][3]);
            ph[2] = packh(s[2 * ks + 1][0], s[2 * ks + 1][1]);
            ph[3] = packh(s[2 * ks + 1][2], s[2 * ks + 1][3]);
            uint32_t bcc = 2 * ks + bc;
            #pragma unroll
            for (int jp = 0; jp < 4; jp++) {
                uint32_t row = 16 * jp + brow;
                uint32_t off = row * 128 + ((bcc ^ bxr) << 4);
                uint32_t vh0, vh1, vh2, vh3;
                ldsm_x4(vh0, vh1, vh2, vh3, kbuf + SM_VHI + off);
                mma16816(o[2 * jp],     ph, vh0, vh1);
                mma16816(o[2 * jp + 1], ph, vh2, vh3);
            }
        }
        __syncthreads();
    }

    const int b_ = bh >> 3;
    const int h  = bh & 7;
    const int c0 = (lane & 3) * 2;
    const float i0 = 1.0f / lrow[0];
    const float i1 = 1.0f / lrow[1];
    const int ra = m0 + w * 16 + rq;
    #pragma unroll
    for (int j = 0; j < 8; j++) {
        int col = 8 * j + c0;
        uint32_t h0, l0, h1, l1;
        split2(o[j][0] * i0, o[j][1] * i0, h0, l0);
        split2(o[j][2] * i1, o[j][3] * i1, h1, l1);
        size_t off0 = ((size_t)(b_ * NN + ra)) * D_MODEL + h * DK + col;
        size_t off1 = ((size_t)(b_ * NN + ra + 8)) * D_MODEL + h * DK + col;
        *reinterpret_cast<uint32_t*>(&g_ah[off0]) = h0;
        *reinterpret_cast<uint32_t*>(&g_al[off0]) = l0;
        *reinterpret_cast<uint32_t*>(&g_ah[off1]) = h1;
        *reinterpret_cast<uint32_t*>(&g_al[off1]) = l1;
    }
}

// ---------------------------------------------------------------------------
extern "C" void kernel_launch(void* const* d_in, const int* in_sizes, int n_in,
                              void* d_out, int out_size)
{
    (void)in_sizes; (void)n_in; (void)out_size;
    const float* x  = (const float*)d_in[0];
    const float* Wq = (const float*)d_in[1];
    const float* bq = (const float*)d_in[2];
    const float* Wk = (const float*)d_in[3];
    const float* bk = (const float*)d_in[4];
    const float* Wv = (const float*)d_in[5];
    const float* bv = (const float*)d_in[6];
    const float* Wo = (const float*)d_in[7];
    const float* bo = (const float*)d_in[8];

    void *xh, *xl, *wth, *ah, *al;
    cudaGetSymbolAddress(&xh, g_xh);
    cudaGetSymbolAddress(&xl, g_xl);
    cudaGetSymbolAddress(&wth, g_wth);
    cudaGetSymbolAddress(&ah, g_ah);
    cudaGetSymbolAddress(&al, g_al);

    __half* whp = (__half*)wth;

    cudaFuncSetAttribute(attn_tc, cudaFuncAttributeMaxDynamicSharedMemorySize, ATTN_SMEM);
    cudaFuncSetAttribute(gemm_raw, cudaFuncAttributeMaxDynamicSharedMemorySize, GEMM_SMEM);

    // single fused prep launch
    prep_all<<<NXB + 1024, 256>>>(x, Wq, Wk, Wv, Wo);

    // fused QKV projection: grid (24, 64)
    dim3 qkv_grid(24, M_TOTAL / 128);
    gemm_raw<<<qkv_grid, 256, GEMM_SMEM>>>((const __half*)xh, (const __half*)xl,
                                           whp, bq, bk, bv, nullptr, nullptr, 1);

    dim3 attn_grid(NN / 128, BH);   // (16, 32)
    attn_tc<<<attn_grid, 256, ATTN_SMEM>>>();

    // O projection: grid (8, 64)
    dim3 o_grid(8, M_TOTAL / 128);
    gemm_raw<<<o_grid, 256, GEMM_SMEM>>>((const __half*)ah, (const __half*)al,
                                         whp, nullptr, nullptr, nullptr, bo, (float*)d_out, 0);
}

// round 15
// speedup vs baseline: 2.3600x; 1.1648x over previous
#include <cuda_runtime.h>
#include <cuda_fp16.h>
#include <math.h>
#include <stdint.h>

#define D_MODEL 512
#define NHEAD   8
#define DK      64
#define BB      4
#define NN      2048
#define M_TOTAL (BB * NN)     // 8192
#define BH      (BB * NHEAD)  // 32
#define NKV     (NN / 64)     // 32 kv blocks
#define WSZ     (D_MODEL * D_MODEL)

// Q pre-scale: 1/sqrt(64) * log2(e)
#define SC_ATTN 0.18033688f

// ---------------- scratch (allocation-free static device arrays) -----------
__device__ __align__(128) __half g_xh[M_TOTAL * D_MODEL];
__device__ __align__(128) __half g_xl[M_TOTAL * D_MODEL];
__device__ __align__(128) __half g_wth[4 * WSZ]; // W^T [n][k], single fp16 limb
__device__ __align__(128) __half g_qh[BH * NN * DK];  // single limb (pre-scaled)
__device__ __align__(128) __half g_kh[BH * NN * DK];  // single limb
__device__ __align__(128) __half g_vth[BH * DK * NN]; // [bh][d][n], single limb
__device__ __align__(128) __half g_ah[M_TOTAL * D_MODEL]; // attn out split
__device__ __align__(128) __half g_al[M_TOTAL * D_MODEL];

// ---------------------------------------------------------------------------
// helpers (fp16 splits)
// ---------------------------------------------------------------------------
__device__ __forceinline__ uint32_t packh(float x, float y) {
    __half2 t = __floats2half2_rn(x, y);
    return *reinterpret_cast<uint32_t*>(&t);
}
__device__ __forceinline__ void split2(float x, float y, uint32_t& hi, uint32_t& lo) {
    float hx = __half2float(__float2half_rn(x));
    float hy = __half2float(__float2half_rn(y));
    hi = packh(hx, hy);
    lo = packh(x - hx, y - hy);
}
__device__ __forceinline__ float rnd_h(float x) {
    return __half2float(__float2half_rn(x));
}
__device__ __forceinline__ void mma16816(float* c, const uint32_t* a, uint32_t b0, uint32_t b1) {
    asm volatile(
        "mma.sync.aligned.m16n8k16.row.col.f32.f16.f16.f32 "
        "{%0,%1,%2,%3}, {%4,%5,%6,%7}, {%8,%9}, {%0,%1,%2,%3};\n"
        : "+f"(c[0]), "+f"(c[1]), "+f"(c[2]), "+f"(c[3])
        : "r"(a[0]), "r"(a[1]), "r"(a[2]), "r"(a[3]), "r"(b0), "r"(b1));
}
__device__ __forceinline__ void ldsm_x4(uint32_t& d0, uint32_t& d1, uint32_t& d2, uint32_t& d3,
                                        uint32_t saddr) {
    asm volatile("ldmatrix.sync.aligned.m8n8.x4.shared.b16 {%0,%1,%2,%3}, [%4];"
                 : "=r"(d0), "=r"(d1), "=r"(d2), "=r"(d3) : "r"(saddr));
}
__device__ __forceinline__ void cp16(uint32_t dst, const void* src) {
    asm volatile("cp.async.cg.shared.global [%0], [%1], 16;" :: "r"(dst), "l"(src));
}
__device__ __forceinline__ void cp_commit() { asm volatile("cp.async.commit_group;"); }
template<int N> __device__ __forceinline__ void cp_wait() {
    asm volatile("cp.async.wait_group %0;" :: "n"(N));
}
__device__ __forceinline__ uint32_t SW(uint32_t r, uint32_t c) {
    return r * 128u + ((c ^ (r & 7u)) << 4);
}

// ---------------------------------------------------------------------------
// fused prep: x hi/lo split + 4x weight transpose (single fp16 limb), one launch.
// ---------------------------------------------------------------------------
#define NXB ((M_TOTAL * D_MODEL / 4) / 256)   // 4096

__global__ void __launch_bounds__(256)
prep_all(const float* __restrict__ x,
         const float* __restrict__ W0, const float* __restrict__ W1,
         const float* __restrict__ W2, const float* __restrict__ W3)
{
    const int bid = blockIdx.x;
    if (bid < NXB) {
        int i = bid * 256 + threadIdx.x;
        float4 v = reinterpret_cast<const float4*>(x)[i];
        uint32_t h01, l01, h23, l23;
        split2(v.x, v.y, h01, l01);
        split2(v.z, v.w, h23, l23);
        reinterpret_cast<uint2*>(g_xh)[i] = make_uint2(h01, h23);
        reinterpret_cast<uint2*>(g_xl)[i] = make_uint2(l01, l23);
        return;
    }
    __shared__ float ts[32][33];
    const int t   = bid - NXB;
    const int mat = t >> 8;
    const int blk = t & 255;
    const float* W = (mat == 0) ? W0 : (mat == 1) ? W1 : (mat == 2) ? W2 : W3;
    __half* th = g_wth + (size_t)mat * WSZ;
    int n0 = (blk & 15) * 32, k0 = (blk >> 4) * 32;
    int tx = threadIdx.x & 31, ty = threadIdx.x >> 5;
    #pragma unroll
    for (int j = 0; j < 4; j++)
        ts[ty + j * 8][tx] = W[(size_t)(k0 + ty + j * 8) * D_MODEL + n0 + tx];
    __syncthreads();
    #pragma unroll
    for (int j = 0; j < 4; j++) {
        int n = ty + j * 8;
        th[(size_t)(n0 + n) * D_MODEL + k0 + tx] = __float2half_rn(ts[tx][n]);
    }
}

// ---------------------------------------------------------------------------
// Raw-mma GEMM: out = A[M,512] @ Wt^T + bias.
// A 2-limb fp16 (hi+lo), W single fp16 limb -> 2 MMAs per fragment pair.
// CTA tile 128x64, BK=64, 256 thr / 8 warps, cp.async double-buffered.
// fused=1: QKV (grid.x=24): Q->1-limb*SC_ATTN, K->1-limb, V->1-limb transposed.
// fused=0: O-projection (grid.x=8): fp32 out, bias = bias_o.
// ---------------------------------------------------------------------------
#define GS_AHI 0
#define GS_ALO 16384
#define GS_BHI 32768
#define GS_STAGE 40960
#define GEMM_SMEM (2 * GS_STAGE)   // 80 KB

__global__ void __launch_bounds__(256, 2)
gemm_raw(const __half* __restrict__ Ah, const __half* __restrict__ Al,
         const __half* __restrict__ Bh,
         const float* __restrict__ bias_q, const float* __restrict__ bias_k,
         const float* __restrict__ bias_v, const float* __restrict__ bias_o,
         float* __restrict__ outf, int fused)
{
    extern __shared__ __align__(128) unsigned char sm[];
    const uint32_t sbase = (uint32_t)__cvta_generic_to_shared(sm);

    const int tid  = threadIdx.x;
    const int lane = tid & 31;
    const int w    = tid >> 5;
    const int rq   = lane >> 2;
    const int cb   = blockIdx.x;
    const int m0   = blockIdx.y * 128;

    const int wsel  = fused ? (cb >> 3) : 3;
    const int n_in  = (cb & 7) * 64;
    const size_t brow0 = (size_t)wsel * D_MODEL + n_in;

    auto load_chunk = [&](int kc, int buf) {
        uint32_t base = sbase + buf * GS_STAGE;
        int kb = kc * 64;
        #pragma unroll
        for (int t = 0; t < 4; t++) {
            int id = tid + t * 256;
            int r = id >> 3, c = id & 7;
            uint32_t so = SW(r, c);
            size_t g = (size_t)(m0 + r) * D_MODEL + kb + c * 8;
            cp16(base + GS_AHI + so, Ah + g);
            cp16(base + GS_ALO + so, Al + g);
        }
        #pragma unroll
        for (int t = 0; t < 2; t++) {
            int id = tid + t * 256;
            int r = id >> 3, c = id & 7;
            uint32_t so = SW(r, c);
            size_t g = (brow0 + r) * D_MODEL + kb + c * 8;
            cp16(base + GS_BHI + so, Bh + g);
        }
        cp_commit();
    };

    float s[8][4];
    #pragma unroll
    for (int j = 0; j < 8; j++)
        #pragma unroll
        for (int e = 0; e < 4; e++) s[j][e] = 0.0f;

    const uint32_t qrow = w * 16 + (lane & 15);
    const uint32_t qc   = lane >> 4;
    const uint32_t qoff = qrow * 128;
    const uint32_t qxr  = qrow & 7;
    const uint32_t brow = ((lane >> 4) << 3) + (lane & 7);
    const uint32_t bc   = (lane >> 3) & 1;
    const uint32_t bxr  = brow & 7;

    load_chunk(0, 0);
    load_chunk(1, 1);

    for (int i = 0; i < 8; i++) {
        if (i == 7) cp_wait<0>(); else cp_wait<1>();
        __syncthreads();
        const uint32_t abuf = sbase + (i & 1) * GS_STAGE;

        #pragma unroll
        for (int ks = 0; ks < 4; ks++) {
            uint32_t ah[4], al[4];
            uint32_t qcc = 2 * ks + qc;
            ldsm_x4(ah[0], ah[1], ah[2], ah[3], abuf + GS_AHI + qoff + ((qcc ^ qxr) << 4));
            ldsm_x4(al[0], al[1], al[2], al[3], abuf + GS_ALO + qoff + ((qcc ^ qxr) << 4));
            uint32_t bcc = 2 * ks + bc;
            #pragma unroll
            for (int jp = 0; jp < 4; jp++) {
                uint32_t row = 16 * jp + brow;
                uint32_t off = row * 128 + ((bcc ^ bxr) << 4);
                uint32_t bh0, bh1, bh2, bh3;
                ldsm_x4(bh0, bh1, bh2, bh3, abuf + GS_BHI + off);
                mma16816(s[2 * jp],     ah, bh0, bh1);
                mma16816(s[2 * jp],     al, bh0, bh1);
                mma16816(s[2 * jp + 1], ah, bh2, bh3);
                mma16816(s[2 * jp + 1], al, bh2, bh3);
            }
        }
        __syncthreads();
        if (i + 2 < 8) load_chunk(i + 2, i & 1);
    }

    float* Cst = (float*)sm;
    {
        const int c0 = (lane & 3) * 2;
        const int ra = w * 16 + rq;
        #pragma unroll
        for (int j = 0; j < 8; j++) {
            int col = 8 * j + c0;
            Cst[ra * 68 + col]           = s[j][0];
            Cst[ra * 68 + col + 1]       = s[j][1];
            Cst[(ra + 8) * 68 + col]     = s[j][2];
            Cst[(ra + 8) * 68 + col + 1] = s[j][3];
        }
    }
    __syncthreads();

    if (!fused) {
        const int orow = tid >> 4;
        const int ocol = (tid & 15) * 4;
        float4 b4 = *reinterpret_cast<const float4*>(&bias_o[n_in + ocol]);
        #pragma unroll
        for (int t = 0; t < 8; t++) {
            int r = orow + t * 16;
            float4 v = *reinterpret_cast<const float4*>(&Cst[r * 68 + ocol]);
            v.x += b4.x; v.y += b4.y; v.z += b4.z; v.w += b4.w;
            *reinterpret_cast<float4*>(&outf[(size_t)(m0 + r) * D_MODEL + n_in + ocol]) = v;
        }
    } else if (wsel < 2) {
        // Q / K: SINGLE limb (Q scaled by SC_ATTN)
        const float scale = (wsel == 0) ? SC_ATTN : 1.0f;
        __half* ohi = (wsel == 0) ? g_qh : g_kh;
        const float* bias = (wsel == 0) ? bias_q : bias_k;
        const int h = cb & 7;
        const int orow = tid >> 4;
        const int ocol = (tid & 15) * 4;
        float4 b4 = *reinterpret_cast<const float4*>(&bias[n_in + ocol]);
        #pragma unroll
        for (int t = 0; t < 8; t++) {
            int r  = orow + t * 16;
            int rg = m0 + r;
            int b_ = rg >> 11;
            int n_ = rg & 2047;
            float4 v = *reinterpret_cast<const float4*>(&Cst[r * 68 + ocol]);
            uint32_t h01 = packh((v.x + b4.x) * scale, (v.y + b4.y) * scale);
            uint32_t h23 = packh((v.z + b4.z) * scale, (v.w + b4.w) * scale);
            size_t off = ((size_t)(b_ * NHEAD + h) * NN + n_) * DK + ocol;
            *reinterpret_cast<uint2*>(&ohi[off]) = make_uint2(h01, h23);
        }
    } else {
        // V transposed, SINGLE fp16 limb [bh][d][n]
        const int h   = cb & 7;
        const int od  = tid >> 2;
        const int on0 = (tid & 3) * 32;
        const int b_  = m0 >> 11;
        const int nb  = (m0 & 2047) + on0;
        const float bv = bias_v[n_in + od];
        size_t rowoff = ((size_t)(b_ * NHEAD + h) * DK + od) * NN + nb;
        #pragma unroll
        for (int i = 0; i < 32; i += 2) {
            float v0 = Cst[(on0 + i) * 68 + od] + bv;
            float v1 = Cst[(on0 + i + 1) * 68 + od] + bv;
            *reinterpret_cast<uint32_t*>(&g_vth[rowoff + i]) = packh(v0, v1);
        }
    }
}

// ---------------------------------------------------------------------------
// Flash attention: BM=128, BN=64, d=64, 256 thr, 2 CTAs/SM.
// S: 1-limb Q x 1-limb K (1 MMA per tile). PV: 1-limb P x 1-limb V.
// ---------------------------------------------------------------------------
#define SM_QHI 0
#define SM_BUF(b) (16384 + (b) * 16384)
#define SM_KHI 0
#define SM_VHI 8192
#define ATTN_SMEM (16384 + 2 * 16384)   // 48 KB

__global__ void __launch_bounds__(256, 2)
attn_tc()
{
    extern __shared__ __align__(128) unsigned char sm[];
    const uint32_t sbase = (uint32_t)__cvta_generic_to_shared(sm);

    const int tid  = threadIdx.x;
    const int lane = tid & 31;
    const int w    = tid >> 5;
    const int rq   = lane >> 2;
    const int bh   = blockIdx.y;
    const int m0   = blockIdx.x * 128;

    const __half* qh_g = g_qh + (size_t)bh * NN * DK;
    const __half* kh_g = g_kh + (size_t)bh * NN * DK;
    const __half* vh_g = g_vth + (size_t)bh * DK * NN;

    {
        #pragma unroll
        for (int p = 0; p < 4; p++) {
            int id = tid + p * 256;
            int r = id >> 3, c = id & 7;
            size_t go = (size_t)(m0 + r) * DK + c * 8;
            cp16(sbase + SM_QHI + SW(r, c), qh_g + go);
        }
        cp_commit();
    }
    {
        #pragma unroll
        for (int p = 0; p < 2; p++) {
            int id = tid + p * 256;
            int r = id >> 3, c = id & 7;
            uint32_t so = SW(r, c);
            cp16(sbase + SM_BUF(0) + SM_KHI + so, kh_g + (size_t)r * DK + c * 8);
            cp16(sbase + SM_BUF(0) + SM_VHI + so, vh_g + (size_t)r * NN + c * 8);
        }
        cp_commit();
    }

    float o[8][4];
    #pragma unroll
    for (int j = 0; j < 8; j++)
        #pragma unroll
        for (int e = 0; e < 4; e++) o[j][e] = 0.0f;
    float mrow[2] = {-1e30f, -1e30f};
    float lrow[2] = {0.0f, 0.0f};

    const uint32_t qrow = w * 16 + (lane & 15);
    const uint32_t qc   = lane >> 4;
    const uint32_t qoff = qrow * 128;
    const uint32_t qxr  = qrow & 7;
    const uint32_t brow = ((lane >> 4) << 3) + (lane & 7);
    const uint32_t bc   = (lane >> 3) & 1;
    const uint32_t bxr  = brow & 7;

    for (int i = 0; i < NKV; i++) {
        if (i < NKV - 1) {
            int buf = (i + 1) & 1;
            int kb = (i + 1) * 64;
            #pragma unroll
            for (int p = 0; p < 2; p++) {
                int id = tid + p * 256;
                int r = id >> 3, c = id & 7;
                uint32_t so = SW(r, c);
                cp16(sbase + SM_BUF(buf) + SM_KHI + so, kh_g + (size_t)(kb + r) * DK + c * 8);
                cp16(sbase + SM_BUF(buf) + SM_VHI + so, vh_g + (size_t)r * NN + kb + c * 8);
            }
            cp_commit();
            cp_wait<1>();
        } else {
            cp_wait<0>();
        }
        __syncthreads();

        const uint32_t kbuf = sbase + SM_BUF(i & 1);

        float s[8][4];
        #pragma unroll
        for (int j = 0; j < 8; j++)
            #pragma unroll
            for (int e = 0; e < 4; e++) s[j][e] = 0.0f;

        #pragma unroll
        for (int ks = 0; ks < 4; ks++) {
            uint32_t qh[4];
            uint32_t qcc = 2 * ks + qc;
            ldsm_x4(qh[0], qh[1], qh[2], qh[3], sbase + SM_QHI + qoff + ((qcc ^ qxr) << 4));
            uint32_t bcc = 2 * ks + bc;
            #pragma unroll
            for (int jp = 0; jp < 4; jp++) {
                uint32_t row = 16 * jp + brow;
                uint32_t off = row * 128 + ((bcc ^ bxr) << 4);
                uint32_t kh0, kh1, kh2, kh3;
                ldsm_x4(kh0, kh1, kh2, kh3, kbuf + SM_KHI + off);
                mma16816(s[2 * jp],     qh, kh0, kh1);
                mma16816(s[2 * jp + 1], qh, kh2, kh3);
            }
        }

        // online softmax; p rounded to fp16 BEFORE accumulating denominator
        #pragma unroll
        for (int hh = 0; hh < 2; hh++) {
            float mx = -1e30f;
            #pragma unroll
            for (int j = 0; j < 8; j++)
                mx = fmaxf(mx, fmaxf(s[j][2 * hh], s[j][2 * hh + 1]));
            mx = fmaxf(mx, __shfl_xor_sync(0xffffffffu, mx, 1));
            mx = fmaxf(mx, __shfl_xor_sync(0xffffffffu, mx, 2));
            float mNew = fmaxf(mrow[hh], mx);
            float corr = exp2f(mrow[hh] - mNew);
            float rs = 0.0f;
            #pragma unroll
            for (int j = 0; j < 8; j++) {
                float p0 = rnd_h(exp2f(s[j][2 * hh]     - mNew));
                float p1 = rnd_h(exp2f(s[j][2 * hh + 1] - mNew));
                s[j][2 * hh]     = p0;
                s[j][2 * hh + 1] = p1;
                rs += p0 + p1;
            }
            rs += __shfl_xor_sync(0xffffffffu, rs, 1);
            rs += __shfl_xor_sync(0xffffffffu, rs, 2);
            lrow[hh] = lrow[hh] * corr + rs;
            mrow[hh] = mNew;
            #pragma unroll
            for (int j = 0; j < 8; j++) {
                o[j][2 * hh]     *= corr;
                o[j][2 * hh + 1] *= corr;
            }
        }

        // O += P @ V : single-limb P x single-limb V
        #pragma unroll
        for (int ks = 0; ks < 4; ks++) {
            uint32_t ph[4];
            ph[0] = packh(s[2 * ks][0],     s[2 * ks][1]);
            ph[1] = packh(s[2 * ks][2],     s[2 * ks][3]);
            ph[2] = packh(s[2 * ks + 1][0], s[2 * ks + 1][1]);
            ph[3] = packh(s[2 * ks + 1][2], s[2 * ks + 1][3]);
            uint32_t bcc = 2 * ks + bc;
            #pragma unroll
            for (int jp = 0; jp < 4; jp++) {
                uint32_t row = 16 * jp + brow;
                uint32_t off = row * 128 + ((bcc ^ bxr) << 4);
                uint32_t vh0, vh1, vh2, vh3;
                ldsm_x4(vh0, vh1, vh2, vh3, kbuf + SM_VHI + off);
                mma16816(o[2 * jp],     ph, vh0, vh1);
                mma16816(o[2 * jp + 1], ph, vh2, vh3);
            }
        }
        __syncthreads();
    }

    const int b_ = bh >> 3;
    const int h  = bh & 7;
    const int c0 = (lane & 3) * 2;
    const float i0 = 1.0f / lrow[0];
    const float i1 = 1.0f / lrow[1];
    const int ra = m0 + w * 16 + rq;
    #pragma unroll
    for (int j = 0; j < 8; j++) {
        int col = 8 * j + c0;
        uint32_t h0, l0, h1, l1;
        split2(o[j][0] * i0, o[j][1] * i0, h0, l0);
        split2(o[j][2] * i1, o[j][3] * i1, h1, l1);
        size_t off0 = ((size_t)(b_ * NN + ra)) * D_MODEL + h * DK + col;
        size_t off1 = ((size_t)(b_ * NN + ra + 8)) * D_MODEL + h * DK + col;
        *reinterpret_cast<uint32_t*>(&g_ah[off0]) = h0;
        *reinterpret_cast<uint32_t*>(&g_al[off0]) = l0;
        *reinterpret_cast<uint32_t*>(&g_ah[off1]) = h1;
        *reinterpret_cast<uint32_t*>(&g_al[off1]) = l1;
    }
}

// ---------------------------------------------------------------------------
extern "C" void kernel_launch(void* const* d_in, const int* in_sizes, int n_in,
                              void* d_out, int out_size)
{
    (void)in_sizes; (void)n_in; (void)out_size;
    const float* x  = (const float*)d_in[0];
    const float* Wq = (const float*)d_in[1];
    const float* bq = (const float*)d_in[2];
    const float* Wk = (const float*)d_in[3];
    const float* bk = (const float*)d_in[4];
    const float* Wv = (const float*)d_in[5];
    const float* bv = (const float*)d_in[6];
    const float* Wo = (const float*)d_in[7];
    const float* bo = (const float*)d_in[8];

    void *xh, *xl, *wth, *ah, *al;
    cudaGetSymbolAddress(&xh, g_xh);
    cudaGetSymbolAddress(&xl, g_xl);
    cudaGetSymbolAddress(&wth, g_wth);
    cudaGetSymbolAddress(&ah, g_ah);
    cudaGetSymbolAddress(&al, g_al);

    __half* whp = (__half*)wth;

    cudaFuncSetAttribute(attn_tc, cudaFuncAttributeMaxDynamicSharedMemorySize, ATTN_SMEM);
    cudaFuncSetAttribute(gemm_raw, cudaFuncAttributeMaxDynamicSharedMemorySize, GEMM_SMEM);

    // single fused prep launch
    prep_all<<<NXB + 1024, 256>>>(x, Wq, Wk, Wv, Wo);

    // fused QKV projection: grid (24, 64)
    dim3 qkv_grid(24, M_TOTAL / 128);
    gemm_raw<<<qkv_grid, 256, GEMM_SMEM>>>((const __half*)xh, (const __half*)xl,
                                           whp, bq, bk, bv, nullptr, nullptr, 1);

    dim3 attn_grid(NN / 128, BH);   // (16, 32)
    attn_tc<<<attn_grid, 256, ATTN_SMEM>>>();

    // O projection: grid (8, 64)
    dim3 o_grid(8, M_TOTAL / 128);
    gemm_raw<<<o_grid, 256, GEMM_SMEM>>>((const __half*)ah, (const __half*)al,
                                         whp, nullptr, nullptr, nullptr, bo, (float*)d_out, 0);
}

// round 16
// speedup vs baseline: 2.7557x; 1.1677x over previous
#include <cuda_runtime.h>
#include <cuda_fp16.h>
#include <math.h>
#include <stdint.h>

#define D_MODEL 512
#define NHEAD   8
#define DK      64
#define BB      4
#define NN      2048
#define M_TOTAL (BB * NN)     // 8192
#define BH      (BB * NHEAD)  // 32
#define NKV     (NN / 64)     // 32 kv blocks
#define WSZ     (D_MODEL * D_MODEL)

// Q pre-scale: 1/sqrt(64) * log2(e)
#define SC_ATTN 0.18033688f

// ---------------- scratch (allocation-free static device arrays) -----------
__device__ __align__(128) __half g_xh[M_TOTAL * D_MODEL];     // x, single fp16 limb
__device__ __align__(128) __half g_wth[4 * WSZ];              // W^T [n][k], 1 limb
__device__ __align__(128) __half g_qh[BH * NN * DK];          // 1 limb (pre-scaled)
__device__ __align__(128) __half g_kh[BH * NN * DK];          // 1 limb
__device__ __align__(128) __half g_vth[BH * DK * NN];         // [bh][d][n], 1 limb
__device__ __align__(128) __half g_ah[M_TOTAL * D_MODEL];     // attn out split hi
__device__ __align__(128) __half g_al[M_TOTAL * D_MODEL];     // attn out split lo

// ---------------------------------------------------------------------------
// helpers
// ---------------------------------------------------------------------------
__device__ __forceinline__ uint32_t packh(float x, float y) {
    __half2 t = __floats2half2_rn(x, y);
    return *reinterpret_cast<uint32_t*>(&t);
}
__device__ __forceinline__ void split2(float x, float y, uint32_t& hi, uint32_t& lo) {
    float hx = __half2float(__float2half_rn(x));
    float hy = __half2float(__float2half_rn(y));
    hi = packh(hx, hy);
    lo = packh(x - hx, y - hy);
}
__device__ __forceinline__ uint32_t ex2h2(float a, float b) {
    uint32_t in = packh(a, b), r;
    asm volatile("ex2.approx.f16x2 %0, %1;" : "=r"(r) : "r"(in));
    return r;
}
__device__ __forceinline__ float2 h22f2(uint32_t p) {
    return __half22float2(*reinterpret_cast<__half2*>(&p));
}
__device__ __forceinline__ void mma16816(float* c, const uint32_t* a, uint32_t b0, uint32_t b1) {
    asm volatile(
        "mma.sync.aligned.m16n8k16.row.col.f32.f16.f16.f32 "
        "{%0,%1,%2,%3}, {%4,%5,%6,%7}, {%8,%9}, {%0,%1,%2,%3};\n"
        : "+f"(c[0]), "+f"(c[1]), "+f"(c[2]), "+f"(c[3])
        : "r"(a[0]), "r"(a[1]), "r"(a[2]), "r"(a[3]), "r"(b0), "r"(b1));
}
__device__ __forceinline__ void ldsm_x4(uint32_t& d0, uint32_t& d1, uint32_t& d2, uint32_t& d3,
                                        uint32_t saddr) {
    asm volatile("ldmatrix.sync.aligned.m8n8.x4.shared.b16 {%0,%1,%2,%3}, [%4];"
                 : "=r"(d0), "=r"(d1), "=r"(d2), "=r"(d3) : "r"(saddr));
}
__device__ __forceinline__ void cp16(uint32_t dst, const void* src) {
    asm volatile("cp.async.cg.shared.global [%0], [%1], 16;" :: "r"(dst), "l"(src));
}
__device__ __forceinline__ void cp_commit() { asm volatile("cp.async.commit_group;"); }
template<int N> __device__ __forceinline__ void cp_wait() {
    asm volatile("cp.async.wait_group %0;" :: "n"(N));
}
__device__ __forceinline__ uint32_t SW(uint32_t r, uint32_t c) {
    return r * 128u + ((c ^ (r & 7u)) << 4);
}

// ---------------------------------------------------------------------------
// fused prep: x -> fp16 (single limb) + 4x weight transpose (single limb).
// ---------------------------------------------------------------------------
#define NXB ((M_TOTAL * D_MODEL / 4) / 256)   // 4096

__global__ void __launch_bounds__(256)
prep_all(const float* __restrict__ x,
         const float* __restrict__ W0, const float* __restrict__ W1,
         const float* __restrict__ W2, const float* __restrict__ W3)
{
    const int bid = blockIdx.x;
    if (bid < NXB) {
        int i = bid * 256 + threadIdx.x;
        float4 v = reinterpret_cast<const float4*>(x)[i];
        reinterpret_cast<uint2*>(g_xh)[i] = make_uint2(packh(v.x, v.y), packh(v.z, v.w));
        return;
    }
    __shared__ float ts[32][33];
    const int t   = bid - NXB;
    const int mat = t >> 8;
    const int blk = t & 255;
    const float* W = (mat == 0) ? W0 : (mat == 1) ? W1 : (mat == 2) ? W2 : W3;
    __half* th = g_wth + (size_t)mat * WSZ;
    int n0 = (blk & 15) * 32, k0 = (blk >> 4) * 32;
    int tx = threadIdx.x & 31, ty = threadIdx.x >> 5;
    #pragma unroll
    for (int j = 0; j < 4; j++)
        ts[ty + j * 8][tx] = W[(size_t)(k0 + ty + j * 8) * D_MODEL + n0 + tx];
    __syncthreads();
    #pragma unroll
    for (int j = 0; j < 4; j++) {
        int n = ty + j * 8;
        th[(size_t)(n0 + n) * D_MODEL + k0 + tx] = __float2half_rn(ts[tx][n]);
    }
}

// ---------------------------------------------------------------------------
// Raw-mma GEMM, templated on A limb count.
// ALIMBS=1 (QKV): A = g_xh only, 1 MMA per fragment pair.
// ALIMBS=2 (O-proj): A = (g_ah, g_al), 2 MMAs.
// CTA tile 128x64, BK=64, 256 thr / 8 warps, cp.async double-buffered.
// ---------------------------------------------------------------------------
template<int ALIMBS>
__global__ void __launch_bounds__(256, 2)
gemm_raw(const __half* __restrict__ Ah, const __half* __restrict__ Al,
         const __half* __restrict__ Bh,
         const float* __restrict__ bias_q, const float* __restrict__ bias_k,
         const float* __restrict__ bias_v, const float* __restrict__ bias_o,
         float* __restrict__ outf, int fused)
{
    constexpr uint32_t GS_AHI = 0;
    constexpr uint32_t GS_ALO = 16384;                       // used iff ALIMBS==2
    constexpr uint32_t GS_BHI = (ALIMBS == 2) ? 32768 : 16384;
    constexpr uint32_t GS_STAGE = GS_BHI + 8192;

    extern __shared__ __align__(128) unsigned char sm[];
    const uint32_t sbase = (uint32_t)__cvta_generic_to_shared(sm);

    const int tid  = threadIdx.x;
    const int lane = tid & 31;
    const int w    = tid >> 5;
    const int rq   = lane >> 2;
    const int cb   = blockIdx.x;
    const int m0   = blockIdx.y * 128;

    const int wsel  = fused ? (cb >> 3) : 3;
    const int n_in  = (cb & 7) * 64;
    const size_t brow0 = (size_t)wsel * D_MODEL + n_in;

    auto load_chunk = [&](int kc, int buf) {
        uint32_t base = sbase + buf * GS_STAGE;
        int kb = kc * 64;
        #pragma unroll
        for (int t = 0; t < 4; t++) {
            int id = tid + t * 256;
            int r = id >> 3, c = id & 7;
            uint32_t so = SW(r, c);
            size_t g = (size_t)(m0 + r) * D_MODEL + kb + c * 8;
            cp16(base + GS_AHI + so, Ah + g);
            if (ALIMBS == 2) cp16(base + GS_ALO + so, Al + g);
        }
        #pragma unroll
        for (int t = 0; t < 2; t++) {
            int id = tid + t * 256;
            int r = id >> 3, c = id & 7;
            uint32_t so = SW(r, c);
            size_t g = (brow0 + r) * D_MODEL + kb + c * 8;
            cp16(base + GS_BHI + so, Bh + g);
        }
        cp_commit();
    };

    float s[8][4];
    #pragma unroll
    for (int j = 0; j < 8; j++)
        #pragma unroll
        for (int e = 0; e < 4; e++) s[j][e] = 0.0f;

    const uint32_t qrow = w * 16 + (lane & 15);
    const uint32_t qc   = lane >> 4;
    const uint32_t qoff = qrow * 128;
    const uint32_t qxr  = qrow & 7;
    const uint32_t brow = ((lane >> 4) << 3) + (lane & 7);
    const uint32_t bc   = (lane >> 3) & 1;
    const uint32_t bxr  = brow & 7;

    load_chunk(0, 0);
    load_chunk(1, 1);

    for (int i = 0; i < 8; i++) {
        if (i == 7) cp_wait<0>(); else cp_wait<1>();
        __syncthreads();
        const uint32_t abuf = sbase + (i & 1) * GS_STAGE;

        #pragma unroll
        for (int ks = 0; ks < 4; ks++) {
            uint32_t ah[4], al[4];
            uint32_t qcc = 2 * ks + qc;
            ldsm_x4(ah[0], ah[1], ah[2], ah[3], abuf + GS_AHI + qoff + ((qcc ^ qxr) << 4));
            if (ALIMBS == 2)
                ldsm_x4(al[0], al[1], al[2], al[3], abuf + GS_ALO + qoff + ((qcc ^ qxr) << 4));
            uint32_t bcc = 2 * ks + bc;
            #pragma unroll
            for (int jp = 0; jp < 4; jp++) {
                uint32_t row = 16 * jp + brow;
                uint32_t off = row * 128 + ((bcc ^ bxr) << 4);
                uint32_t bh0, bh1, bh2, bh3;
                ldsm_x4(bh0, bh1, bh2, bh3, abuf + GS_BHI + off);
                mma16816(s[2 * jp],     ah, bh0, bh1);
                mma16816(s[2 * jp + 1], ah, bh2, bh3);
                if (ALIMBS == 2) {
                    mma16816(s[2 * jp],     al, bh0, bh1);
                    mma16816(s[2 * jp + 1], al, bh2, bh3);
                }
            }
        }
        __syncthreads();
        if (i + 2 < 8) load_chunk(i + 2, i & 1);
    }

    float* Cst = (float*)sm;
    {
        const int c0 = (lane & 3) * 2;
        const int ra = w * 16 + rq;
        #pragma unroll
        for (int j = 0; j < 8; j++) {
            int col = 8 * j + c0;
            Cst[ra * 68 + col]           = s[j][0];
            Cst[ra * 68 + col + 1]       = s[j][1];
            Cst[(ra + 8) * 68 + col]     = s[j][2];
            Cst[(ra + 8) * 68 + col + 1] = s[j][3];
        }
    }
    __syncthreads();

    if (!fused) {
        const int orow = tid >> 4;
        const int ocol = (tid & 15) * 4;
        float4 b4 = *reinterpret_cast<const float4*>(&bias_o[n_in + ocol]);
        #pragma unroll
        for (int t = 0; t < 8; t++) {
            int r = orow + t * 16;
            float4 v = *reinterpret_cast<const float4*>(&Cst[r * 68 + ocol]);
            v.x += b4.x; v.y += b4.y; v.z += b4.z; v.w += b4.w;
            *reinterpret_cast<float4*>(&outf[(size_t)(m0 + r) * D_MODEL + n_in + ocol]) = v;
        }
    } else if (wsel < 2) {
        // Q / K: single fp16 limb (Q scaled by SC_ATTN)
        const float scale = (wsel == 0) ? SC_ATTN : 1.0f;
        __half* ohi = (wsel == 0) ? g_qh : g_kh;
        const float* bias = (wsel == 0) ? bias_q : bias_k;
        const int h = cb & 7;
        const int orow = tid >> 4;
        const int ocol = (tid & 15) * 4;
        float4 b4 = *reinterpret_cast<const float4*>(&bias[n_in + ocol]);
        #pragma unroll
        for (int t = 0; t < 8; t++) {
            int r  = orow + t * 16;
            int rg = m0 + r;
            int b_ = rg >> 11;
            int n_ = rg & 2047;
            float4 v = *reinterpret_cast<const float4*>(&Cst[r * 68 + ocol]);
            uint32_t h01 = packh((v.x + b4.x) * scale, (v.y + b4.y) * scale);
            uint32_t h23 = packh((v.z + b4.z) * scale, (v.w + b4.w) * scale);
            size_t off = ((size_t)(b_ * NHEAD + h) * NN + n_) * DK + ocol;
            *reinterpret_cast<uint2*>(&ohi[off]) = make_uint2(h01, h23);
        }
    } else {
        // V transposed, single fp16 limb [bh][d][n]
        const int h   = cb & 7;
        const int od  = tid >> 2;
        const int on0 = (tid & 3) * 32;
        const int b_  = m0 >> 11;
        const int nb  = (m0 & 2047) + on0;
        const float bv = bias_v[n_in + od];
        size_t rowoff = ((size_t)(b_ * NHEAD + h) * DK + od) * NN + nb;
        #pragma unroll
        for (int i = 0; i < 32; i += 2) {
            float v0 = Cst[(on0 + i) * 68 + od] + bv;
            float v1 = Cst[(on0 + i + 1) * 68 + od] + bv;
            *reinterpret_cast<uint32_t*>(&g_vth[rowoff + i]) = packh(v0, v1);
        }
    }
}

#define GEMM_SMEM_1 (2 * (16384 + 8192 + 8192))   // 2 * 32768... see template: stage=24576 -> 49152
#define GEMM_SMEM_QKV (2 * 24576)   // 49152
#define GEMM_SMEM_O   (2 * 40960)   // 81920

// ---------------------------------------------------------------------------
// Flash attention: BM=128, BN=64, d=64, 256 thr, 2 CTAs/SM.
// S: 1-limb Q x 1-limb K. Softmax via ex2.approx.f16x2 (p is fp16 directly).
// PV: fp16 P (from ex2) x 1-limb V.
// ---------------------------------------------------------------------------
#define SM_QHI 0
#define SM_BUF(b) (16384 + (b) * 16384)
#define SM_KHI 0
#define SM_VHI 8192
#define ATTN_SMEM (16384 + 2 * 16384)   // 48 KB

__global__ void __launch_bounds__(256, 2)
attn_tc()
{
    extern __shared__ __align__(128) unsigned char sm[];
    const uint32_t sbase = (uint32_t)__cvta_generic_to_shared(sm);

    const int tid  = threadIdx.x;
    const int lane = tid & 31;
    const int w    = tid >> 5;
    const int rq   = lane >> 2;
    const int bh   = blockIdx.y;
    const int m0   = blockIdx.x * 128;

    const __half* qh_g = g_qh + (size_t)bh * NN * DK;
    const __half* kh_g = g_kh + (size_t)bh * NN * DK;
    const __half* vh_g = g_vth + (size_t)bh * DK * NN;

    {
        #pragma unroll
        for (int p = 0; p < 4; p++) {
            int id = tid + p * 256;
            int r = id >> 3, c = id & 7;
            size_t go = (size_t)(m0 + r) * DK + c * 8;
            cp16(sbase + SM_QHI + SW(r, c), qh_g + go);
        }
        cp_commit();
    }
    {
        #pragma unroll
        for (int p = 0; p < 2; p++) {
            int id = tid + p * 256;
            int r = id >> 3, c = id & 7;
            uint32_t so = SW(r, c);
            cp16(sbase + SM_BUF(0) + SM_KHI + so, kh_g + (size_t)r * DK + c * 8);
            cp16(sbase + SM_BUF(0) + SM_VHI + so, vh_g + (size_t)r * NN + c * 8);
        }
        cp_commit();
    }

    float o[8][4];
    #pragma unroll
    for (int j = 0; j < 8; j++)
        #pragma unroll
        for (int e = 0; e < 4; e++) o[j][e] = 0.0f;
    float mrow[2] = {-1e30f, -1e30f};
    float lrow[2] = {0.0f, 0.0f};

    const uint32_t qrow = w * 16 + (lane & 15);
    const uint32_t qc   = lane >> 4;
    const uint32_t qoff = qrow * 128;
    const uint32_t qxr  = qrow & 7;
    const uint32_t brow = ((lane >> 4) << 3) + (lane & 7);
    const uint32_t bc   = (lane >> 3) & 1;
    const uint32_t bxr  = brow & 7;

    for (int i = 0; i < NKV; i++) {
        if (i < NKV - 1) {
            int buf = (i + 1) & 1;
            int kb = (i + 1) * 64;
            #pragma unroll
            for (int p = 0; p < 2; p++) {
                int id = tid + p * 256;
                int r = id >> 3, c = id & 7;
                uint32_t so = SW(r, c);
                cp16(sbase + SM_BUF(buf) + SM_KHI + so, kh_g + (size_t)(kb + r) * DK + c * 8);
                cp16(sbase + SM_BUF(buf) + SM_VHI + so, vh_g + (size_t)r * NN + kb + c * 8);
            }
            cp_commit();
            cp_wait<1>();
        } else {
            cp_wait<0>();
        }
        __syncthreads();

        const uint32_t kbuf = sbase + SM_BUF(i & 1);

        float s[8][4];
        #pragma unroll
        for (int j = 0; j < 8; j++)
            #pragma unroll
            for (int e = 0; e < 4; e++) s[j][e] = 0.0f;

        #pragma unroll
        for (int ks = 0; ks < 4; ks++) {
            uint32_t qh[4];
            uint32_t qcc = 2 * ks + qc;
            ldsm_x4(qh[0], qh[1], qh[2], qh[3], sbase + SM_QHI + qoff + ((qcc ^ qxr) << 4));
            uint32_t bcc = 2 * ks + bc;
            #pragma unroll
            for (int jp = 0; jp < 4; jp++) {
                uint32_t row = 16 * jp + brow;
                uint32_t off = row * 128 + ((bcc ^ bxr) << 4);
                uint32_t kh0, kh1, kh2, kh3;
                ldsm_x4(kh0, kh1, kh2, kh3, kbuf + SM_KHI + off);
                mma16816(s[2 * jp],     qh, kh0, kh1);
                mma16816(s[2 * jp + 1], qh, kh2, kh3);
            }
        }

        // ---- online softmax stats (fp32) ----
        float mNew[2], corr[2];
        #pragma unroll
        for (int hh = 0; hh < 2; hh++) {
            float mx = -1e30f;
            #pragma unroll
            for (int j = 0; j < 8; j++)
                mx = fmaxf(mx, fmaxf(s[j][2 * hh], s[j][2 * hh + 1]));
            mx = fmaxf(mx, __shfl_xor_sync(0xffffffffu, mx, 1));
            mx = fmaxf(mx, __shfl_xor_sync(0xffffffffu, mx, 2));
            mNew[hh] = fmaxf(mrow[hh], mx);
            corr[hh] = exp2f(mrow[hh] - mNew[hh]);
        }

        // ---- p = exp2(s - m) via f16x2 MUFU; results ARE the MMA fragments ----
        uint32_t sp[8][2];
        float rs0 = 0.0f, rs1 = 0.0f;
        #pragma unroll
        for (int j = 0; j < 8; j++) {
            uint32_t p01 = ex2h2(s[j][0] - mNew[0], s[j][1] - mNew[0]);
            uint32_t p23 = ex2h2(s[j][2] - mNew[1], s[j][3] - mNew[1]);
            sp[j][0] = p01;
            sp[j][1] = p23;
            float2 f01 = h22f2(p01);
            float2 f23 = h22f2(p23);
            rs0 += f01.x + f01.y;
            rs1 += f23.x + f23.y;
        }
        rs0 += __shfl_xor_sync(0xffffffffu, rs0, 1);
        rs0 += __shfl_xor_sync(0xffffffffu, rs0, 2);
        rs1 += __shfl_xor_sync(0xffffffffu, rs1, 1);
        rs1 += __shfl_xor_sync(0xffffffffu, rs1, 2);
        lrow[0] = lrow[0] * corr[0] + rs0;
        lrow[1] = lrow[1] * corr[1] + rs1;
        mrow[0] = mNew[0];
        mrow[1] = mNew[1];
        #pragma unroll
        for (int j = 0; j < 8; j++) {
            o[j][0] *= corr[0];
            o[j][1] *= corr[0];
            o[j][2] *= corr[1];
            o[j][3] *= corr[1];
        }

        // ---- O += P @ V ----
        #pragma unroll
        for (int ks = 0; ks < 4; ks++) {
            uint32_t ph[4];
            ph[0] = sp[2 * ks][0];
            ph[1] = sp[2 * ks][1];
            ph[2] = sp[2 * ks + 1][0];
            ph[3] = sp[2 * ks + 1][1];
            uint32_t bcc = 2 * ks + bc;
            #pragma unroll
            for (int jp = 0; jp < 4; jp++) {
                uint32_t row = 16 * jp + brow;
                uint32_t off = row * 128 + ((bcc ^ bxr) << 4);
                uint32_t vh0, vh1, vh2, vh3;
                ldsm_x4(vh0, vh1, vh2, vh3, kbuf + SM_VHI + off);
                mma16816(o[2 * jp],     ph, vh0, vh1);
                mma16816(o[2 * jp + 1], ph, vh2, vh3);
            }
        }
        __syncthreads();
    }

    const int b_ = bh >> 3;
    const int h  = bh & 7;
    const int c0 = (lane & 3) * 2;
    const float i0 = 1.0f / lrow[0];
    const float i1 = 1.0f / lrow[1];
    const int ra = m0 + w * 16 + rq;
    #pragma unroll
    for (int j = 0; j < 8; j++) {
        int col = 8 * j + c0;
        uint32_t h0, l0, h1, l1;
        split2(o[j][0] * i0, o[j][1] * i0, h0, l0);
        split2(o[j][2] * i1, o[j][3] * i1, h1, l1);
        size_t off0 = ((size_t)(b_ * NN + ra)) * D_MODEL + h * DK + col;
        size_t off1 = ((size_t)(b_ * NN + ra + 8)) * D_MODEL + h * DK + col;
        *reinterpret_cast<uint32_t*>(&g_ah[off0]) = h0;
        *reinterpret_cast<uint32_t*>(&g_al[off0]) = l0;
        *reinterpret_cast<uint32_t*>(&g_ah[off1]) = h1;
        *reinterpret_cast<uint32_t*>(&g_al[off1]) = l1;
    }
}

// ---------------------------------------------------------------------------
extern "C" void kernel_launch(void* const* d_in, const int* in_sizes, int n_in,
                              void* d_out, int out_size)
{
    (void)in_sizes; (void)n_in; (void)out_size;
    const float* x  = (const float*)d_in[0];
    const float* Wq = (const float*)d_in[1];
    const float* bq = (const float*)d_in[2];
    const float* Wk = (const float*)d_in[3];
    const float* bk = (const float*)d_in[4];
    const float* Wv = (const float*)d_in[5];
    const float* bv = (const float*)d_in[6];
    const float* Wo = (const float*)d_in[7];
    const float* bo = (const float*)d_in[8];

    void *xh, *wth, *ah, *al;
    cudaGetSymbolAddress(&xh, g_xh);
    cudaGetSymbolAddress(&wth, g_wth);
    cudaGetSymbolAddress(&ah, g_ah);
    cudaGetSymbolAddress(&al, g_al);

    __half* whp = (__half*)wth;

    cudaFuncSetAttribute(attn_tc, cudaFuncAttributeMaxDynamicSharedMemorySize, ATTN_SMEM);
    cudaFuncSetAttribute(gemm_raw<1>, cudaFuncAttributeMaxDynamicSharedMemorySize, GEMM_SMEM_QKV);
    cudaFuncSetAttribute(gemm_raw<2>, cudaFuncAttributeMaxDynamicSharedMemorySize, GEMM_SMEM_O);

    // single fused prep launch
    prep_all<<<NXB + 1024, 256>>>(x, Wq, Wk, Wv, Wo);

    // fused QKV projection (1-limb A): grid (24, 64)
    dim3 qkv_grid(24, M_TOTAL / 128);
    gemm_raw<1><<<qkv_grid, 256, GEMM_SMEM_QKV>>>((const __half*)xh, nullptr,
                                                  whp, bq, bk, bv, nullptr, nullptr, 1);

    dim3 attn_grid(NN / 128, BH);   // (16, 32)
    attn_tc<<<attn_grid, 256, ATTN_SMEM>>>();

    // O projection (2-limb A): grid (8, 64)
    dim3 o_grid(8, M_TOTAL / 128);
    gemm_raw<2><<<o_grid, 256, GEMM_SMEM_O>>>((const __half*)ah, (const __half*)al,
                                              whp, nullptr, nullptr, nullptr, bo, (float*)d_out, 0);
}

// round 17
// speedup vs baseline: 2.8758x; 1.0436x over previous
#include <cuda_runtime.h>
#include <cuda_fp16.h>
#include <math.h>
#include <stdint.h>

#define D_MODEL 512
#define NHEAD   8
#define DK      64
#define BB      4
#define NN      2048
#define M_TOTAL (BB * NN)     // 8192
#define BH      (BB * NHEAD)  // 32
#define NKV     (NN / 64)     // 32 kv blocks
#define WSZ     (D_MODEL * D_MODEL)

// Q pre-scale: 1/sqrt(64) * log2(e)
#define SC_ATTN 0.18033688f

// ---------------- scratch (allocation-free static device arrays) -----------
__device__ __align__(128) __half g_xh[M_TOTAL * D_MODEL];     // x, single fp16 limb
__device__ __align__(128) __half g_wth[4 * WSZ];              // W^T [n][k], 1 limb
__device__ __align__(128) __half g_qh[BH * NN * DK];          // 1 limb (pre-scaled)
__device__ __align__(128) __half g_kh[BH * NN * DK];          // 1 limb
__device__ __align__(128) __half g_vth[BH * DK * NN];         // [bh][d][n], 1 limb
__device__ __align__(128) __half g_ah[M_TOTAL * D_MODEL];     // attn out, 1 limb

// ---------------------------------------------------------------------------
// helpers
// ---------------------------------------------------------------------------
__device__ __forceinline__ uint32_t packh(float x, float y) {
    __half2 t = __floats2half2_rn(x, y);
    return *reinterpret_cast<uint32_t*>(&t);
}
__device__ __forceinline__ uint32_t ex2h2(float a, float b) {
    uint32_t in = packh(a, b), r;
    asm volatile("ex2.approx.f16x2 %0, %1;" : "=r"(r) : "r"(in));
    return r;
}
__device__ __forceinline__ float2 h22f2(uint32_t p) {
    return __half22float2(*reinterpret_cast<__half2*>(&p));
}
__device__ __forceinline__ void mma16816(float* c, const uint32_t* a, uint32_t b0, uint32_t b1) {
    asm volatile(
        "mma.sync.aligned.m16n8k16.row.col.f32.f16.f16.f32 "
        "{%0,%1,%2,%3}, {%4,%5,%6,%7}, {%8,%9}, {%0,%1,%2,%3};\n"
        : "+f"(c[0]), "+f"(c[1]), "+f"(c[2]), "+f"(c[3])
        : "r"(a[0]), "r"(a[1]), "r"(a[2]), "r"(a[3]), "r"(b0), "r"(b1));
}
__device__ __forceinline__ void ldsm_x4(uint32_t& d0, uint32_t& d1, uint32_t& d2, uint32_t& d3,
                                        uint32_t saddr) {
    asm volatile("ldmatrix.sync.aligned.m8n8.x4.shared.b16 {%0,%1,%2,%3}, [%4];"
                 : "=r"(d0), "=r"(d1), "=r"(d2), "=r"(d3) : "r"(saddr));
}
__device__ __forceinline__ void cp16(uint32_t dst, const void* src) {
    asm volatile("cp.async.cg.shared.global [%0], [%1], 16;" :: "r"(dst), "l"(src));
}
__device__ __forceinline__ void cp_commit() { asm volatile("cp.async.commit_group;"); }
template<int N> __device__ __forceinline__ void cp_wait() {
    asm volatile("cp.async.wait_group %0;" :: "n"(N));
}
__device__ __forceinline__ uint32_t SW(uint32_t r, uint32_t c) {
    return r * 128u + ((c ^ (r & 7u)) << 4);
}

// ---------------------------------------------------------------------------
// fused prep: x -> fp16 (single limb) + 4x weight transpose (single limb).
// ---------------------------------------------------------------------------
#define NXB ((M_TOTAL * D_MODEL / 4) / 256)   // 4096

__global__ void __launch_bounds__(256)
prep_all(const float* __restrict__ x,
         const float* __restrict__ W0, const float* __restrict__ W1,
         const float* __restrict__ W2, const float* __restrict__ W3)
{
    const int bid = blockIdx.x;
    if (bid < NXB) {
        int i = bid * 256 + threadIdx.x;
        float4 v = reinterpret_cast<const float4*>(x)[i];
        reinterpret_cast<uint2*>(g_xh)[i] = make_uint2(packh(v.x, v.y), packh(v.z, v.w));
        return;
    }
    __shared__ float ts[32][33];
    const int t   = bid - NXB;
    const int mat = t >> 8;
    const int blk = t & 255;
    const float* W = (mat == 0) ? W0 : (mat == 1) ? W1 : (mat == 2) ? W2 : W3;
    __half* th = g_wth + (size_t)mat * WSZ;
    int n0 = (blk & 15) * 32, k0 = (blk >> 4) * 32;
    int tx = threadIdx.x & 31, ty = threadIdx.x >> 5;
    #pragma unroll
    for (int j = 0; j < 4; j++)
        ts[ty + j * 8][tx] = W[(size_t)(k0 + ty + j * 8) * D_MODEL + n0 + tx];
    __syncthreads();
    #pragma unroll
    for (int j = 0; j < 4; j++) {
        int n = ty + j * 8;
        th[(size_t)(n0 + n) * D_MODEL + k0 + tx] = __float2half_rn(ts[tx][n]);
    }
}

// ---------------------------------------------------------------------------
// Raw-mma GEMM, 1-limb A x 1-limb B. CTA tile 128x64, BK=64, 256 thr.
// fused=1: QKV (grid.x=24): Q->1-limb*SC_ATTN, K->1-limb, V->1-limb transposed.
// fused=0: O-projection (grid.x=8): fp32 out + bias_o.
// ---------------------------------------------------------------------------
#define GS_AHI 0
#define GS_BHI 16384
#define GS_STAGE 24576
#define GEMM_SMEM (2 * GS_STAGE)   // 48 KB

__global__ void __launch_bounds__(256, 2)
gemm_raw(const __half* __restrict__ Ah, const __half* __restrict__ Bh,
         const float* __restrict__ bias_q, const float* __restrict__ bias_k,
         const float* __restrict__ bias_v, const float* __restrict__ bias_o,
         float* __restrict__ outf, int fused)
{
    extern __shared__ __align__(128) unsigned char sm[];
    const uint32_t sbase = (uint32_t)__cvta_generic_to_shared(sm);

    const int tid  = threadIdx.x;
    const int lane = tid & 31;
    const int w    = tid >> 5;
    const int rq   = lane >> 2;
    const int cb   = blockIdx.x;
    const int m0   = blockIdx.y * 128;

    const int wsel  = fused ? (cb >> 3) : 3;
    const int n_in  = (cb & 7) * 64;
    const size_t brow0 = (size_t)wsel * D_MODEL + n_in;

    auto load_chunk = [&](int kc, int buf) {
        uint32_t base = sbase + buf * GS_STAGE;
        int kb = kc * 64;
        #pragma unroll
        for (int t = 0; t < 4; t++) {
            int id = tid + t * 256;
            int r = id >> 3, c = id & 7;
            cp16(base + GS_AHI + SW(r, c), Ah + (size_t)(m0 + r) * D_MODEL + kb + c * 8);
        }
        #pragma unroll
        for (int t = 0; t < 2; t++) {
            int id = tid + t * 256;
            int r = id >> 3, c = id & 7;
            cp16(base + GS_BHI + SW(r, c), Bh + (brow0 + r) * D_MODEL + kb + c * 8);
        }
        cp_commit();
    };

    float s[8][4];
    #pragma unroll
    for (int j = 0; j < 8; j++)
        #pragma unroll
        for (int e = 0; e < 4; e++) s[j][e] = 0.0f;

    const uint32_t qrow = w * 16 + (lane & 15);
    const uint32_t qc   = lane >> 4;
    const uint32_t qoff = qrow * 128;
    const uint32_t qxr  = qrow & 7;
    const uint32_t brow = ((lane >> 4) << 3) + (lane & 7);
    const uint32_t bc   = (lane >> 3) & 1;
    const uint32_t bxr  = brow & 7;

    load_chunk(0, 0);
    load_chunk(1, 1);

    for (int i = 0; i < 8; i++) {
        if (i == 7) cp_wait<0>(); else cp_wait<1>();
        __syncthreads();
        const uint32_t abuf = sbase + (i & 1) * GS_STAGE;

        #pragma unroll
        for (int ks = 0; ks < 4; ks++) {
            uint32_t ah[4];
            uint32_t qcc = 2 * ks + qc;
            ldsm_x4(ah[0], ah[1], ah[2], ah[3], abuf + GS_AHI + qoff + ((qcc ^ qxr) << 4));
            uint32_t bcc = 2 * ks + bc;
            #pragma unroll
            for (int jp = 0; jp < 4; jp++) {
                uint32_t row = 16 * jp + brow;
                uint32_t off = row * 128 + ((bcc ^ bxr) << 4);
                uint32_t bh0, bh1, bh2, bh3;
                ldsm_x4(bh0, bh1, bh2, bh3, abuf + GS_BHI + off);
                mma16816(s[2 * jp],     ah, bh0, bh1);
                mma16816(s[2 * jp + 1], ah, bh2, bh3);
            }
        }
        __syncthreads();
        if (i + 2 < 8) load_chunk(i + 2, i & 1);
    }

    float* Cst = (float*)sm;
    {
        const int c0 = (lane & 3) * 2;
        const int ra = w * 16 + rq;
        #pragma unroll
        for (int j = 0; j < 8; j++) {
            int col = 8 * j + c0;
            Cst[ra * 68 + col]           = s[j][0];
            Cst[ra * 68 + col + 1]       = s[j][1];
            Cst[(ra + 8) * 68 + col]     = s[j][2];
            Cst[(ra + 8) * 68 + col + 1] = s[j][3];
        }
    }
    __syncthreads();

    if (!fused) {
        const int orow = tid >> 4;
        const int ocol = (tid & 15) * 4;
        float4 b4 = *reinterpret_cast<const float4*>(&bias_o[n_in + ocol]);
        #pragma unroll
        for (int t = 0; t < 8; t++) {
            int r = orow + t * 16;
            float4 v = *reinterpret_cast<const float4*>(&Cst[r * 68 + ocol]);
            v.x += b4.x; v.y += b4.y; v.z += b4.z; v.w += b4.w;
            *reinterpret_cast<float4*>(&outf[(size_t)(m0 + r) * D_MODEL + n_in + ocol]) = v;
        }
    } else if (wsel < 2) {
        // Q / K: single fp16 limb (Q scaled by SC_ATTN)
        const float scale = (wsel == 0) ? SC_ATTN : 1.0f;
        __half* ohi = (wsel == 0) ? g_qh : g_kh;
        const float* bias = (wsel == 0) ? bias_q : bias_k;
        const int h = cb & 7;
        const int orow = tid >> 4;
        const int ocol = (tid & 15) * 4;
        float4 b4 = *reinterpret_cast<const float4*>(&bias[n_in + ocol]);
        #pragma unroll
        for (int t = 0; t < 8; t++) {
            int r  = orow + t * 16;
            int rg = m0 + r;
            int b_ = rg >> 11;
            int n_ = rg & 2047;
            float4 v = *reinterpret_cast<const float4*>(&Cst[r * 68 + ocol]);
            uint32_t h01 = packh((v.x + b4.x) * scale, (v.y + b4.y) * scale);
            uint32_t h23 = packh((v.z + b4.z) * scale, (v.w + b4.w) * scale);
            size_t off = ((size_t)(b_ * NHEAD + h) * NN + n_) * DK + ocol;
            *reinterpret_cast<uint2*>(&ohi[off]) = make_uint2(h01, h23);
        }
    } else {
        // V transposed, single fp16 limb [bh][d][n]
        const int h   = cb & 7;
        const int od  = tid >> 2;
        const int on0 = (tid & 3) * 32;
        const int b_  = m0 >> 11;
        const int nb  = (m0 & 2047) + on0;
        const float bv = bias_v[n_in + od];
        size_t rowoff = ((size_t)(b_ * NHEAD + h) * DK + od) * NN + nb;
        #pragma unroll
        for (int i = 0; i < 32; i += 2) {
            float v0 = Cst[(on0 + i) * 68 + od] + bv;
            float v1 = Cst[(on0 + i + 1) * 68 + od] + bv;
            *reinterpret_cast<uint32_t*>(&g_vth[rowoff + i]) = packh(v0, v1);
        }
    }
}

// ---------------------------------------------------------------------------
// Flash attention: BM=128, BN=64, d=64, 256 thr, 2 CTAs/SM.
// S: 1-limb Q x 1-limb K. Softmax via ex2.approx.f16x2 (p is fp16 directly).
// PV: fp16 P x 1-limb V. Output: single fp16 limb.
// ---------------------------------------------------------------------------
#define SM_QHI 0
#define SM_BUF(b) (16384 + (b) * 16384)
#define SM_KHI 0
#define SM_VHI 8192
#define ATTN_SMEM (16384 + 2 * 16384)   // 48 KB

__global__ void __launch_bounds__(256, 2)
attn_tc()
{
    extern __shared__ __align__(128) unsigned char sm[];
    const uint32_t sbase = (uint32_t)__cvta_generic_to_shared(sm);

    const int tid  = threadIdx.x;
    const int lane = tid & 31;
    const int w    = tid >> 5;
    const int rq   = lane >> 2;
    const int bh   = blockIdx.y;
    const int m0   = blockIdx.x * 128;

    const __half* qh_g = g_qh + (size_t)bh * NN * DK;
    const __half* kh_g = g_kh + (size_t)bh * NN * DK;
    const __half* vh_g = g_vth + (size_t)bh * DK * NN;

    {
        #pragma unroll
        for (int p = 0; p < 4; p++) {
            int id = tid + p * 256;
            int r = id >> 3, c = id & 7;
            cp16(sbase + SM_QHI + SW(r, c), qh_g + (size_t)(m0 + r) * DK + c * 8);
        }
        cp_commit();
    }
    {
        #pragma unroll
        for (int p = 0; p < 2; p++) {
            int id = tid + p * 256;
            int r = id >> 3, c = id & 7;
            uint32_t so = SW(r, c);
            cp16(sbase + SM_BUF(0) + SM_KHI + so, kh_g + (size_t)r * DK + c * 8);
            cp16(sbase + SM_BUF(0) + SM_VHI + so, vh_g + (size_t)r * NN + c * 8);
        }
        cp_commit();
    }

    float o[8][4];
    #pragma unroll
    for (int j = 0; j < 8; j++)
        #pragma unroll
        for (int e = 0; e < 4; e++) o[j][e] = 0.0f;
    float mrow[2] = {-1e30f, -1e30f};
    float lrow[2] = {0.0f, 0.0f};

    const uint32_t qrow = w * 16 + (lane & 15);
    const uint32_t qc   = lane >> 4;
    const uint32_t qoff = qrow * 128;
    const uint32_t qxr  = qrow & 7;
    const uint32_t brow = ((lane >> 4) << 3) + (lane & 7);
    const uint32_t bc   = (lane >> 3) & 1;
    const uint32_t bxr  = brow & 7;

    for (int i = 0; i < NKV; i++) {
        if (i < NKV - 1) {
            int buf = (i + 1) & 1;
            int kb = (i + 1) * 64;
            #pragma unroll
            for (int p = 0; p < 2; p++) {
                int id = tid + p * 256;
                int r = id >> 3, c = id & 7;
                uint32_t so = SW(r, c);
                cp16(sbase + SM_BUF(buf) + SM_KHI + so, kh_g + (size_t)(kb + r) * DK + c * 8);
                cp16(sbase + SM_BUF(buf) + SM_VHI + so, vh_g + (size_t)r * NN + kb + c * 8);
            }
            cp_commit();
            cp_wait<1>();
        } else {
            cp_wait<0>();
        }
        __syncthreads();

        const uint32_t kbuf = sbase + SM_BUF(i & 1);

        float s[8][4];
        #pragma unroll
        for (int j = 0; j < 8; j++)
            #pragma unroll
            for (int e = 0; e < 4; e++) s[j][e] = 0.0f;

        #pragma unroll
        for (int ks = 0; ks < 4; ks++) {
            uint32_t qh[4];
            uint32_t qcc = 2 * ks + qc;
            ldsm_x4(qh[0], qh[1], qh[2], qh[3], sbase + SM_QHI + qoff + ((qcc ^ qxr) << 4));
            uint32_t bcc = 2 * ks + bc;
            #pragma unroll
            for (int jp = 0; jp < 4; jp++) {
                uint32_t row = 16 * jp + brow;
                uint32_t off = row * 128 + ((bcc ^ bxr) << 4);
                uint32_t kh0, kh1, kh2, kh3;
                ldsm_x4(kh0, kh1, kh2, kh3, kbuf + SM_KHI + off);
                mma16816(s[2 * jp],     qh, kh0, kh1);
                mma16816(s[2 * jp + 1], qh, kh2, kh3);
            }
        }

        // ---- online softmax stats (fp32) ----
        float mNew[2], corr[2];
        #pragma unroll
        for (int hh = 0; hh < 2; hh++) {
            float mx = -1e30f;
            #pragma unroll
            for (int j = 0; j < 8; j++)
                mx = fmaxf(mx, fmaxf(s[j][2 * hh], s[j][2 * hh + 1]));
            mx = fmaxf(mx, __shfl_xor_sync(0xffffffffu, mx, 1));
            mx = fmaxf(mx, __shfl_xor_sync(0xffffffffu, mx, 2));
            mNew[hh] = fmaxf(mrow[hh], mx);
            corr[hh] = exp2f(mrow[hh] - mNew[hh]);
        }

        // ---- p = exp2(s - m) via f16x2 MUFU; results ARE the MMA fragments ----
        uint32_t sp[8][2];
        float rs0 = 0.0f, rs1 = 0.0f;
        #pragma unroll
        for (int j = 0; j < 8; j++) {
            uint32_t p01 = ex2h2(s[j][0] - mNew[0], s[j][1] - mNew[0]);
            uint32_t p23 = ex2h2(s[j][2] - mNew[1], s[j][3] - mNew[1]);
            sp[j][0] = p01;
            sp[j][1] = p23;
            float2 f01 = h22f2(p01);
            float2 f23 = h22f2(p23);
            rs0 += f01.x + f01.y;
            rs1 += f23.x + f23.y;
        }
        rs0 += __shfl_xor_sync(0xffffffffu, rs0, 1);
        rs0 += __shfl_xor_sync(0xffffffffu, rs0, 2);
        rs1 += __shfl_xor_sync(0xffffffffu, rs1, 1);
        rs1 += __shfl_xor_sync(0xffffffffu, rs1, 2);
        lrow[0] = lrow[0] * corr[0] + rs0;
        lrow[1] = lrow[1] * corr[1] + rs1;
        mrow[0] = mNew[0];
        mrow[1] = mNew[1];
        #pragma unroll
        for (int j = 0; j < 8; j++) {
            o[j][0] *= corr[0];
            o[j][1] *= corr[0];
            o[j][2] *= corr[1];
            o[j][3] *= corr[1];
        }

        // ---- O += P @ V ----
        #pragma unroll
        for (int ks = 0; ks < 4; ks++) {
            uint32_t ph[4];
            ph[0] = sp[2 * ks][0];
            ph[1] = sp[2 * ks][1];
            ph[2] = sp[2 * ks + 1][0];
            ph[3] = sp[2 * ks + 1][1];
            uint32_t bcc = 2 * ks + bc;
            #pragma unroll
            for (int jp = 0; jp < 4; jp++) {
                uint32_t row = 16 * jp + brow;
                uint32_t off = row * 128 + ((bcc ^ bxr) << 4);
                uint32_t vh0, vh1, vh2, vh3;
                ldsm_x4(vh0, vh1, vh2, vh3, kbuf + SM_VHI + off);
                mma16816(o[2 * jp],     ph, vh0, vh1);
                mma16816(o[2 * jp + 1], ph, vh2, vh3);
            }
        }
        __syncthreads();
    }

    // epilogue: merge heads, write SINGLE fp16 limb -> g_ah
    const int b_ = bh >> 3;
    const int h  = bh & 7;
    const int c0 = (lane & 3) * 2;
    const float i0 = 1.0f / lrow[0];
    const float i1 = 1.0f / lrow[1];
    const int ra = m0 + w * 16 + rq;
    #pragma unroll
    for (int j = 0; j < 8; j++) {
        int col = 8 * j + c0;
        size_t off0 = ((size_t)(b_ * NN + ra)) * D_MODEL + h * DK + col;
        size_t off1 = ((size_t)(b_ * NN + ra + 8)) * D_MODEL + h * DK + col;
        *reinterpret_cast<uint32_t*>(&g_ah[off0]) = packh(o[j][0] * i0, o[j][1] * i0);
        *reinterpret_cast<uint32_t*>(&g_ah[off1]) = packh(o[j][2] * i1, o[j][3] * i1);
    }
}

// ---------------------------------------------------------------------------
extern "C" void kernel_launch(void* const* d_in, const int* in_sizes, int n_in,
                              void* d_out, int out_size)
{
    (void)in_sizes; (void)n_in; (void)out_size;
    const float* x  = (const float*)d_in[0];
    const float* Wq = (const float*)d_in[1];
    const float* bq = (const float*)d_in[2];
    const float* Wk = (const float*)d_in[3];
    const float* bk = (const float*)d_in[4];
    const float* Wv = (const float*)d_in[5];
    const float* bv = (const float*)d_in[6];
    const float* Wo = (const float*)d_in[7];
    const float* bo = (const float*)d_in[8];

    void *xh, *wth, *ah;
    cudaGetSymbolAddress(&xh, g_xh);
    cudaGetSymbolAddress(&wth, g_wth);
    cudaGetSymbolAddress(&ah, g_ah);

    __half* whp = (__half*)wth;

    cudaFuncSetAttribute(attn_tc, cudaFuncAttributeMaxDynamicSharedMemorySize, ATTN_SMEM);
    cudaFuncSetAttribute(gemm_raw, cudaFuncAttributeMaxDynamicSharedMemorySize, GEMM_SMEM);

    // single fused prep launch
    prep_all<<<NXB + 1024, 256>>>(x, Wq, Wk, Wv, Wo);

    // fused QKV projection: grid (24, 64)
    dim3 qkv_grid(24, M_TOTAL / 128);
    gemm_raw<<<qkv_grid, 256, GEMM_SMEM>>>((const __half*)xh, whp,
                                           bq, bk, bv, nullptr, nullptr, 1);

    dim3 attn_grid(NN / 128, BH);   // (16, 32)
    attn_tc<<<attn_grid, 256, ATTN_SMEM>>>();

    // O projection: grid (8, 64)
    dim3 o_grid(8, M_TOTAL / 128);
    gemm_raw<<<o_grid, 256, GEMM_SMEM>>>((const __half*)ah, whp,
                                         nullptr, nullptr, nullptr, bo, (float*)d_out, 0);
}